// round 5
// baseline (speedup 1.0000x reference)
#include <cuda_runtime.h>
#include <cuda_bf16.h>
#include <math.h>
#include <stdint.h>

// ---------------- problem constants ----------------
#define NG        50
#define KNB       32
#define NUM_G     64
#define ATOMS     128
#define NTOT      (NUM_G * ATOMS)     // 8192
#define HID       128
#define FIL       128
#define LAYERS    6
#define EDGES     (NTOT * KNB)        // 262144
#define NTILES    (EDGES / 128)       // 2048
#define CUTOFF    10.0f
#define PI_C      3.14159265f

#define INVALID_KEY 0xFFFFFFFFFFFFFFFFULL
typedef unsigned long long ull;

// ---------------- device scratch ----------------
__device__ int   g_idx [EDGES];
__device__ float g_dist[EDGES];
__device__ float g_cval[EDGES];
__device__ float g_h   [NTOT * HID];
__device__ float g_x1  [NTOT * FIL];
__device__ float g_agg [NTOT * FIL];
__device__ float g_msg [EDGES * 128];     // 134 MB edge messages

// dst-sorted adjacency (built once)
__device__ int   g_adj [EDGES];
__device__ int   g_off [NTOT];
__device__ int   g_deg [NTOT];

// ldmatrix-layout bf16 tile images
__device__ unsigned char g_rbf_hi[NTILES * 16384];   // per tile: [128 e][64 k]
__device__ unsigned char g_rbf_lo[NTILES * 16384];
__device__ unsigned char g_w1_hi [LAYERS * 16384];   // [128 n][64 k]
__device__ unsigned char g_w1_lo [LAYERS * 16384];
__device__ unsigned char g_w2_hi [LAYERS * 32768];   // [128 n][128 k]
__device__ unsigned char g_w2_lo [LAYERS * 32768];

__device__ __forceinline__ float silu_f(float v) {
    return v / (1.0f + __expf(-v));
}

// ---------------- packed f32x2 helpers ----------------
__device__ __forceinline__ ull pack2(float x, float y) {
    ull r; asm("mov.b64 %0, {%1,%2};" : "=l"(r) : "f"(x), "f"(y)); return r;
}
__device__ __forceinline__ void unpack2(ull v, float& x, float& y) {
    asm("mov.b64 {%0,%1}, %2;" : "=f"(x), "=f"(y) : "l"(v));
}
__device__ __forceinline__ ull fma2(ull a, ull b, ull c) {
    ull d; asm("fma.rn.f32x2 %0, %1, %2, %3;" : "=l"(d) : "l"(a), "l"(b), "l"(c));
    return d;
}

__device__ __forceinline__ uint32_t smem_u32(const void* p) {
    uint32_t a;
    asm("{ .reg .u64 t; cvta.to.shared.u64 t, %1; cvt.u32.u64 %0, t; }" : "=r"(a) : "l"(p));
    return a;
}

// ---------------- mma.sync / ldmatrix helpers (baseline PTX, sm_80+) ----------------
__device__ __forceinline__ void ldsm4(uint32_t* r, uint32_t addr) {
    asm volatile("ldmatrix.sync.aligned.m8n8.x4.shared.b16 {%0,%1,%2,%3}, [%4];"
                 : "=r"(r[0]), "=r"(r[1]), "=r"(r[2]), "=r"(r[3]) : "r"(addr));
}
__device__ __forceinline__ void mma16816(float* c, const uint32_t* a, uint32_t b0, uint32_t b1) {
    asm volatile("mma.sync.aligned.m16n8k16.row.col.f32.bf16.bf16.f32 "
                 "{%0,%1,%2,%3}, {%4,%5,%6,%7}, {%8,%9}, {%0,%1,%2,%3};"
                 : "+f"(c[0]), "+f"(c[1]), "+f"(c[2]), "+f"(c[3])
                 : "r"(a[0]), "r"(a[1]), "r"(a[2]), "r"(a[3]), "r"(b0), "r"(b1));
}

// swizzled byte offsets for ldmatrix-friendly layouts
__device__ __forceinline__ uint32_t off1(int r, int k) {
    return (uint32_t)(r * 128 + (((k >> 3) ^ (r & 7)) << 4) + (k & 7) * 2);
}
__device__ __forceinline__ uint32_t off2(int r, int k) {
    return (uint32_t)(r * 256 + (((k >> 3) ^ (r & 7)) << 4) + (k & 7) * 2);
}

// ---------------- graph build ----------------
__global__ void build_graph_kernel(const float* __restrict__ pos,
                                   const int* __restrict__ batch)
{
    const int i = blockIdx.x;
    const int t = threadIdx.x;
    const int base = (i >> 7) << 7;
    const int j = base + t;

    __shared__ unsigned long long key[ATOMS];
    __shared__ unsigned long long red[ATOMS];

    const float px = pos[3*i], py = pos[3*i+1], pz = pos[3*i+2];
    const float dx = pos[3*j]   - px;
    const float dy = pos[3*j+1] - py;
    const float dz = pos[3*j+2] - pz;
    const float d2 = dx*dx + dy*dy + dz*dz;
    const bool valid = (j != i) && (batch[j] == batch[i]) && (d2 < CUTOFF*CUTOFF);

    key[t] = valid
        ? ((((unsigned long long)__float_as_uint(d2)) << 32) | (unsigned int)j)
        : INVALID_KEY;
    __syncthreads();

    for (int k = 0; k < KNB; k++) {
        red[t] = key[t];
        __syncthreads();
        #pragma unroll
        for (int s = 64; s >= 1; s >>= 1) {
            if (t < s) {
                unsigned long long o = red[t + s];
                if (o < red[t]) red[t] = o;
            }
            __syncthreads();
        }
        const unsigned long long best = red[0];
        if (best != INVALID_KEY && key[t] == best) key[t] = INVALID_KEY;
        if (t == k) {
            const int eo = i * KNB + k;
            if (best != INVALID_KEY) {
                const int   jj = (int)(best & 0xffffffffu);
                const float d  = sqrtf(__uint_as_float((unsigned int)(best >> 32)));
                g_idx[eo]  = jj;
                g_dist[eo] = d;
                const float cv = 0.5f * (cosf(d * (PI_C / CUTOFF)) + 1.0f);
                g_cval[eo] = (d < CUTOFF) ? cv : 0.0f;
            } else {
                g_idx[eo]  = i;
                g_dist[eo] = 1.0f;
                g_cval[eo] = 0.0f;
            }
        }
        __syncthreads();
    }
}

// ---------------- adjacency build: deterministic per-graph counting sort by dst ----------------
__global__ void adj_build_kernel()
{
    __shared__ int sdst[4096];       // local dst of each edge in graph
    __shared__ int scnt[128];
    const int g = blockIdx.x;
    const int t = threadIdx.x;
    const int ebase = g * 4096;

    for (int i = t; i < 4096; i += 128)
        sdst[i] = g_idx[ebase + i] & 127;
    __syncthreads();

    int cnt = 0;
    for (int e = 0; e < 4096; e++) cnt += (sdst[e] == t);
    scnt[t] = cnt;
    __syncthreads();
    // Hillis-Steele inclusive scan
    for (int s = 1; s < 128; s <<= 1) {
        int v = (t >= s) ? scnt[t - s] : 0;
        __syncthreads();
        scnt[t] += v;
        __syncthreads();
    }
    const int offx = scnt[t] - cnt;          // exclusive prefix
    g_deg[g * 128 + t] = cnt;
    g_off[g * 128 + t] = ebase + offx;

    int pos = ebase + offx;
    for (int e = 0; e < 4096; e++)
        if (sdst[e] == t) g_adj[pos++] = ebase + e;
}

// ---------------- rbf prep ----------------
__global__ void rbf_prep_kernel()
{
    const int id = blockIdx.x * blockDim.x + threadIdx.x;
    if (id >= EDGES * 64) return;
    const int e = id >> 6;
    const int k = id & 63;
    const int tile = e >> 7;
    const int r    = e & 127;
    float val = 0.0f;
    if (k < NG) {
        const float w = CUTOFF / (float)(NG - 1);
        const float t = (g_dist[e] - (float)k * w) / w;
        val = expf(-0.5f * t * t);
    }
    const __nv_bfloat16 hi = __float2bfloat16(val);
    const __nv_bfloat16 lo = __float2bfloat16(val - __bfloat162float(hi));
    const uint32_t o = (uint32_t)tile * 16384u + off1(r, k);
    *(unsigned short*)(g_rbf_hi + o) = __bfloat16_as_ushort(hi);
    *(unsigned short*)(g_rbf_lo + o) = __bfloat16_as_ushort(lo);
}

// ---------------- weight prep ----------------
__global__ void w1_prep_kernel(const float* __restrict__ mw1)
{
    const int id = blockIdx.x * blockDim.x + threadIdx.x;
    if (id >= LAYERS * 128 * 64) return;
    const int l = id >> 13;
    const int n = (id >> 6) & 127;
    const int k = id & 63;
    const float val = (k < NG) ? mw1[l * NG * FIL + k * FIL + n] : 0.0f;
    const __nv_bfloat16 hi = __float2bfloat16(val);
    const __nv_bfloat16 lo = __float2bfloat16(val - __bfloat162float(hi));
    const uint32_t o = (uint32_t)l * 16384u + off1(n, k);
    *(unsigned short*)(g_w1_hi + o) = __bfloat16_as_ushort(hi);
    *(unsigned short*)(g_w1_lo + o) = __bfloat16_as_ushort(lo);
}

__global__ void w2_prep_kernel(const float* __restrict__ mw2)
{
    const int id = blockIdx.x * blockDim.x + threadIdx.x;
    if (id >= LAYERS * 128 * 128) return;
    const int l = id >> 14;
    const int n = (id >> 7) & 127;
    const int k = id & 127;
    const float val = mw2[l * FIL * FIL + k * FIL + n];
    const __nv_bfloat16 hi = __float2bfloat16(val);
    const __nv_bfloat16 lo = __float2bfloat16(val - __bfloat162float(hi));
    const uint32_t o = (uint32_t)l * 32768u + off2(n, k);
    *(unsigned short*)(g_w2_hi + o) = __bfloat16_as_ushort(hi);
    *(unsigned short*)(g_w2_lo + o) = __bfloat16_as_ushort(lo);
}

// ---------------- embedding ----------------
__global__ void embed_kernel(const int* __restrict__ z, const float* __restrict__ emb)
{
    const int id = blockIdx.x * blockDim.x + threadIdx.x;
    if (id >= NTOT * HID) return;
    const int n = id >> 7;
    const int c = id & 127;
    g_h[id] = emb[z[n] * HID + c];
}

// ---------------- node linear (f32x2, 8 rows/block) ----------------
__global__ void linear_kernel(const float* __restrict__ x,
                              const float* __restrict__ W,
                              const float* __restrict__ b,
                              float* __restrict__ y,
                              int mode)
{
    __shared__ float xs[128 * 8];       // [k][e]
    const int c  = threadIdx.x;
    const int r0 = blockIdx.x * 8;

    #pragma unroll
    for (int e = 0; e < 8; e++)
        xs[c * 8 + e] = x[(r0 + e) * 128 + c];
    __syncthreads();

    ull acc[4];
    #pragma unroll
    for (int p = 0; p < 4; p++) acc[p] = 0ULL;

    #pragma unroll 4
    for (int k = 0; k < 128; k++) {
        const float w = W[k * 128 + c];
        const ull wp = pack2(w, w);
        const float* xp = &xs[k * 8];
        #pragma unroll
        for (int p = 0; p < 4; p++) {
            const ull xv = *(const ull*)(xp + 2 * p);
            acc[p] = fma2(xv, wp, acc[p]);
        }
    }
    const float bias = b[c];
    if (mode == 0) {
        #pragma unroll
        for (int p = 0; p < 4; p++) {
            float lo, hi; unpack2(acc[p], lo, hi);
            y[(r0 + 2*p)     * 128 + c] = lo + bias;
            y[(r0 + 2*p + 1) * 128 + c] = hi + bias;
        }
    } else {
        #pragma unroll
        for (int p = 0; p < 4; p++) {
            float lo, hi; unpack2(acc[p], lo, hi);
            y[(r0 + 2*p)     * 128 + c] += silu_f(lo + bias);
            y[(r0 + 2*p + 1) * 128 + c] += silu_f(hi + bias);
        }
    }
}

// ---------------- gather: agg[d] = sum of msg over in-edges (dst-sorted, deterministic) ----
__global__ void gather_kernel()
{
    __shared__ int se[192];
    const int d = blockIdx.x;
    const int c = threadIdx.x;
    const int off = g_off[d];
    const int deg = g_deg[d];

    for (int j = c; j < deg; j += 128) se[j] = g_adj[off + j];
    __syncthreads();

    float s0 = 0.0f, s1 = 0.0f, s2 = 0.0f, s3 = 0.0f;
    int j = 0;
    for (; j + 4 <= deg; j += 4) {
        s0 += g_msg[se[j]     * 128 + c];
        s1 += g_msg[se[j + 1] * 128 + c];
        s2 += g_msg[se[j + 2] * 128 + c];
        s3 += g_msg[se[j + 3] * 128 + c];
    }
    for (; j < deg; j++) s0 += g_msg[se[j] * 128 + c];
    g_agg[d * 128 + c] = (s0 + s1) + (s2 + s3);
}

// ---------------- tensor-core (mma.sync) filter kernel ----------------
#define SO_A1HI 0
#define SO_A1LO 16384
#define SO_A2HI 32768
#define SO_A2LO 65536
#define SO_B1HI 98304
#define SO_B1LO 114688
#define SO_B2HI 131072
#define SO_B2LO 163840
#define SO_AUX  196608
#define AUX_X1P 0                 // 512 floats (4 src rows x 128)
#define AUX_X1Q 2048              // 512 floats
#define AUX_CV  4096              // 128 floats
#define AUX_B1  4608              // 128 floats
#define FILT_SMEM_BYTES (SO_AUX + 5120)

__global__ void __launch_bounds__(256, 1)
filter_mma_kernel(const float* __restrict__ b1g, const float* __restrict__ b2g,
                  const unsigned char* __restrict__ w1hi, const unsigned char* __restrict__ w1lo,
                  const unsigned char* __restrict__ w2hi, const unsigned char* __restrict__ w2lo)
{
    extern __shared__ unsigned char base[];
    const uint32_t base32 = smem_u32(base);

    const int tid  = threadIdx.x;
    const int lane = tid & 31;
    const int wid  = tid >> 5;
    const int wm   = wid & 3;          // warp m-tile: 32 edges
    const int wn   = wid >> 2;         // warp n-tile: 64 channels
    const int m0w  = wm * 32;
    const int n0w  = wn * 64;

    float* sx1p = (float*)(base + SO_AUX + AUX_X1P);
    float* sx1q = (float*)(base + SO_AUX + AUX_X1Q);
    float* scv  = (float*)(base + SO_AUX + AUX_CV);
    float* sb1  = (float*)(base + SO_AUX + AUX_B1);

    // resident weight copies
    {
        const uint4* s1h = (const uint4*)w1hi;  const uint4* s1l = (const uint4*)w1lo;
        const uint4* s2h = (const uint4*)w2hi;  const uint4* s2l = (const uint4*)w2lo;
        uint4* d1h = (uint4*)(base + SO_B1HI);  uint4* d1l = (uint4*)(base + SO_B1LO);
        uint4* d2h = (uint4*)(base + SO_B2HI);  uint4* d2l = (uint4*)(base + SO_B2LO);
        for (int i = tid; i < 1024; i += 256) { d1h[i] = s1h[i]; d1l[i] = s1l[i]; }
        for (int i = tid; i < 2048; i += 256) { d2h[i] = s2h[i]; d2l[i] = s2l[i]; }
        if (tid < 128) sb1[tid] = b1g[tid];
    }
    __syncthreads();

    const int lr = lane & 15;          // row within 16
    const int lk = (lane >> 4) * 8;    // k-block 0/8

    for (int tile = blockIdx.x; tile < NTILES; tile += gridDim.x) {
        const int e0 = tile * 128;
        // ---- stage A1 + aux ----
        {
            const uint4* sh = (const uint4*)(g_rbf_hi + (size_t)tile * 16384);
            const uint4* sl = (const uint4*)(g_rbf_lo + (size_t)tile * 16384);
            uint4* dh = (uint4*)(base + SO_A1HI);
            uint4* dl = (uint4*)(base + SO_A1LO);
            for (int i = tid; i < 1024; i += 256) { dh[i] = sh[i]; dl[i] = sl[i]; }
            if (tid < 128) scv[tid] = g_cval[e0 + tid];
            for (int i = tid; i < 512; i += 256) {
                const int jj = i >> 7, c = i & 127;
                const float v = g_x1[(4 * tile + jj) * 128 + c];
                sx1p[i] = v;
                sx1q[i] = v * b2g[c];
            }
        }
        __syncthreads();

        float acc[2][8][4];
        #pragma unroll
        for (int mi = 0; mi < 2; mi++)
            #pragma unroll
            for (int nj = 0; nj < 8; nj++)
                #pragma unroll
                for (int q = 0; q < 4; q++) acc[mi][nj][q] = 0.0f;

        // ---- GEMM1: K=64 ----
        #pragma unroll
        for (int ks = 0; ks < 4; ks++) {
            const int kb = ks * 16 + lk;
            uint32_t Ah[2][4], Al[2][4];
            #pragma unroll
            for (int mi = 0; mi < 2; mi++) {
                const uint32_t o = off1(m0w + mi * 16 + lr, kb);
                ldsm4(Ah[mi], base32 + SO_A1HI + o);
                ldsm4(Al[mi], base32 + SO_A1LO + o);
            }
            #pragma unroll
            for (int nt = 0; nt < 4; nt++) {
                uint32_t Bh[4], Bl[4];
                const uint32_t o = off1(n0w + nt * 16 + lr, kb);
                ldsm4(Bh, base32 + SO_B1HI + o);
                ldsm4(Bl, base32 + SO_B1LO + o);
                #pragma unroll
                for (int h = 0; h < 2; h++) {
                    const int nj = nt * 2 + h;
                    #pragma unroll
                    for (int mi = 0; mi < 2; mi++) {
                        mma16816(acc[mi][nj], Ah[mi], Bh[h], Bh[2 + h]);
                        mma16816(acc[mi][nj], Ah[mi], Bl[h], Bl[2 + h]);
                        mma16816(acc[mi][nj], Al[mi], Bh[h], Bh[2 + h]);
                    }
                }
            }
        }

        // ---- epilogue1: silu, split, store A2 ----
        {
            unsigned char* a2h = base + SO_A2HI;
            unsigned char* a2l = base + SO_A2LO;
            const int rbase = m0w + (lane >> 2);
            const int cbase = n0w + (lane & 3) * 2;
            #pragma unroll
            for (int mi = 0; mi < 2; mi++) {
                #pragma unroll
                for (int nj = 0; nj < 8; nj++) {
                    const int col = cbase + nj * 8;
                    const float bb0 = sb1[col], bb1 = sb1[col + 1];
                    #pragma unroll
                    for (int half = 0; half < 2; half++) {
                        const int row = rbase + mi * 16 + half * 8;
                        const float s0 = silu_f(acc[mi][nj][half * 2]     + bb0);
                        const float s1 = silu_f(acc[mi][nj][half * 2 + 1] + bb1);
                        const __nv_bfloat16 h0 = __float2bfloat16(s0);
                        const __nv_bfloat16 h1 = __float2bfloat16(s1);
                        const __nv_bfloat16 l0 = __float2bfloat16(s0 - __bfloat162float(h0));
                        const __nv_bfloat16 l1 = __float2bfloat16(s1 - __bfloat162float(h1));
                        const uint32_t o = off2(row, col);
                        *(uint32_t*)(a2h + o) = (uint32_t)__bfloat16_as_ushort(h0) |
                                                ((uint32_t)__bfloat16_as_ushort(h1) << 16);
                        *(uint32_t*)(a2l + o) = (uint32_t)__bfloat16_as_ushort(l0) |
                                                ((uint32_t)__bfloat16_as_ushort(l1) << 16);
                    }
                }
            }
        }
        __syncthreads();

        #pragma unroll
        for (int mi = 0; mi < 2; mi++)
            #pragma unroll
            for (int nj = 0; nj < 8; nj++)
                #pragma unroll
                for (int q = 0; q < 4; q++) acc[mi][nj][q] = 0.0f;

        // ---- GEMM2: K=128 ----
        #pragma unroll
        for (int ks = 0; ks < 8; ks++) {
            const int kb = ks * 16 + lk;
            uint32_t Ah[2][4], Al[2][4];
            #pragma unroll
            for (int mi = 0; mi < 2; mi++) {
                const uint32_t o = off2(m0w + mi * 16 + lr, kb);
                ldsm4(Ah[mi], base32 + SO_A2HI + o);
                ldsm4(Al[mi], base32 + SO_A2LO + o);
            }
            #pragma unroll
            for (int nt = 0; nt < 4; nt++) {
                uint32_t Bh[4], Bl[4];
                const uint32_t o = off2(n0w + nt * 16 + lr, kb);
                ldsm4(Bh, base32 + SO_B2HI + o);
                ldsm4(Bl, base32 + SO_B2LO + o);
                #pragma unroll
                for (int h = 0; h < 2; h++) {
                    const int nj = nt * 2 + h;
                    #pragma unroll
                    for (int mi = 0; mi < 2; mi++) {
                        mma16816(acc[mi][nj], Ah[mi], Bh[h], Bh[2 + h]);
                        mma16816(acc[mi][nj], Ah[mi], Bl[h], Bl[2 + h]);
                        mma16816(acc[mi][nj], Al[mi], Bh[h], Bh[2 + h]);
                    }
                }
            }
        }

        // ---- epilogue2: msg = cv*(d*x1 + b2*x1) -> plain coalesced-ish STG.64 ----
        {
            const int rbase = m0w + (lane >> 2);
            const int cbase = n0w + (lane & 3) * 2;
            #pragma unroll
            for (int mi = 0; mi < 2; mi++) {
                #pragma unroll
                for (int half = 0; half < 2; half++) {
                    const int row = rbase + mi * 16 + half * 8;
                    const float cv = scv[row];
                    const int   j4 = row >> 5;
                    const float* pv = &sx1p[j4 * 128];
                    const float* qv = &sx1q[j4 * 128];
                    float* mp = &g_msg[(e0 + row) * 128];
                    #pragma unroll
                    for (int nj = 0; nj < 8; nj++) {
                        const int col = cbase + nj * 8;
                        float2 v;
                        v.x = cv * fmaf(acc[mi][nj][half * 2],     pv[col],     qv[col]);
                        v.y = cv * fmaf(acc[mi][nj][half * 2 + 1], pv[col + 1], qv[col + 1]);
                        *(float2*)(mp + col) = v;
                    }
                }
            }
        }
        __syncthreads();
    }
}

// ---------------- output head + per-graph sum ----------------
#define OUT_SMEM_FLOATS (128*128 + 128*65)

__global__ void out_kernel(const float* __restrict__ ow1, const float* __restrict__ ob1,
                           const float* __restrict__ ow2, const float* __restrict__ ob2,
                           float* __restrict__ out)
{
    extern __shared__ float sm[];
    float* sh = sm;
    float* st = sh + 128*128;
    __shared__ float rsum[256];

    const int g    = blockIdx.x;
    const int tid  = threadIdx.x;
    const int base = g * ATOMS;

    for (int idx = tid; idx < 128 * 128; idx += 256)
        sh[idx] = g_h[base * 128 + idx];
    __syncthreads();

    const int d   = tid & 63;
    const int grp = tid >> 6;
    float acc[32];
    #pragma unroll
    for (int e = 0; e < 32; e++) acc[e] = 0.0f;
    const float* hh = sh + grp * 32 * 128;
    #pragma unroll 2
    for (int k = 0; k < 128; k++) {
        const float w = ow1[k * 64 + d];
        #pragma unroll
        for (int e = 0; e < 32; e++) acc[e] += hh[e * 128 + k] * w;
    }
    const float bb = ob1[d];
    #pragma unroll
    for (int e = 0; e < 32; e++) {
        const float v = acc[e] + bb;
        st[(grp * 32 + e) * 65 + d] = silu_f(v);
    }
    __syncthreads();

    float o = 0.0f;
    if (tid < 128) {
        float s = ob2[0];
        #pragma unroll 4
        for (int dd = 0; dd < 64; dd++) s += st[tid * 65 + dd] * ow2[dd];
        o = s;
    }
    rsum[tid] = o;
    __syncthreads();
    for (int s = 128; s >= 1; s >>= 1) {
        if (tid < s) rsum[tid] += rsum[tid + s];
        __syncthreads();
    }
    if (tid == 0) out[g] = rsum[0];
}

// ---------------- launch ----------------
extern "C" void kernel_launch(void* const* d_in, const int* in_sizes, int n_in,
                              void* d_out, int out_size)
{
    const float* pos   = (const float*)d_in[0];
    const int*   z     = (const int*)  d_in[1];
    const int*   batch = (const int*)  d_in[2];
    const float* emb   = (const float*)d_in[3];
    const float* mw1   = (const float*)d_in[4];
    const float* mb1   = (const float*)d_in[5];
    const float* mw2   = (const float*)d_in[6];
    const float* mb2   = (const float*)d_in[7];
    const float* l1w   = (const float*)d_in[8];
    const float* l1b   = (const float*)d_in[9];
    const float* l2w   = (const float*)d_in[10];
    const float* l2b   = (const float*)d_in[11];
    const float* ow1   = (const float*)d_in[12];
    const float* ob1   = (const float*)d_in[13];
    const float* ow2   = (const float*)d_in[14];
    const float* ob2   = (const float*)d_in[15];
    float* out = (float*)d_out;

    float *hp, *x1p, *aggp;
    cudaGetSymbolAddress((void**)&hp,   g_h);
    cudaGetSymbolAddress((void**)&x1p,  g_x1);
    cudaGetSymbolAddress((void**)&aggp, g_agg);
    unsigned char *w1h, *w1l, *w2h, *w2l;
    cudaGetSymbolAddress((void**)&w1h, g_w1_hi);
    cudaGetSymbolAddress((void**)&w1l, g_w1_lo);
    cudaGetSymbolAddress((void**)&w2h, g_w2_hi);
    cudaGetSymbolAddress((void**)&w2l, g_w2_lo);

    cudaFuncSetAttribute(filter_mma_kernel, cudaFuncAttributeMaxDynamicSharedMemorySize,
                         FILT_SMEM_BYTES);
    cudaFuncSetAttribute(out_kernel, cudaFuncAttributeMaxDynamicSharedMemorySize,
                         OUT_SMEM_FLOATS * (int)sizeof(float));

    build_graph_kernel<<<NTOT, ATOMS>>>(pos, batch);
    adj_build_kernel<<<NUM_G, 128>>>();
    rbf_prep_kernel<<<(EDGES * 64) / 256, 256>>>();
    w1_prep_kernel<<<(LAYERS * 128 * 64 + 255) / 256, 256>>>(mw1);
    w2_prep_kernel<<<(LAYERS * 128 * 128 + 255) / 256, 256>>>(mw2);
    embed_kernel<<<(NTOT * HID + 255) / 256, 256>>>(z, emb);

    for (int l = 0; l < LAYERS; l++) {
        linear_kernel<<<NTOT / 8, 128>>>(hp, l1w + l * HID * FIL, l1b + l * FIL, x1p, 0);
        filter_mma_kernel<<<148, 256, FILT_SMEM_BYTES>>>(
            mb1 + l * FIL, mb2 + l * FIL,
            w1h + l * 16384, w1l + l * 16384,
            w2h + l * 32768, w2l + l * 32768);
        gather_kernel<<<NTOT, 128>>>();
        linear_kernel<<<NTOT / 8, 128>>>(aggp, l2w + l * FIL * HID, l2b + l * HID, hp, 1);
    }

    out_kernel<<<NUM_G, 256, OUT_SMEM_FLOATS * sizeof(float)>>>(ow1, ob1, ow2, ob2, out);
}

// round 6
// speedup vs baseline: 1.3286x; 1.3286x over previous
#include <cuda_runtime.h>
#include <cuda_bf16.h>
#include <math.h>
#include <stdint.h>

// ---------------- problem constants ----------------
#define NG        50
#define KNB       32
#define NUM_G     64
#define ATOMS     128
#define NTOT      (NUM_G * ATOMS)     // 8192
#define HID       128
#define FIL       128
#define LAYERS    6
#define EDGES     (NTOT * KNB)        // 262144
#define NTILES    (EDGES / 128)       // 2048
#define CUTOFF    10.0f
#define PI_C      3.14159265f

#define INVALID_KEY 0xFFFFFFFFFFFFFFFFULL
typedef unsigned long long ull;

// ---------------- device scratch ----------------
__device__ int   g_idx [EDGES];
__device__ float g_dist[EDGES];
__device__ float g_cval[EDGES];
__device__ float g_h   [NTOT * HID];
__device__ float g_x1  [NTOT * FIL];
__device__ float g_agg [NTOT * FIL];

// ldmatrix-layout bf16 tile images
__device__ unsigned char g_rbf_hi[NTILES * 16384];   // per tile: [128 e][64 k]
__device__ unsigned char g_rbf_lo[NTILES * 16384];
__device__ unsigned char g_w1_hi [LAYERS * 16384];   // [128 n][64 k]
__device__ unsigned char g_w1_lo [LAYERS * 16384];
__device__ unsigned char g_w2_hi [LAYERS * 32768];   // [128 n][128 k], n-permuted
__device__ unsigned char g_w2_lo [LAYERS * 32768];

__device__ __forceinline__ float silu_f(float v) {
    return v / (1.0f + __expf(-v));
}

// ---------------- packed f32x2 helpers ----------------
__device__ __forceinline__ ull pack2(float x, float y) {
    ull r; asm("mov.b64 %0, {%1,%2};" : "=l"(r) : "f"(x), "f"(y)); return r;
}
__device__ __forceinline__ void unpack2(ull v, float& x, float& y) {
    asm("mov.b64 {%0,%1}, %2;" : "=f"(x), "=f"(y) : "l"(v));
}
__device__ __forceinline__ ull fma2(ull a, ull b, ull c) {
    ull d; asm("fma.rn.f32x2 %0, %1, %2, %3;" : "=l"(d) : "l"(a), "l"(b), "l"(c));
    return d;
}
__device__ __forceinline__ void red_add_v4(float* p, float a, float b, float c, float d) {
    asm volatile("red.global.add.v4.f32 [%0], {%1,%2,%3,%4};"
                 :: "l"(p), "f"(a), "f"(b), "f"(c), "f"(d) : "memory");
}

__device__ __forceinline__ uint32_t smem_u32(const void* p) {
    uint32_t a;
    asm("{ .reg .u64 t; cvta.to.shared.u64 t, %1; cvt.u32.u64 %0, t; }" : "=r"(a) : "l"(p));
    return a;
}

// ---------------- cp.async helpers (baseline sm_80 PTX) ----------------
__device__ __forceinline__ void cp_async16(uint32_t saddr, const void* gaddr) {
    asm volatile("cp.async.cg.shared.global [%0], [%1], 16;" :: "r"(saddr), "l"(gaddr));
}
#define CP_COMMIT() asm volatile("cp.async.commit_group;" ::: "memory")
#define CP_WAIT0()  asm volatile("cp.async.wait_group 0;" ::: "memory")

// ---------------- mma.sync / ldmatrix helpers ----------------
__device__ __forceinline__ void ldsm4(uint32_t* r, uint32_t addr) {
    asm volatile("ldmatrix.sync.aligned.m8n8.x4.shared.b16 {%0,%1,%2,%3}, [%4];"
                 : "=r"(r[0]), "=r"(r[1]), "=r"(r[2]), "=r"(r[3]) : "r"(addr));
}
__device__ __forceinline__ void mma16816(float* c, const uint32_t* a, uint32_t b0, uint32_t b1) {
    asm volatile("mma.sync.aligned.m16n8k16.row.col.f32.bf16.bf16.f32 "
                 "{%0,%1,%2,%3}, {%4,%5,%6,%7}, {%8,%9}, {%0,%1,%2,%3};"
                 : "+f"(c[0]), "+f"(c[1]), "+f"(c[2]), "+f"(c[3])
                 : "r"(a[0]), "r"(a[1]), "r"(a[2]), "r"(a[3]), "r"(b0), "r"(b1));
}

// swizzled byte offsets for ldmatrix-friendly layouts
__device__ __forceinline__ uint32_t off1(int r, int k) {
    return (uint32_t)(r * 128 + (((k >> 3) ^ (r & 7)) << 4) + (k & 7) * 2);
}
__device__ __forceinline__ uint32_t off2(int r, int k) {
    return (uint32_t)(r * 256 + (((k >> 3) ^ (r & 7)) << 4) + (k & 7) * 2);
}
// output-channel permutation for red.v4-friendly epilogue
__device__ __forceinline__ int perm_n(int n) {
    const int a = n >> 3, q = (n >> 1) & 3, h = n & 1;
    return ((a >> 1) << 4) + (q << 2) + ((a & 1) << 1) + h;
}

// ---------------- graph build ----------------
__global__ void build_graph_kernel(const float* __restrict__ pos,
                                   const int* __restrict__ batch)
{
    const int i = blockIdx.x;
    const int t = threadIdx.x;
    const int base = (i >> 7) << 7;
    const int j = base + t;

    __shared__ unsigned long long key[ATOMS];
    __shared__ unsigned long long red[ATOMS];

    const float px = pos[3*i], py = pos[3*i+1], pz = pos[3*i+2];
    const float dx = pos[3*j]   - px;
    const float dy = pos[3*j+1] - py;
    const float dz = pos[3*j+2] - pz;
    const float d2 = dx*dx + dy*dy + dz*dz;
    const bool valid = (j != i) && (batch[j] == batch[i]) && (d2 < CUTOFF*CUTOFF);

    key[t] = valid
        ? ((((unsigned long long)__float_as_uint(d2)) << 32) | (unsigned int)j)
        : INVALID_KEY;
    __syncthreads();

    for (int k = 0; k < KNB; k++) {
        red[t] = key[t];
        __syncthreads();
        #pragma unroll
        for (int s = 64; s >= 1; s >>= 1) {
            if (t < s) {
                unsigned long long o = red[t + s];
                if (o < red[t]) red[t] = o;
            }
            __syncthreads();
        }
        const unsigned long long best = red[0];
        if (best != INVALID_KEY && key[t] == best) key[t] = INVALID_KEY;
        if (t == k) {
            const int eo = i * KNB + k;
            if (best != INVALID_KEY) {
                const int   jj = (int)(best & 0xffffffffu);
                const float d  = sqrtf(__uint_as_float((unsigned int)(best >> 32)));
                g_idx[eo]  = jj;
                g_dist[eo] = d;
                const float cv = 0.5f * (cosf(d * (PI_C / CUTOFF)) + 1.0f);
                g_cval[eo] = (d < CUTOFF) ? cv : 0.0f;
            } else {
                g_idx[eo]  = i;
                g_dist[eo] = 1.0f;
                g_cval[eo] = 0.0f;
            }
        }
        __syncthreads();
    }
}

// ---------------- fused prep: rbf + w1 + w2(perm) + embed ----------------
#define PREP_RBF   (EDGES * 64)                    // 16777216
#define PREP_W1    (LAYERS * 128 * 64)             // 49152
#define PREP_W2    (LAYERS * 128 * 128)            // 98304
#define PREP_EMB   (NTOT * HID)                    // 1048576
#define PREP_TOTAL (PREP_RBF + PREP_W1 + PREP_W2 + PREP_EMB)

__global__ void prep_all_kernel(const float* __restrict__ mw1,
                                const float* __restrict__ mw2,
                                const int* __restrict__ z,
                                const float* __restrict__ emb)
{
    const int id = blockIdx.x * blockDim.x + threadIdx.x;
    if (id < PREP_RBF) {
        const int e = id >> 6;
        const int k = id & 63;
        const int tile = e >> 7;
        const int r    = e & 127;
        float val = 0.0f;
        if (k < NG) {
            const float w = CUTOFF / (float)(NG - 1);
            const float t = (g_dist[e] - (float)k * w) / w;
            val = expf(-0.5f * t * t);
        }
        const __nv_bfloat16 hi = __float2bfloat16(val);
        const __nv_bfloat16 lo = __float2bfloat16(val - __bfloat162float(hi));
        const uint32_t o = (uint32_t)tile * 16384u + off1(r, k);
        *(unsigned short*)(g_rbf_hi + o) = __bfloat16_as_ushort(hi);
        *(unsigned short*)(g_rbf_lo + o) = __bfloat16_as_ushort(lo);
    } else if (id < PREP_RBF + PREP_W1) {
        const int t = id - PREP_RBF;
        const int l = t >> 13;
        const int n = (t >> 6) & 127;
        const int k = t & 63;
        const float val = (k < NG) ? mw1[l * NG * FIL + k * FIL + n] : 0.0f;
        const __nv_bfloat16 hi = __float2bfloat16(val);
        const __nv_bfloat16 lo = __float2bfloat16(val - __bfloat162float(hi));
        const uint32_t o = (uint32_t)l * 16384u + off1(n, k);
        *(unsigned short*)(g_w1_hi + o) = __bfloat16_as_ushort(hi);
        *(unsigned short*)(g_w1_lo + o) = __bfloat16_as_ushort(lo);
    } else if (id < PREP_RBF + PREP_W1 + PREP_W2) {
        const int t = id - PREP_RBF - PREP_W1;
        const int l = t >> 14;
        const int n = (t >> 7) & 127;
        const int k = t & 127;
        const float val = mw2[l * FIL * FIL + k * FIL + perm_n(n)];
        const __nv_bfloat16 hi = __float2bfloat16(val);
        const __nv_bfloat16 lo = __float2bfloat16(val - __bfloat162float(hi));
        const uint32_t o = (uint32_t)l * 32768u + off2(n, k);
        *(unsigned short*)(g_w2_hi + o) = __bfloat16_as_ushort(hi);
        *(unsigned short*)(g_w2_lo + o) = __bfloat16_as_ushort(lo);
    } else if (id < PREP_TOTAL) {
        const int t = id - PREP_RBF - PREP_W1 - PREP_W2;
        const int n = t >> 7;
        const int c = t & 127;
        g_h[t] = emb[z[n] * HID + c];
    }
}

// ---------------- node linear (f32x2, 8 rows/block); mode0 also zeroes g_agg ----
__global__ void linear_kernel(const float* __restrict__ x,
                              const float* __restrict__ W,
                              const float* __restrict__ b,
                              float* __restrict__ y,
                              int mode)
{
    __shared__ float xs[128 * 8];       // [k][e]
    const int c  = threadIdx.x;
    const int r0 = blockIdx.x * 8;

    #pragma unroll
    for (int e = 0; e < 8; e++)
        xs[c * 8 + e] = x[(r0 + e) * 128 + c];
    __syncthreads();

    ull acc[4];
    #pragma unroll
    for (int p = 0; p < 4; p++) acc[p] = 0ULL;

    #pragma unroll 4
    for (int k = 0; k < 128; k++) {
        const float w = W[k * 128 + c];
        const ull wp = pack2(w, w);
        const float* xp = &xs[k * 8];
        #pragma unroll
        for (int p = 0; p < 4; p++) {
            const ull xv = *(const ull*)(xp + 2 * p);
            acc[p] = fma2(xv, wp, acc[p]);
        }
    }
    const float bias = b[c];
    if (mode == 0) {
        #pragma unroll
        for (int p = 0; p < 4; p++) {
            float lo, hi; unpack2(acc[p], lo, hi);
            y[(r0 + 2*p)     * 128 + c] = lo + bias;
            y[(r0 + 2*p + 1) * 128 + c] = hi + bias;
        }
        #pragma unroll
        for (int e = 0; e < 8; e++) g_agg[(r0 + e) * 128 + c] = 0.0f;
    } else {
        #pragma unroll
        for (int p = 0; p < 4; p++) {
            float lo, hi; unpack2(acc[p], lo, hi);
            y[(r0 + 2*p)     * 128 + c] += silu_f(lo + bias);
            y[(r0 + 2*p + 1) * 128 + c] += silu_f(hi + bias);
        }
    }
}

// ---------------- tensor-core (mma.sync) filter kernel ----------------
#define SO_A1HI 0
#define SO_A1LO 16384
#define SO_A2HI 32768
#define SO_A2LO 65536
#define SO_B1HI 98304
#define SO_B1LO 114688
#define SO_B2HI 131072
#define SO_B2LO 163840
#define SO_AUX  196608
#define AUX_X1P 0                 // 512 floats (4 src rows x 128)
#define AUX_X1Q 2048              // 512 floats
#define AUX_CV  4096              // 128 floats
#define AUX_B1  4608              // 128 floats
#define AUX_DST 5120              // 128 ints
#define FILT_SMEM_BYTES (SO_AUX + 5632)

__global__ void __launch_bounds__(256, 1)
filter_mma_kernel(const float* __restrict__ b1g, const float* __restrict__ b2g,
                  const unsigned char* __restrict__ w1hi, const unsigned char* __restrict__ w1lo,
                  const unsigned char* __restrict__ w2hi, const unsigned char* __restrict__ w2lo)
{
    extern __shared__ unsigned char base[];
    const uint32_t base32 = smem_u32(base);

    const int tid  = threadIdx.x;
    const int lane = tid & 31;
    const int wid  = tid >> 5;
    const int wm   = wid & 3;          // warp m-tile: 32 edges
    const int wn   = wid >> 2;         // warp n-tile: 64 channels
    const int m0w  = wm * 32;
    const int n0w  = wn * 64;

    float* sx1p = (float*)(base + SO_AUX + AUX_X1P);
    float* sx1q = (float*)(base + SO_AUX + AUX_X1Q);
    float* scv  = (float*)(base + SO_AUX + AUX_CV);
    float* sb1  = (float*)(base + SO_AUX + AUX_B1);
    int*   sdst = (int*)  (base + SO_AUX + AUX_DST);

    // resident weight copies
    {
        const uint4* s1h = (const uint4*)w1hi;  const uint4* s1l = (const uint4*)w1lo;
        const uint4* s2h = (const uint4*)w2hi;  const uint4* s2l = (const uint4*)w2lo;
        uint4* d1h = (uint4*)(base + SO_B1HI);  uint4* d1l = (uint4*)(base + SO_B1LO);
        uint4* d2h = (uint4*)(base + SO_B2HI);  uint4* d2l = (uint4*)(base + SO_B2LO);
        for (int i = tid; i < 1024; i += 256) { d1h[i] = s1h[i]; d1l[i] = s1l[i]; }
        for (int i = tid; i < 2048; i += 256) { d2h[i] = s2h[i]; d2l[i] = s2l[i]; }
        if (tid < 128) sb1[tid] = b1g[tid];
    }

    // prefetch first tile's A1 via cp.async
    if (blockIdx.x < NTILES) {
        const size_t tb = (size_t)blockIdx.x * 16384;
        for (int i = tid; i < 1024; i += 256) {
            cp_async16(base32 + SO_A1HI + i * 16, g_rbf_hi + tb + i * 16);
            cp_async16(base32 + SO_A1LO + i * 16, g_rbf_lo + tb + i * 16);
        }
    }
    CP_COMMIT();

    const int lr = lane & 15;          // row within 16
    const int lk = (lane >> 4) * 8;    // k-block 0/8

    for (int tile = blockIdx.x; tile < NTILES; tile += gridDim.x) {
        const int e0 = tile * 128;
        // ---- aux stage ----
        if (tid < 128) { scv[tid] = g_cval[e0 + tid]; sdst[tid] = g_idx[e0 + tid]; }
        for (int i = tid; i < 512; i += 256) {
            const int jj = i >> 7, c = i & 127;
            const float v = g_x1[(4 * tile + jj) * 128 + c];
            sx1p[i] = v;
            sx1q[i] = v * b2g[c];
        }
        CP_WAIT0();
        __syncthreads();

        float acc[2][8][4];
        #pragma unroll
        for (int mi = 0; mi < 2; mi++)
            #pragma unroll
            for (int nj = 0; nj < 8; nj++)
                #pragma unroll
                for (int q = 0; q < 4; q++) acc[mi][nj][q] = 0.0f;

        // ---- GEMM1: K=64 ----
        #pragma unroll
        for (int ks = 0; ks < 4; ks++) {
            const int kb = ks * 16 + lk;
            uint32_t Ah[2][4], Al[2][4];
            #pragma unroll
            for (int mi = 0; mi < 2; mi++) {
                const uint32_t o = off1(m0w + mi * 16 + lr, kb);
                ldsm4(Ah[mi], base32 + SO_A1HI + o);
                ldsm4(Al[mi], base32 + SO_A1LO + o);
            }
            #pragma unroll
            for (int nt = 0; nt < 4; nt++) {
                uint32_t Bh[4], Bl[4];
                const uint32_t o = off1(n0w + nt * 16 + lr, kb);
                ldsm4(Bh, base32 + SO_B1HI + o);
                ldsm4(Bl, base32 + SO_B1LO + o);
                #pragma unroll
                for (int h = 0; h < 2; h++) {
                    const int nj = nt * 2 + h;
                    #pragma unroll
                    for (int mi = 0; mi < 2; mi++) {
                        mma16816(acc[mi][nj], Ah[mi], Bh[h], Bh[2 + h]);
                        mma16816(acc[mi][nj], Ah[mi], Bl[h], Bl[2 + h]);
                        mma16816(acc[mi][nj], Al[mi], Bh[h], Bh[2 + h]);
                    }
                }
            }
        }

        // ---- epilogue1: silu, split, store A2 ----
        {
            unsigned char* a2h = base + SO_A2HI;
            unsigned char* a2l = base + SO_A2LO;
            const int rbase = m0w + (lane >> 2);
            const int cbase = n0w + (lane & 3) * 2;
            #pragma unroll
            for (int mi = 0; mi < 2; mi++) {
                #pragma unroll
                for (int nj = 0; nj < 8; nj++) {
                    const int col = cbase + nj * 8;
                    const float bb0 = sb1[col], bb1 = sb1[col + 1];
                    #pragma unroll
                    for (int half = 0; half < 2; half++) {
                        const int row = rbase + mi * 16 + half * 8;
                        const float s0 = silu_f(acc[mi][nj][half * 2]     + bb0);
                        const float s1 = silu_f(acc[mi][nj][half * 2 + 1] + bb1);
                        const __nv_bfloat16 h0 = __float2bfloat16(s0);
                        const __nv_bfloat16 h1 = __float2bfloat16(s1);
                        const __nv_bfloat16 l0 = __float2bfloat16(s0 - __bfloat162float(h0));
                        const __nv_bfloat16 l1 = __float2bfloat16(s1 - __bfloat162float(h1));
                        const uint32_t o = off2(row, col);
                        *(uint32_t*)(a2h + o) = (uint32_t)__bfloat16_as_ushort(h0) |
                                                ((uint32_t)__bfloat16_as_ushort(h1) << 16);
                        *(uint32_t*)(a2l + o) = (uint32_t)__bfloat16_as_ushort(l0) |
                                                ((uint32_t)__bfloat16_as_ushort(l1) << 16);
                    }
                }
            }
        }
        __syncthreads();

        // ---- prefetch next tile's A1 (A1 is dead now; overlaps GEMM2+epi2) ----
        {
            const int tnext = tile + gridDim.x;
            if (tnext < NTILES) {
                const size_t tb = (size_t)tnext * 16384;
                for (int i = tid; i < 1024; i += 256) {
                    cp_async16(base32 + SO_A1HI + i * 16, g_rbf_hi + tb + i * 16);
                    cp_async16(base32 + SO_A1LO + i * 16, g_rbf_lo + tb + i * 16);
                }
            }
            CP_COMMIT();
        }

        #pragma unroll
        for (int mi = 0; mi < 2; mi++)
            #pragma unroll
            for (int nj = 0; nj < 8; nj++)
                #pragma unroll
                for (int q = 0; q < 4; q++) acc[mi][nj][q] = 0.0f;

        // ---- GEMM2: K=128 ----
        #pragma unroll
        for (int ks = 0; ks < 8; ks++) {
            const int kb = ks * 16 + lk;
            uint32_t Ah[2][4], Al[2][4];
            #pragma unroll
            for (int mi = 0; mi < 2; mi++) {
                const uint32_t o = off2(m0w + mi * 16 + lr, kb);
                ldsm4(Ah[mi], base32 + SO_A2HI + o);
                ldsm4(Al[mi], base32 + SO_A2LO + o);
            }
            #pragma unroll
            for (int nt = 0; nt < 4; nt++) {
                uint32_t Bh[4], Bl[4];
                const uint32_t o = off2(n0w + nt * 16 + lr, kb);
                ldsm4(Bh, base32 + SO_B2HI + o);
                ldsm4(Bl, base32 + SO_B2LO + o);
                #pragma unroll
                for (int h = 0; h < 2; h++) {
                    const int nj = nt * 2 + h;
                    #pragma unroll
                    for (int mi = 0; mi < 2; mi++) {
                        mma16816(acc[mi][nj], Ah[mi], Bh[h], Bh[2 + h]);
                        mma16816(acc[mi][nj], Ah[mi], Bl[h], Bl[2 + h]);
                        mma16816(acc[mi][nj], Al[mi], Bh[h], Bh[2 + h]);
                    }
                }
            }
        }

        // ---- epilogue2: permuted channels -> red.v4 ----
        // mma col n = n0w + 8*nj + 2*q + h holds PHYSICAL channel
        // 64*wn + 16*(nj>>1) + 4*q + 2*(nj&1) + h  (perm baked into w2 prep)
        {
            const int q4 = (lane & 3) << 2;
            const int rbase = m0w + (lane >> 2);
            #pragma unroll
            for (int mi = 0; mi < 2; mi++) {
                #pragma unroll
                for (int half = 0; half < 2; half++) {
                    const int row = rbase + mi * 16 + half * 8;
                    const float cv = scv[row];
                    const int   dst = sdst[row];
                    const int   j4 = row >> 5;
                    const float* pv = &sx1p[j4 * 128];
                    const float* qv = &sx1q[j4 * 128];
                    float* aggp = &g_agg[dst * 128];
                    #pragma unroll
                    for (int pj = 0; pj < 4; pj++) {
                        const int pb = n0w + (pj << 4) + q4;      // physical base, 16B aligned
                        const float4 pvv = *(const float4*)&pv[pb];
                        const float4 qvv = *(const float4*)&qv[pb];
                        const float m0 = cv * fmaf(acc[mi][2*pj    ][half * 2],     pvv.x, qvv.x);
                        const float m1 = cv * fmaf(acc[mi][2*pj    ][half * 2 + 1], pvv.y, qvv.y);
                        const float m2 = cv * fmaf(acc[mi][2*pj + 1][half * 2],     pvv.z, qvv.z);
                        const float m3 = cv * fmaf(acc[mi][2*pj + 1][half * 2 + 1], pvv.w, qvv.w);
                        red_add_v4(aggp + pb, m0, m1, m2, m3);
                    }
                }
            }
        }
        __syncthreads();
    }
}

// ---------------- output head + per-graph sum ----------------
#define OUT_SMEM_FLOATS (128*128 + 128*65)

__global__ void out_kernel(const float* __restrict__ ow1, const float* __restrict__ ob1,
                           const float* __restrict__ ow2, const float* __restrict__ ob2,
                           float* __restrict__ out)
{
    extern __shared__ float sm[];
    float* sh = sm;
    float* st = sh + 128*128;
    __shared__ float rsum[256];

    const int g    = blockIdx.x;
    const int tid  = threadIdx.x;
    const int base = g * ATOMS;

    for (int idx = tid; idx < 128 * 128; idx += 256)
        sh[idx] = g_h[base * 128 + idx];
    __syncthreads();

    const int d   = tid & 63;
    const int grp = tid >> 6;
    float acc[32];
    #pragma unroll
    for (int e = 0; e < 32; e++) acc[e] = 0.0f;
    const float* hh = sh + grp * 32 * 128;
    #pragma unroll 2
    for (int k = 0; k < 128; k++) {
        const float w = ow1[k * 64 + d];
        #pragma unroll
        for (int e = 0; e < 32; e++) acc[e] += hh[e * 128 + k] * w;
    }
    const float bb = ob1[d];
    #pragma unroll
    for (int e = 0; e < 32; e++) {
        const float v = acc[e] + bb;
        st[(grp * 32 + e) * 65 + d] = silu_f(v);
    }
    __syncthreads();

    float o = 0.0f;
    if (tid < 128) {
        float s = ob2[0];
        #pragma unroll 4
        for (int dd = 0; dd < 64; dd++) s += st[tid * 65 + dd] * ow2[dd];
        o = s;
    }
    rsum[tid] = o;
    __syncthreads();
    for (int s = 128; s >= 1; s >>= 1) {
        if (tid < s) rsum[tid] += rsum[tid + s];
        __syncthreads();
    }
    if (tid == 0) out[g] = rsum[0];
}

// ---------------- launch ----------------
extern "C" void kernel_launch(void* const* d_in, const int* in_sizes, int n_in,
                              void* d_out, int out_size)
{
    const float* pos   = (const float*)d_in[0];
    const int*   z     = (const int*)  d_in[1];
    const int*   batch = (const int*)  d_in[2];
    const float* emb   = (const float*)d_in[3];
    const float* mw1   = (const float*)d_in[4];
    const float* mb1   = (const float*)d_in[5];
    const float* mw2   = (const float*)d_in[6];
    const float* mb2   = (const float*)d_in[7];
    const float* l1w   = (const float*)d_in[8];
    const float* l1b   = (const float*)d_in[9];
    const float* l2w   = (const float*)d_in[10];
    const float* l2b   = (const float*)d_in[11];
    const float* ow1   = (const float*)d_in[12];
    const float* ob1   = (const float*)d_in[13];
    const float* ow2   = (const float*)d_in[14];
    const float* ob2   = (const float*)d_in[15];
    float* out = (float*)d_out;

    float *hp, *x1p, *aggp;
    cudaGetSymbolAddress((void**)&hp,   g_h);
    cudaGetSymbolAddress((void**)&x1p,  g_x1);
    cudaGetSymbolAddress((void**)&aggp, g_agg);
    unsigned char *w1h, *w1l, *w2h, *w2l;
    cudaGetSymbolAddress((void**)&w1h, g_w1_hi);
    cudaGetSymbolAddress((void**)&w1l, g_w1_lo);
    cudaGetSymbolAddress((void**)&w2h, g_w2_hi);
    cudaGetSymbolAddress((void**)&w2l, g_w2_lo);

    cudaFuncSetAttribute(filter_mma_kernel, cudaFuncAttributeMaxDynamicSharedMemorySize,
                         FILT_SMEM_BYTES);
    cudaFuncSetAttribute(out_kernel, cudaFuncAttributeMaxDynamicSharedMemorySize,
                         OUT_SMEM_FLOATS * (int)sizeof(float));

    build_graph_kernel<<<NTOT, ATOMS>>>(pos, batch);
    prep_all_kernel<<<(PREP_TOTAL + 255) / 256, 256>>>(mw1, mw2, z, emb);

    for (int l = 0; l < LAYERS; l++) {
        linear_kernel<<<NTOT / 8, 128>>>(hp, l1w + l * HID * FIL, l1b + l * FIL, x1p, 0);
        filter_mma_kernel<<<148, 256, FILT_SMEM_BYTES>>>(
            mb1 + l * FIL, mb2 + l * FIL,
            w1h + l * 16384, w1l + l * 16384,
            w2h + l * 32768, w2l + l * 32768);
        linear_kernel<<<NTOT / 8, 128>>>(aggp, l2w + l * FIL * HID, l2b + l * HID, hp, 1);
    }

    out_kernel<<<NUM_G, 256, OUT_SMEM_FLOATS * sizeof(float)>>>(ow1, ob1, ow2, ob2, out);
}

// round 7
// speedup vs baseline: 1.5313x; 1.1526x over previous
#include <cuda_runtime.h>
#include <cuda_bf16.h>
#include <math.h>
#include <stdint.h>

// ---------------- problem constants ----------------
#define NG        50
#define KNB       32
#define NUM_G     64
#define ATOMS     128
#define NTOT      (NUM_G * ATOMS)     // 8192
#define HID       128
#define FIL       128
#define LAYERS    6
#define EDGES     (NTOT * KNB)        // 262144
#define NTILES    (EDGES / 128)       // 2048
#define CUTOFF    10.0f
#define PI_C      3.14159265f

#define INVALID_KEY 0xFFFFFFFFFFFFFFFFULL
typedef unsigned long long ull;

// ---------------- device scratch ----------------
__device__ int   g_idx [EDGES];
__device__ float g_dist[EDGES];
__device__ float g_cval[EDGES];
__device__ float g_h   [NTOT * HID];
__device__ float g_x1  [NTOT * FIL];
__device__ float g_agg [NTOT * FIL];

// ldmatrix-layout bf16 tile images
__device__ unsigned char g_rbf_hi[NTILES * 16384];   // per tile: [128 e][64 k]
__device__ unsigned char g_rbf_lo[NTILES * 16384];
__device__ unsigned char g_w1_hi [LAYERS * 16384];   // [128 n][64 k]
__device__ unsigned char g_w1_lo [LAYERS * 16384];
__device__ unsigned char g_w2_hi [LAYERS * 32768];   // [128 n][128 k], n-permuted
__device__ unsigned char g_w2_lo [LAYERS * 32768];

__device__ __forceinline__ float silu_f(float v) {
    return v / (1.0f + __expf(-v));
}

// ---------------- packed f32x2 helpers ----------------
__device__ __forceinline__ ull pack2(float x, float y) {
    ull r; asm("mov.b64 %0, {%1,%2};" : "=l"(r) : "f"(x), "f"(y)); return r;
}
__device__ __forceinline__ void unpack2(ull v, float& x, float& y) {
    asm("mov.b64 {%0,%1}, %2;" : "=f"(x), "=f"(y) : "l"(v));
}
__device__ __forceinline__ ull fma2(ull a, ull b, ull c) {
    ull d; asm("fma.rn.f32x2 %0, %1, %2, %3;" : "=l"(d) : "l"(a), "l"(b), "l"(c));
    return d;
}
__device__ __forceinline__ void red_add_v4(float* p, float a, float b, float c, float d) {
    asm volatile("red.global.add.v4.f32 [%0], {%1,%2,%3,%4};"
                 :: "l"(p), "f"(a), "f"(b), "f"(c), "f"(d) : "memory");
}

__device__ __forceinline__ uint32_t smem_u32(const void* p) {
    uint32_t a;
    asm("{ .reg .u64 t; cvta.to.shared.u64 t, %1; cvt.u32.u64 %0, t; }" : "=r"(a) : "l"(p));
    return a;
}

// ---------------- cp.async helpers ----------------
__device__ __forceinline__ void cp_async16(uint32_t saddr, const void* gaddr) {
    asm volatile("cp.async.cg.shared.global [%0], [%1], 16;" :: "r"(saddr), "l"(gaddr));
}
#define CP_COMMIT() asm volatile("cp.async.commit_group;" ::: "memory")
#define CP_WAIT0()  asm volatile("cp.async.wait_group 0;" ::: "memory")

// ---------------- mma.sync / ldmatrix helpers ----------------
__device__ __forceinline__ void ldsm4(uint32_t* r, uint32_t addr) {
    asm volatile("ldmatrix.sync.aligned.m8n8.x4.shared.b16 {%0,%1,%2,%3}, [%4];"
                 : "=r"(r[0]), "=r"(r[1]), "=r"(r[2]), "=r"(r[3]) : "r"(addr));
}
__device__ __forceinline__ void mma16816(float* c, const uint32_t* a, uint32_t b0, uint32_t b1) {
    asm volatile("mma.sync.aligned.m16n8k16.row.col.f32.bf16.bf16.f32 "
                 "{%0,%1,%2,%3}, {%4,%5,%6,%7}, {%8,%9}, {%0,%1,%2,%3};"
                 : "+f"(c[0]), "+f"(c[1]), "+f"(c[2]), "+f"(c[3])
                 : "r"(a[0]), "r"(a[1]), "r"(a[2]), "r"(a[3]), "r"(b0), "r"(b1));
}

// swizzled byte offsets
__device__ __forceinline__ uint32_t off1(int r, int k) {
    return (uint32_t)(r * 128 + (((k >> 3) ^ (r & 7)) << 4) + (k & 7) * 2);
}
__device__ __forceinline__ uint32_t off2(int r, int k) {
    return (uint32_t)(r * 256 + (((k >> 3) ^ (r & 7)) << 4) + (k & 7) * 2);
}
// output-channel permutation for red.v4-friendly epilogue
__device__ __forceinline__ int perm_n(int n) {
    const int a = n >> 3, q = (n >> 1) & 3, h = n & 1;
    return ((a >> 1) << 4) + (q << 2) + ((a & 1) << 1) + h;
}

// ---------------- graph build ----------------
__global__ void build_graph_kernel(const float* __restrict__ pos,
                                   const int* __restrict__ batch)
{
    const int i = blockIdx.x;
    const int t = threadIdx.x;
    const int base = (i >> 7) << 7;
    const int j = base + t;

    __shared__ unsigned long long key[ATOMS];
    __shared__ unsigned long long red[ATOMS];

    const float px = pos[3*i], py = pos[3*i+1], pz = pos[3*i+2];
    const float dx = pos[3*j]   - px;
    const float dy = pos[3*j+1] - py;
    const float dz = pos[3*j+2] - pz;
    const float d2 = dx*dx + dy*dy + dz*dz;
    const bool valid = (j != i) && (batch[j] == batch[i]) && (d2 < CUTOFF*CUTOFF);

    key[t] = valid
        ? ((((unsigned long long)__float_as_uint(d2)) << 32) | (unsigned int)j)
        : INVALID_KEY;
    __syncthreads();

    for (int k = 0; k < KNB; k++) {
        red[t] = key[t];
        __syncthreads();
        #pragma unroll
        for (int s = 64; s >= 1; s >>= 1) {
            if (t < s) {
                unsigned long long o = red[t + s];
                if (o < red[t]) red[t] = o;
            }
            __syncthreads();
        }
        const unsigned long long best = red[0];
        if (best != INVALID_KEY && key[t] == best) key[t] = INVALID_KEY;
        if (t == k) {
            const int eo = i * KNB + k;
            if (best != INVALID_KEY) {
                const int   jj = (int)(best & 0xffffffffu);
                const float d  = sqrtf(__uint_as_float((unsigned int)(best >> 32)));
                g_idx[eo]  = jj;
                g_dist[eo] = d;
                const float cv = 0.5f * (cosf(d * (PI_C / CUTOFF)) + 1.0f);
                g_cval[eo] = (d < CUTOFF) ? cv : 0.0f;
            } else {
                g_idx[eo]  = i;
                g_dist[eo] = 1.0f;
                g_cval[eo] = 0.0f;
            }
        }
        __syncthreads();
    }
}

// ---------------- fused prep: rbf + w1 + w2(perm) + embed ----------------
#define PREP_RBF   (EDGES * 64)
#define PREP_W1    (LAYERS * 128 * 64)
#define PREP_W2    (LAYERS * 128 * 128)
#define PREP_EMB   (NTOT * HID)
#define PREP_TOTAL (PREP_RBF + PREP_W1 + PREP_W2 + PREP_EMB)

__global__ void prep_all_kernel(const float* __restrict__ mw1,
                                const float* __restrict__ mw2,
                                const int* __restrict__ z,
                                const float* __restrict__ emb)
{
    const int id = blockIdx.x * blockDim.x + threadIdx.x;
    if (id < PREP_RBF) {
        const int e = id >> 6;
        const int k = id & 63;
        const int tile = e >> 7;
        const int r    = e & 127;
        float val = 0.0f;
        if (k < NG) {
            const float w = CUTOFF / (float)(NG - 1);
            const float t = (g_dist[e] - (float)k * w) / w;
            val = expf(-0.5f * t * t);
        }
        const __nv_bfloat16 hi = __float2bfloat16(val);
        const __nv_bfloat16 lo = __float2bfloat16(val - __bfloat162float(hi));
        const uint32_t o = (uint32_t)tile * 16384u + off1(r, k);
        *(unsigned short*)(g_rbf_hi + o) = __bfloat16_as_ushort(hi);
        *(unsigned short*)(g_rbf_lo + o) = __bfloat16_as_ushort(lo);
    } else if (id < PREP_RBF + PREP_W1) {
        const int t = id - PREP_RBF;
        const int l = t >> 13;
        const int n = (t >> 6) & 127;
        const int k = t & 63;
        const float val = (k < NG) ? mw1[l * NG * FIL + k * FIL + n] : 0.0f;
        const __nv_bfloat16 hi = __float2bfloat16(val);
        const __nv_bfloat16 lo = __float2bfloat16(val - __bfloat162float(hi));
        const uint32_t o = (uint32_t)l * 16384u + off1(n, k);
        *(unsigned short*)(g_w1_hi + o) = __bfloat16_as_ushort(hi);
        *(unsigned short*)(g_w1_lo + o) = __bfloat16_as_ushort(lo);
    } else if (id < PREP_RBF + PREP_W1 + PREP_W2) {
        const int t = id - PREP_RBF - PREP_W1;
        const int l = t >> 14;
        const int n = (t >> 7) & 127;
        const int k = t & 127;
        const float val = mw2[l * FIL * FIL + k * FIL + perm_n(n)];
        const __nv_bfloat16 hi = __float2bfloat16(val);
        const __nv_bfloat16 lo = __float2bfloat16(val - __bfloat162float(hi));
        const uint32_t o = (uint32_t)l * 32768u + off2(n, k);
        *(unsigned short*)(g_w2_hi + o) = __bfloat16_as_ushort(hi);
        *(unsigned short*)(g_w2_lo + o) = __bfloat16_as_ushort(lo);
    } else if (id < PREP_TOTAL) {
        const int t = id - PREP_RBF - PREP_W1 - PREP_W2;
        const int n = t >> 7;
        const int c = t & 127;
        g_h[t] = emb[z[n] * HID + c];
    }
}

// ---------------- node linear (f32x2, 8 rows/block); mode0 also zeroes g_agg ----
__global__ void linear_kernel(const float* __restrict__ x,
                              const float* __restrict__ W,
                              const float* __restrict__ b,
                              float* __restrict__ y,
                              int mode)
{
    __shared__ float xs[128 * 8];       // [k][e]
    const int c  = threadIdx.x;
    const int r0 = blockIdx.x * 8;

    #pragma unroll
    for (int e = 0; e < 8; e++)
        xs[c * 8 + e] = x[(r0 + e) * 128 + c];
    __syncthreads();

    ull acc[4];
    #pragma unroll
    for (int p = 0; p < 4; p++) acc[p] = 0ULL;

    #pragma unroll 4
    for (int k = 0; k < 128; k++) {
        const float w = W[k * 128 + c];
        const ull wp = pack2(w, w);
        const float* xp = &xs[k * 8];
        #pragma unroll
        for (int p = 0; p < 4; p++) {
            const ull xv = *(const ull*)(xp + 2 * p);
            acc[p] = fma2(xv, wp, acc[p]);
        }
    }
    const float bias = b[c];
    if (mode == 0) {
        #pragma unroll
        for (int p = 0; p < 4; p++) {
            float lo, hi; unpack2(acc[p], lo, hi);
            y[(r0 + 2*p)     * 128 + c] = lo + bias;
            y[(r0 + 2*p + 1) * 128 + c] = hi + bias;
        }
        #pragma unroll
        for (int e = 0; e < 8; e++) g_agg[(r0 + e) * 128 + c] = 0.0f;
    } else {
        #pragma unroll
        for (int p = 0; p < 4; p++) {
            float lo, hi; unpack2(acc[p], lo, hi);
            y[(r0 + 2*p)     * 128 + c] += silu_f(lo + bias);
            y[(r0 + 2*p + 1) * 128 + c] += silu_f(hi + bias);
        }
    }
}

// ---------------- tensor-core (mma.sync) filter kernel, 512 threads ----------------
#define SO_A1HI 0
#define SO_A1LO 16384
#define SO_A2HI 32768
#define SO_A2LO 65536
#define SO_B1HI 98304
#define SO_B1LO 114688
#define SO_B2HI 131072
#define SO_B2LO 163840
#define SO_AUX  196608
// per-parity aux block (5120 B each): X1P 2048 | X1Q 2048 | CV 512 | DST 512
#define AUXB_X1P 0
#define AUXB_X1Q 2048
#define AUXB_CV  4096
#define AUXB_DST 4608
#define AUX_B1   10240            // shared bias (512 B)
#define FILT_SMEM_BYTES (SO_AUX + 10752)

__global__ void __launch_bounds__(512, 1)
filter_mma_kernel(const float* __restrict__ b1g, const float* __restrict__ b2g,
                  const unsigned char* __restrict__ w1hi, const unsigned char* __restrict__ w1lo,
                  const unsigned char* __restrict__ w2hi, const unsigned char* __restrict__ w2lo)
{
    extern __shared__ unsigned char base[];
    const uint32_t base32 = smem_u32(base);

    const int tid  = threadIdx.x;
    const int lane = tid & 31;
    const int wid  = tid >> 5;
    const int wm   = wid & 3;          // warp m-tile: 32 edges
    const int wn   = wid >> 2;         // warp n-tile: 32 channels (0..3)
    const int m0w  = wm * 32;
    const int n0w  = wn * 32;

    float* sb1 = (float*)(base + SO_AUX + AUX_B1);

    // resident weight copies
    {
        const uint4* s1h = (const uint4*)w1hi;  const uint4* s1l = (const uint4*)w1lo;
        const uint4* s2h = (const uint4*)w2hi;  const uint4* s2l = (const uint4*)w2lo;
        uint4* d1h = (uint4*)(base + SO_B1HI);  uint4* d1l = (uint4*)(base + SO_B1LO);
        uint4* d2h = (uint4*)(base + SO_B2HI);  uint4* d2l = (uint4*)(base + SO_B2LO);
        for (int i = tid; i < 1024; i += 512) { d1h[i] = s1h[i]; d1l[i] = s1l[i]; }
        for (int i = tid; i < 2048; i += 512) { d2h[i] = s2h[i]; d2l[i] = s2l[i]; }
        if (tid < 128) sb1[tid] = b1g[tid];
    }

    // prefetch first tile's A1 via cp.async
    if (blockIdx.x < NTILES) {
        const size_t tb = (size_t)blockIdx.x * 16384;
        for (int i = tid; i < 1024; i += 512) {
            cp_async16(base32 + SO_A1HI + i * 16, g_rbf_hi + tb + i * 16);
            cp_async16(base32 + SO_A1LO + i * 16, g_rbf_lo + tb + i * 16);
        }
    }
    CP_COMMIT();

    const int lr = lane & 15;          // row within 16
    const int lk = (lane >> 4) * 8;    // k-block 0/8

    int par = 0;
    for (int tile = blockIdx.x; tile < NTILES; tile += gridDim.x, par ^= 1) {
        const int e0 = tile * 128;
        unsigned char* aux = base + SO_AUX + par * 5120;
        float* sx1p = (float*)(aux + AUXB_X1P);
        float* sx1q = (float*)(aux + AUXB_X1Q);
        float* scv  = (float*)(aux + AUXB_CV);
        int*   sdst = (int*)  (aux + AUXB_DST);

        // ---- aux stage (parity buffer; epi2 of previous tile reads the other) ----
        if (tid < 128) { scv[tid] = g_cval[e0 + tid]; sdst[tid] = g_idx[e0 + tid]; }
        if (tid < 512) {
            const int jj = tid >> 7, c = tid & 127;
            const float v = g_x1[(4 * tile + jj) * 128 + c];
            sx1p[tid] = v;
            sx1q[tid] = v * b2g[c];
        }
        CP_WAIT0();
        __syncthreads();

        float acc[2][4][4];
        #pragma unroll
        for (int mi = 0; mi < 2; mi++)
            #pragma unroll
            for (int nj = 0; nj < 4; nj++)
                #pragma unroll
                for (int q = 0; q < 4; q++) acc[mi][nj][q] = 0.0f;

        // ---- GEMM1: K=64 ----
        #pragma unroll
        for (int ks = 0; ks < 4; ks++) {
            const int kb = ks * 16 + lk;
            uint32_t Ah[2][4], Al[2][4];
            #pragma unroll
            for (int mi = 0; mi < 2; mi++) {
                const uint32_t o = off1(m0w + mi * 16 + lr, kb);
                ldsm4(Ah[mi], base32 + SO_A1HI + o);
                ldsm4(Al[mi], base32 + SO_A1LO + o);
            }
            #pragma unroll
            for (int nt = 0; nt < 2; nt++) {
                uint32_t Bh[4], Bl[4];
                const uint32_t o = off1(n0w + nt * 16 + lr, kb);
                ldsm4(Bh, base32 + SO_B1HI + o);
                ldsm4(Bl, base32 + SO_B1LO + o);
                #pragma unroll
                for (int h = 0; h < 2; h++) {
                    const int nj = nt * 2 + h;
                    #pragma unroll
                    for (int mi = 0; mi < 2; mi++) {
                        mma16816(acc[mi][nj], Ah[mi], Bh[h], Bh[2 + h]);
                        mma16816(acc[mi][nj], Ah[mi], Bl[h], Bl[2 + h]);
                        mma16816(acc[mi][nj], Al[mi], Bh[h], Bh[2 + h]);
                    }
                }
            }
        }

        // ---- epilogue1: silu, split, store A2 ----
        {
            unsigned char* a2h = base + SO_A2HI;
            unsigned char* a2l = base + SO_A2LO;
            const int rbase = m0w + (lane >> 2);
            const int cbase = n0w + (lane & 3) * 2;
            #pragma unroll
            for (int mi = 0; mi < 2; mi++) {
                #pragma unroll
                for (int nj = 0; nj < 4; nj++) {
                    const int col = cbase + nj * 8;
                    const float bb0 = sb1[col], bb1 = sb1[col + 1];
                    #pragma unroll
                    for (int half = 0; half < 2; half++) {
                        const int row = rbase + mi * 16 + half * 8;
                        const float s0 = silu_f(acc[mi][nj][half * 2]     + bb0);
                        const float s1 = silu_f(acc[mi][nj][half * 2 + 1] + bb1);
                        const __nv_bfloat16 h0 = __float2bfloat16(s0);
                        const __nv_bfloat16 h1 = __float2bfloat16(s1);
                        const __nv_bfloat16 l0 = __float2bfloat16(s0 - __bfloat162float(h0));
                        const __nv_bfloat16 l1 = __float2bfloat16(s1 - __bfloat162float(h1));
                        const uint32_t o = off2(row, col);
                        *(uint32_t*)(a2h + o) = (uint32_t)__bfloat16_as_ushort(h0) |
                                                ((uint32_t)__bfloat16_as_ushort(h1) << 16);
                        *(uint32_t*)(a2l + o) = (uint32_t)__bfloat16_as_ushort(l0) |
                                                ((uint32_t)__bfloat16_as_ushort(l1) << 16);
                    }
                }
            }
        }
        __syncthreads();

        // ---- prefetch next tile's A1 (A1 dead; overlaps GEMM2+epi2) ----
        {
            const int tnext = tile + gridDim.x;
            if (tnext < NTILES) {
                const size_t tb = (size_t)tnext * 16384;
                for (int i = tid; i < 1024; i += 512) {
                    cp_async16(base32 + SO_A1HI + i * 16, g_rbf_hi + tb + i * 16);
                    cp_async16(base32 + SO_A1LO + i * 16, g_rbf_lo + tb + i * 16);
                }
            }
            CP_COMMIT();
        }

        #pragma unroll
        for (int mi = 0; mi < 2; mi++)
            #pragma unroll
            for (int nj = 0; nj < 4; nj++)
                #pragma unroll
                for (int q = 0; q < 4; q++) acc[mi][nj][q] = 0.0f;

        // ---- GEMM2: K=128 ----
        #pragma unroll
        for (int ks = 0; ks < 8; ks++) {
            const int kb = ks * 16 + lk;
            uint32_t Ah[2][4], Al[2][4];
            #pragma unroll
            for (int mi = 0; mi < 2; mi++) {
                const uint32_t o = off2(m0w + mi * 16 + lr, kb);
                ldsm4(Ah[mi], base32 + SO_A2HI + o);
                ldsm4(Al[mi], base32 + SO_A2LO + o);
            }
            #pragma unroll
            for (int nt = 0; nt < 2; nt++) {
                uint32_t Bh[4], Bl[4];
                const uint32_t o = off2(n0w + nt * 16 + lr, kb);
                ldsm4(Bh, base32 + SO_B2HI + o);
                ldsm4(Bl, base32 + SO_B2LO + o);
                #pragma unroll
                for (int h = 0; h < 2; h++) {
                    const int nj = nt * 2 + h;
                    #pragma unroll
                    for (int mi = 0; mi < 2; mi++) {
                        mma16816(acc[mi][nj], Ah[mi], Bh[h], Bh[2 + h]);
                        mma16816(acc[mi][nj], Ah[mi], Bl[h], Bl[2 + h]);
                        mma16816(acc[mi][nj], Al[mi], Bh[h], Bh[2 + h]);
                    }
                }
            }
        }

        // ---- epilogue2: permuted channels -> red.v4 (no trailing sync; aux dbl-buffered) ----
        {
            const int q4 = (lane & 3) << 2;
            const int rbase = m0w + (lane >> 2);
            #pragma unroll
            for (int mi = 0; mi < 2; mi++) {
                #pragma unroll
                for (int half = 0; half < 2; half++) {
                    const int row = rbase + mi * 16 + half * 8;
                    const float cv = scv[row];
                    const int   dst = sdst[row];
                    const int   j4 = row >> 5;
                    const float* pv = &sx1p[j4 * 128];
                    const float* qv = &sx1q[j4 * 128];
                    float* aggp = &g_agg[dst * 128];
                    #pragma unroll
                    for (int pj = 0; pj < 2; pj++) {
                        const int pb = n0w + (pj << 4) + q4;      // physical base, 16B aligned
                        const float4 pvv = *(const float4*)&pv[pb];
                        const float4 qvv = *(const float4*)&qv[pb];
                        const float m0 = cv * fmaf(acc[mi][2*pj    ][half * 2],     pvv.x, qvv.x);
                        const float m1 = cv * fmaf(acc[mi][2*pj    ][half * 2 + 1], pvv.y, qvv.y);
                        const float m2 = cv * fmaf(acc[mi][2*pj + 1][half * 2],     pvv.z, qvv.z);
                        const float m3 = cv * fmaf(acc[mi][2*pj + 1][half * 2 + 1], pvv.w, qvv.w);
                        red_add_v4(aggp + pb, m0, m1, m2, m3);
                    }
                }
            }
        }
        // no trailing __syncthreads: next iteration writes the other aux parity,
        // and A1 prefetch for next tile was issued after the mid-tile barrier.
    }
}

// ---------------- output head + per-graph sum ----------------
#define OUT_SMEM_FLOATS (128*128 + 128*65)

__global__ void out_kernel(const float* __restrict__ ow1, const float* __restrict__ ob1,
                           const float* __restrict__ ow2, const float* __restrict__ ob2,
                           float* __restrict__ out)
{
    extern __shared__ float sm[];
    float* sh = sm;
    float* st = sh + 128*128;
    __shared__ float rsum[256];

    const int g    = blockIdx.x;
    const int tid  = threadIdx.x;
    const int base = g * ATOMS;

    for (int idx = tid; idx < 128 * 128; idx += 256)
        sh[idx] = g_h[base * 128 + idx];
    __syncthreads();

    const int d   = tid & 63;
    const int grp = tid >> 6;
    float acc[32];
    #pragma unroll
    for (int e = 0; e < 32; e++) acc[e] = 0.0f;
    const float* hh = sh + grp * 32 * 128;
    #pragma unroll 2
    for (int k = 0; k < 128; k++) {
        const float w = ow1[k * 64 + d];
        #pragma unroll
        for (int e = 0; e < 32; e++) acc[e] += hh[e * 128 + k] * w;
    }
    const float bb = ob1[d];
    #pragma unroll
    for (int e = 0; e < 32; e++) {
        const float v = acc[e] + bb;
        st[(grp * 32 + e) * 65 + d] = silu_f(v);
    }
    __syncthreads();

    float o = 0.0f;
    if (tid < 128) {
        float s = ob2[0];
        #pragma unroll 4
        for (int dd = 0; dd < 64; dd++) s += st[tid * 65 + dd] * ow2[dd];
        o = s;
    }
    rsum[tid] = o;
    __syncthreads();
    for (int s = 128; s >= 1; s >>= 1) {
        if (tid < s) rsum[tid] += rsum[tid + s];
        __syncthreads();
    }
    if (tid == 0) out[g] = rsum[0];
}

// ---------------- launch ----------------
extern "C" void kernel_launch(void* const* d_in, const int* in_sizes, int n_in,
                              void* d_out, int out_size)
{
    const float* pos   = (const float*)d_in[0];
    const int*   z     = (const int*)  d_in[1];
    const int*   batch = (const int*)  d_in[2];
    const float* emb   = (const float*)d_in[3];
    const float* mw1   = (const float*)d_in[4];
    const float* mb1   = (const float*)d_in[5];
    const float* mw2   = (const float*)d_in[6];
    const float* mb2   = (const float*)d_in[7];
    const float* l1w   = (const float*)d_in[8];
    const float* l1b   = (const float*)d_in[9];
    const float* l2w   = (const float*)d_in[10];
    const float* l2b   = (const float*)d_in[11];
    const float* ow1   = (const float*)d_in[12];
    const float* ob1   = (const float*)d_in[13];
    const float* ow2   = (const float*)d_in[14];
    const float* ob2   = (const float*)d_in[15];
    float* out = (float*)d_out;

    float *hp, *x1p, *aggp;
    cudaGetSymbolAddress((void**)&hp,   g_h);
    cudaGetSymbolAddress((void**)&x1p,  g_x1);
    cudaGetSymbolAddress((void**)&aggp, g_agg);
    unsigned char *w1h, *w1l, *w2h, *w2l;
    cudaGetSymbolAddress((void**)&w1h, g_w1_hi);
    cudaGetSymbolAddress((void**)&w1l, g_w1_lo);
    cudaGetSymbolAddress((void**)&w2h, g_w2_hi);
    cudaGetSymbolAddress((void**)&w2l, g_w2_lo);

    cudaFuncSetAttribute(filter_mma_kernel, cudaFuncAttributeMaxDynamicSharedMemorySize,
                         FILT_SMEM_BYTES);
    cudaFuncSetAttribute(out_kernel, cudaFuncAttributeMaxDynamicSharedMemorySize,
                         OUT_SMEM_FLOATS * (int)sizeof(float));

    build_graph_kernel<<<NTOT, ATOMS>>>(pos, batch);
    prep_all_kernel<<<(PREP_TOTAL + 255) / 256, 256>>>(mw1, mw2, z, emb);

    for (int l = 0; l < LAYERS; l++) {
        linear_kernel<<<NTOT / 8, 128>>>(hp, l1w + l * HID * FIL, l1b + l * FIL, x1p, 0);
        filter_mma_kernel<<<148, 512, FILT_SMEM_BYTES>>>(
            mb1 + l * FIL, mb2 + l * FIL,
            w1h + l * 16384, w1l + l * 16384,
            w2h + l * 32768, w2l + l * 32768);
        linear_kernel<<<NTOT / 8, 128>>>(aggp, l2w + l * FIL * HID, l2b + l * HID, hp, 1);
    }

    out_kernel<<<NUM_G, 256, OUT_SMEM_FLOATS * sizeof(float)>>>(ow1, ob1, ow2, ob2, out);
}

// round 8
// speedup vs baseline: 1.6120x; 1.0527x over previous
#include <cuda_runtime.h>
#include <cuda_bf16.h>
#include <math.h>
#include <stdint.h>

// ---------------- problem constants ----------------
#define NG        50
#define KNB       32
#define NUM_G     64
#define ATOMS     128
#define NTOT      (NUM_G * ATOMS)     // 8192
#define HID       128
#define FIL       128
#define LAYERS    6
#define EDGES     (NTOT * KNB)        // 262144
#define NTILES    (EDGES / 128)       // 2048
#define CUTOFF    10.0f
#define PI_C      3.14159265f

#define INVALID_KEY 0xFFFFFFFFFFFFFFFFULL
typedef unsigned long long ull;

// ---------------- device scratch ----------------
__device__ int   g_idx [EDGES];
__device__ float g_dist[EDGES];
__device__ float g_cval[EDGES];
__device__ float g_h   [NTOT * HID];
__device__ float g_x1  [NTOT * FIL];
__device__ float g_agg [NTOT * FIL];

// ldmatrix-layout bf16 tile images
__device__ unsigned char g_rbf_hi[NTILES * 16384];   // per tile: [128 e][64 k]
__device__ unsigned char g_rbf_lo[NTILES * 16384];
__device__ unsigned char g_w1_hi [LAYERS * 16384];   // [128 n][64 k]
__device__ unsigned char g_w1_lo [LAYERS * 16384];
__device__ unsigned char g_w2_hi [LAYERS * 32768];   // [128 n][128 k], n-permuted
__device__ unsigned char g_w2_lo [LAYERS * 32768];

__device__ __forceinline__ float silu_f(float v) {
    return v / (1.0f + __expf(-v));
}

// ---------------- packed f32x2 helpers ----------------
__device__ __forceinline__ ull pack2(float x, float y) {
    ull r; asm("mov.b64 %0, {%1,%2};" : "=l"(r) : "f"(x), "f"(y)); return r;
}
__device__ __forceinline__ void unpack2(ull v, float& x, float& y) {
    asm("mov.b64 {%0,%1}, %2;" : "=f"(x), "=f"(y) : "l"(v));
}
__device__ __forceinline__ ull fma2(ull a, ull b, ull c) {
    ull d; asm("fma.rn.f32x2 %0, %1, %2, %3;" : "=l"(d) : "l"(a), "l"(b), "l"(c));
    return d;
}
__device__ __forceinline__ void red_add_v4(float* p, float a, float b, float c, float d) {
    asm volatile("red.global.add.v4.f32 [%0], {%1,%2,%3,%4};"
                 :: "l"(p), "f"(a), "f"(b), "f"(c), "f"(d) : "memory");
}

__device__ __forceinline__ uint32_t smem_u32(const void* p) {
    uint32_t a;
    asm("{ .reg .u64 t; cvta.to.shared.u64 t, %1; cvt.u32.u64 %0, t; }" : "=r"(a) : "l"(p));
    return a;
}

// ---------------- cp.async helpers ----------------
__device__ __forceinline__ void cp_async16(uint32_t saddr, const void* gaddr) {
    asm volatile("cp.async.cg.shared.global [%0], [%1], 16;" :: "r"(saddr), "l"(gaddr));
}
#define CP_COMMIT() asm volatile("cp.async.commit_group;" ::: "memory")
#define CP_WAIT0()  asm volatile("cp.async.wait_group 0;" ::: "memory")

// ---------------- mma.sync / ldmatrix helpers ----------------
__device__ __forceinline__ void ldsm4(uint32_t* r, uint32_t addr) {
    asm volatile("ldmatrix.sync.aligned.m8n8.x4.shared.b16 {%0,%1,%2,%3}, [%4];"
                 : "=r"(r[0]), "=r"(r[1]), "=r"(r[2]), "=r"(r[3]) : "r"(addr));
}
__device__ __forceinline__ void mma16816(float* c, const uint32_t* a, uint32_t b0, uint32_t b1) {
    asm volatile("mma.sync.aligned.m16n8k16.row.col.f32.bf16.bf16.f32 "
                 "{%0,%1,%2,%3}, {%4,%5,%6,%7}, {%8,%9}, {%0,%1,%2,%3};"
                 : "+f"(c[0]), "+f"(c[1]), "+f"(c[2]), "+f"(c[3])
                 : "r"(a[0]), "r"(a[1]), "r"(a[2]), "r"(a[3]), "r"(b0), "r"(b1));
}

// swizzled byte offsets
__device__ __forceinline__ uint32_t off1(int r, int k) {
    return (uint32_t)(r * 128 + (((k >> 3) ^ (r & 7)) << 4) + (k & 7) * 2);
}
__device__ __forceinline__ uint32_t off2(int r, int k) {
    return (uint32_t)(r * 256 + (((k >> 3) ^ (r & 7)) << 4) + (k & 7) * 2);
}
// output-channel permutation for red.v4-friendly epilogue
__device__ __forceinline__ int perm_n(int n) {
    const int a = n >> 3, q = (n >> 1) & 3, h = n & 1;
    return ((a >> 1) << 4) + (q << 2) + ((a & 1) << 1) + h;
}

// ---------------- graph build: warp-per-node, shfl min-reduce ----------------
__global__ void build_graph_kernel(const float* __restrict__ pos,
                                   const int* __restrict__ batch)
{
    const int wid  = threadIdx.x >> 5;
    const int lane = threadIdx.x & 31;
    const int i    = blockIdx.x * 4 + wid;
    const int base = (i >> 7) << 7;

    const float px = pos[3*i], py = pos[3*i+1], pz = pos[3*i+2];

    ull key[4];
    #pragma unroll
    for (int c = 0; c < 4; c++) {
        const int j = base + c * 32 + lane;
        const float dx = pos[3*j]   - px;
        const float dy = pos[3*j+1] - py;
        const float dz = pos[3*j+2] - pz;
        const float d2 = dx*dx + dy*dy + dz*dz;
        // candidates are same-graph by construction; exclude self + cutoff
        key[c] = (j != i && d2 < CUTOFF*CUTOFF)
            ? ((((ull)__float_as_uint(d2)) << 32) | (unsigned int)j)
            : INVALID_KEY;
    }

    for (int k = 0; k < KNB; k++) {
        ull m0 = key[0] < key[1] ? key[0] : key[1];
        ull m1 = key[2] < key[3] ? key[2] : key[3];
        ull m  = m0 < m1 ? m0 : m1;
        #pragma unroll
        for (int s = 16; s >= 1; s >>= 1) {
            ull o = __shfl_xor_sync(0xffffffffu, m, s);
            if (o < m) m = o;
        }
        #pragma unroll
        for (int c = 0; c < 4; c++)
            if (key[c] == m) key[c] = INVALID_KEY;
        if (lane == k) {
            const int eo = i * KNB + k;
            if (m != INVALID_KEY) {
                const int   jj = (int)(m & 0xffffffffu);
                const float d  = sqrtf(__uint_as_float((unsigned int)(m >> 32)));
                g_idx[eo]  = jj;
                g_dist[eo] = d;
                const float cv = 0.5f * (cosf(d * (PI_C / CUTOFF)) + 1.0f);
                g_cval[eo] = (d < CUTOFF) ? cv : 0.0f;
            } else {
                g_idx[eo]  = i;
                g_dist[eo] = 1.0f;
                g_cval[eo] = 0.0f;
            }
        }
    }
}

// ---------------- fused prep: rbf + w1 + w2(perm) + embed ----------------
#define PREP_RBF   (EDGES * 64)
#define PREP_W1    (LAYERS * 128 * 64)
#define PREP_W2    (LAYERS * 128 * 128)
#define PREP_EMB   (NTOT * HID)
#define PREP_TOTAL (PREP_RBF + PREP_W1 + PREP_W2 + PREP_EMB)

__global__ void prep_all_kernel(const float* __restrict__ mw1,
                                const float* __restrict__ mw2,
                                const int* __restrict__ z,
                                const float* __restrict__ emb)
{
    const int id = blockIdx.x * blockDim.x + threadIdx.x;
    if (id < PREP_RBF) {
        const int e = id >> 6;
        const int k = id & 63;
        const int tile = e >> 7;
        const int r    = e & 127;
        float val = 0.0f;
        if (k < NG) {
            const float w = CUTOFF / (float)(NG - 1);
            const float t = (g_dist[e] - (float)k * w) / w;
            val = expf(-0.5f * t * t);
        }
        const __nv_bfloat16 hi = __float2bfloat16(val);
        const __nv_bfloat16 lo = __float2bfloat16(val - __bfloat162float(hi));
        const uint32_t o = (uint32_t)tile * 16384u + off1(r, k);
        *(unsigned short*)(g_rbf_hi + o) = __bfloat16_as_ushort(hi);
        *(unsigned short*)(g_rbf_lo + o) = __bfloat16_as_ushort(lo);
    } else if (id < PREP_RBF + PREP_W1) {
        const int t = id - PREP_RBF;
        const int l = t >> 13;
        const int n = (t >> 6) & 127;
        const int k = t & 63;
        const float val = (k < NG) ? mw1[l * NG * FIL + k * FIL + n] : 0.0f;
        const __nv_bfloat16 hi = __float2bfloat16(val);
        const __nv_bfloat16 lo = __float2bfloat16(val - __bfloat162float(hi));
        const uint32_t o = (uint32_t)l * 16384u + off1(n, k);
        *(unsigned short*)(g_w1_hi + o) = __bfloat16_as_ushort(hi);
        *(unsigned short*)(g_w1_lo + o) = __bfloat16_as_ushort(lo);
    } else if (id < PREP_RBF + PREP_W1 + PREP_W2) {
        const int t = id - PREP_RBF - PREP_W1;
        const int l = t >> 14;
        const int n = (t >> 7) & 127;
        const int k = t & 127;
        const float val = mw2[l * FIL * FIL + k * FIL + perm_n(n)];
        const __nv_bfloat16 hi = __float2bfloat16(val);
        const __nv_bfloat16 lo = __float2bfloat16(val - __bfloat162float(hi));
        const uint32_t o = (uint32_t)l * 32768u + off2(n, k);
        *(unsigned short*)(g_w2_hi + o) = __bfloat16_as_ushort(hi);
        *(unsigned short*)(g_w2_lo + o) = __bfloat16_as_ushort(lo);
    } else if (id < PREP_TOTAL) {
        const int t = id - PREP_RBF - PREP_W1 - PREP_W2;
        const int n = t >> 7;
        const int c = t & 127;
        g_h[t] = emb[z[n] * HID + c];
    }
}

// ---------------- node linear (f32x2, 8 rows/block); mode0 also zeroes g_agg ----
__global__ void linear_kernel(const float* __restrict__ x,
                              const float* __restrict__ W,
                              const float* __restrict__ b,
                              float* __restrict__ y,
                              int mode)
{
    __shared__ float xs[128 * 8];       // [k][e]
    const int c  = threadIdx.x;
    const int r0 = blockIdx.x * 8;

    #pragma unroll
    for (int e = 0; e < 8; e++)
        xs[c * 8 + e] = x[(r0 + e) * 128 + c];
    __syncthreads();

    ull acc[4];
    #pragma unroll
    for (int p = 0; p < 4; p++) acc[p] = 0ULL;

    #pragma unroll 4
    for (int k = 0; k < 128; k++) {
        const float w = W[k * 128 + c];
        const ull wp = pack2(w, w);
        const float* xp = &xs[k * 8];
        #pragma unroll
        for (int p = 0; p < 4; p++) {
            const ull xv = *(const ull*)(xp + 2 * p);
            acc[p] = fma2(xv, wp, acc[p]);
        }
    }
    const float bias = b[c];
    if (mode == 0) {
        #pragma unroll
        for (int p = 0; p < 4; p++) {
            float lo, hi; unpack2(acc[p], lo, hi);
            y[(r0 + 2*p)     * 128 + c] = lo + bias;
            y[(r0 + 2*p + 1) * 128 + c] = hi + bias;
        }
        #pragma unroll
        for (int e = 0; e < 8; e++) g_agg[(r0 + e) * 128 + c] = 0.0f;
    } else {
        #pragma unroll
        for (int p = 0; p < 4; p++) {
            float lo, hi; unpack2(acc[p], lo, hi);
            y[(r0 + 2*p)     * 128 + c] += silu_f(lo + bias);
            y[(r0 + 2*p + 1) * 128 + c] += silu_f(hi + bias);
        }
    }
}

// ---------------- tensor-core (mma.sync) filter kernel, 1024 threads ----------------
#define SO_A1HI 0
#define SO_A1LO 16384
#define SO_A2HI 32768
#define SO_A2LO 65536
#define SO_B1HI 98304
#define SO_B1LO 114688
#define SO_B2HI 131072
#define SO_B2LO 163840
#define SO_AUX  196608
// per-parity aux block (5120 B each): X1P 2048 | X1Q 2048 | CV 512 | DST 512
#define AUXB_X1P 0
#define AUXB_X1Q 2048
#define AUXB_CV  4096
#define AUXB_DST 4608
#define AUX_B1   10240            // shared bias (512 B)
#define FILT_SMEM_BYTES (SO_AUX + 10752)

__global__ void __launch_bounds__(1024, 1)
filter_mma_kernel(const float* __restrict__ b1g, const float* __restrict__ b2g,
                  const unsigned char* __restrict__ w1hi, const unsigned char* __restrict__ w1lo,
                  const unsigned char* __restrict__ w2hi, const unsigned char* __restrict__ w2lo)
{
    extern __shared__ unsigned char base[];
    const uint32_t base32 = smem_u32(base);

    const int tid  = threadIdx.x;
    const int lane = tid & 31;
    const int wid  = tid >> 5;
    const int wm   = wid & 7;          // warp m-tile: 16 edges (0..7)
    const int wn   = wid >> 3;         // warp n-tile: 32 channels (0..3)
    const int m0w  = wm * 16;
    const int n0w  = wn * 32;

    float* sb1 = (float*)(base + SO_AUX + AUX_B1);

    // resident weight copies
    {
        const uint4* s1h = (const uint4*)w1hi;  const uint4* s1l = (const uint4*)w1lo;
        const uint4* s2h = (const uint4*)w2hi;  const uint4* s2l = (const uint4*)w2lo;
        uint4* d1h = (uint4*)(base + SO_B1HI);  uint4* d1l = (uint4*)(base + SO_B1LO);
        uint4* d2h = (uint4*)(base + SO_B2HI);  uint4* d2l = (uint4*)(base + SO_B2LO);
        if (tid < 1024) { d1h[tid] = s1h[tid]; d1l[tid] = s1l[tid]; }
        for (int i = tid; i < 2048; i += 1024) { d2h[i] = s2h[i]; d2l[i] = s2l[i]; }
        if (tid < 128) sb1[tid] = b1g[tid];
    }

    // prefetch first tile's A1 via cp.async
    if (blockIdx.x < NTILES) {
        const size_t tb = (size_t)blockIdx.x * 16384;
        if (tid < 1024) {
            cp_async16(base32 + SO_A1HI + tid * 16, g_rbf_hi + tb + tid * 16);
            cp_async16(base32 + SO_A1LO + tid * 16, g_rbf_lo + tb + tid * 16);
        }
    }
    CP_COMMIT();

    const int lr = lane & 15;          // row within 16
    const int lk = (lane >> 4) * 8;    // k-block 0/8

    int par = 0;
    for (int tile = blockIdx.x; tile < NTILES; tile += gridDim.x, par ^= 1) {
        const int e0 = tile * 128;
        unsigned char* aux = base + SO_AUX + par * 5120;
        float* sx1p = (float*)(aux + AUXB_X1P);
        float* sx1q = (float*)(aux + AUXB_X1Q);
        float* scv  = (float*)(aux + AUXB_CV);
        int*   sdst = (int*)  (aux + AUXB_DST);

        // ---- aux stage (parity buffer) ----
        if (tid < 128) { scv[tid] = g_cval[e0 + tid]; sdst[tid] = g_idx[e0 + tid]; }
        if (tid < 512) {
            const int jj = tid >> 7, c = tid & 127;
            const float v = g_x1[(4 * tile + jj) * 128 + c];
            sx1p[tid] = v;
            sx1q[tid] = v * b2g[c];
        }
        CP_WAIT0();
        __syncthreads();

        float acc[4][4];
        #pragma unroll
        for (int nj = 0; nj < 4; nj++)
            #pragma unroll
            for (int q = 0; q < 4; q++) acc[nj][q] = 0.0f;

        // ---- GEMM1: K=64 ----
        #pragma unroll
        for (int ks = 0; ks < 4; ks++) {
            const int kb = ks * 16 + lk;
            uint32_t Ah[4], Al[4];
            {
                const uint32_t o = off1(m0w + lr, kb);
                ldsm4(Ah, base32 + SO_A1HI + o);
                ldsm4(Al, base32 + SO_A1LO + o);
            }
            #pragma unroll
            for (int nt = 0; nt < 2; nt++) {
                uint32_t Bh[4], Bl[4];
                const uint32_t o = off1(n0w + nt * 16 + lr, kb);
                ldsm4(Bh, base32 + SO_B1HI + o);
                ldsm4(Bl, base32 + SO_B1LO + o);
                #pragma unroll
                for (int h = 0; h < 2; h++) {
                    const int nj = nt * 2 + h;
                    mma16816(acc[nj], Ah, Bh[h], Bh[2 + h]);
                    mma16816(acc[nj], Ah, Bl[h], Bl[2 + h]);
                    mma16816(acc[nj], Al, Bh[h], Bh[2 + h]);
                }
            }
        }

        // ---- epilogue1: silu, split, store A2 ----
        {
            unsigned char* a2h = base + SO_A2HI;
            unsigned char* a2l = base + SO_A2LO;
            const int rbase = m0w + (lane >> 2);
            const int cbase = n0w + (lane & 3) * 2;
            #pragma unroll
            for (int nj = 0; nj < 4; nj++) {
                const int col = cbase + nj * 8;
                const float bb0 = sb1[col], bb1 = sb1[col + 1];
                #pragma unroll
                for (int half = 0; half < 2; half++) {
                    const int row = rbase + half * 8;
                    const float s0 = silu_f(acc[nj][half * 2]     + bb0);
                    const float s1 = silu_f(acc[nj][half * 2 + 1] + bb1);
                    const __nv_bfloat16 h0 = __float2bfloat16(s0);
                    const __nv_bfloat16 h1 = __float2bfloat16(s1);
                    const __nv_bfloat16 l0 = __float2bfloat16(s0 - __bfloat162float(h0));
                    const __nv_bfloat16 l1 = __float2bfloat16(s1 - __bfloat162float(h1));
                    const uint32_t o = off2(row, col);
                    *(uint32_t*)(a2h + o) = (uint32_t)__bfloat16_as_ushort(h0) |
                                            ((uint32_t)__bfloat16_as_ushort(h1) << 16);
                    *(uint32_t*)(a2l + o) = (uint32_t)__bfloat16_as_ushort(l0) |
                                            ((uint32_t)__bfloat16_as_ushort(l1) << 16);
                }
            }
        }
        __syncthreads();

        // ---- prefetch next tile's A1 (A1 dead; overlaps GEMM2+epi2) ----
        {
            const int tnext = tile + gridDim.x;
            if (tnext < NTILES) {
                const size_t tb = (size_t)tnext * 16384;
                if (tid < 1024) {
                    cp_async16(base32 + SO_A1HI + tid * 16, g_rbf_hi + tb + tid * 16);
                    cp_async16(base32 + SO_A1LO + tid * 16, g_rbf_lo + tb + tid * 16);
                }
            }
            CP_COMMIT();
        }

        #pragma unroll
        for (int nj = 0; nj < 4; nj++)
            #pragma unroll
            for (int q = 0; q < 4; q++) acc[nj][q] = 0.0f;

        // ---- GEMM2: K=128 ----
        #pragma unroll
        for (int ks = 0; ks < 8; ks++) {
            const int kb = ks * 16 + lk;
            uint32_t Ah[4], Al[4];
            {
                const uint32_t o = off2(m0w + lr, kb);
                ldsm4(Ah, base32 + SO_A2HI + o);
                ldsm4(Al, base32 + SO_A2LO + o);
            }
            #pragma unroll
            for (int nt = 0; nt < 2; nt++) {
                uint32_t Bh[4], Bl[4];
                const uint32_t o = off2(n0w + nt * 16 + lr, kb);
                ldsm4(Bh, base32 + SO_B2HI + o);
                ldsm4(Bl, base32 + SO_B2LO + o);
                #pragma unroll
                for (int h = 0; h < 2; h++) {
                    const int nj = nt * 2 + h;
                    mma16816(acc[nj], Ah, Bh[h], Bh[2 + h]);
                    mma16816(acc[nj], Ah, Bl[h], Bl[2 + h]);
                    mma16816(acc[nj], Al, Bh[h], Bh[2 + h]);
                }
            }
        }

        // ---- epilogue2: permuted channels -> red.v4 (no trailing sync) ----
        {
            const int q4 = (lane & 3) << 2;
            const int rbase = m0w + (lane >> 2);
            const int j4 = m0w >> 5;                  // warp-uniform source row group
            const float* pv = &sx1p[j4 * 128];
            const float* qv = &sx1q[j4 * 128];
            #pragma unroll
            for (int half = 0; half < 2; half++) {
                const int row = rbase + half * 8;
                const float cv = scv[row];
                const int   dst = sdst[row];
                float* aggp = &g_agg[dst * 128];
                #pragma unroll
                for (int pj = 0; pj < 2; pj++) {
                    const int pb = n0w + (pj << 4) + q4;      // physical base, 16B aligned
                    const float4 pvv = *(const float4*)&pv[pb];
                    const float4 qvv = *(const float4*)&qv[pb];
                    const float m0 = cv * fmaf(acc[2*pj    ][half * 2],     pvv.x, qvv.x);
                    const float m1 = cv * fmaf(acc[2*pj    ][half * 2 + 1], pvv.y, qvv.y);
                    const float m2 = cv * fmaf(acc[2*pj + 1][half * 2],     pvv.z, qvv.z);
                    const float m3 = cv * fmaf(acc[2*pj + 1][half * 2 + 1], pvv.w, qvv.w);
                    red_add_v4(aggp + pb, m0, m1, m2, m3);
                }
            }
        }
        // no trailing __syncthreads: aux is parity double-buffered.
    }
}

// ---------------- output head + per-graph sum ----------------
#define OUT_SMEM_FLOATS (128*128 + 128*65)

__global__ void out_kernel(const float* __restrict__ ow1, const float* __restrict__ ob1,
                           const float* __restrict__ ow2, const float* __restrict__ ob2,
                           float* __restrict__ out)
{
    extern __shared__ float sm[];
    float* sh = sm;
    float* st = sh + 128*128;
    __shared__ float rsum[256];

    const int g    = blockIdx.x;
    const int tid  = threadIdx.x;
    const int base = g * ATOMS;

    for (int idx = tid; idx < 128 * 128; idx += 256)
        sh[idx] = g_h[base * 128 + idx];
    __syncthreads();

    const int d   = tid & 63;
    const int grp = tid >> 6;
    float acc[32];
    #pragma unroll
    for (int e = 0; e < 32; e++) acc[e] = 0.0f;
    const float* hh = sh + grp * 32 * 128;
    #pragma unroll 2
    for (int k = 0; k < 128; k++) {
        const float w = ow1[k * 64 + d];
        #pragma unroll
        for (int e = 0; e < 32; e++) acc[e] += hh[e * 128 + k] * w;
    }
    const float bb = ob1[d];
    #pragma unroll
    for (int e = 0; e < 32; e++) {
        const float v = acc[e] + bb;
        st[(grp * 32 + e) * 65 + d] = silu_f(v);
    }
    __syncthreads();

    float o = 0.0f;
    if (tid < 128) {
        float s = ob2[0];
        #pragma unroll 4
        for (int dd = 0; dd < 64; dd++) s += st[tid * 65 + dd] * ow2[dd];
        o = s;
    }
    rsum[tid] = o;
    __syncthreads();
    for (int s = 128; s >= 1; s >>= 1) {
        if (tid < s) rsum[tid] += rsum[tid + s];
        __syncthreads();
    }
    if (tid == 0) out[g] = rsum[0];
}

// ---------------- launch ----------------
extern "C" void kernel_launch(void* const* d_in, const int* in_sizes, int n_in,
                              void* d_out, int out_size)
{
    const float* pos   = (const float*)d_in[0];
    const int*   z     = (const int*)  d_in[1];
    const int*   batch = (const int*)  d_in[2];
    const float* emb   = (const float*)d_in[3];
    const float* mw1   = (const float*)d_in[4];
    const float* mb1   = (const float*)d_in[5];
    const float* mw2   = (const float*)d_in[6];
    const float* mb2   = (const float*)d_in[7];
    const float* l1w   = (const float*)d_in[8];
    const float* l1b   = (const float*)d_in[9];
    const float* l2w   = (const float*)d_in[10];
    const float* l2b   = (const float*)d_in[11];
    const float* ow1   = (const float*)d_in[12];
    const float* ob1   = (const float*)d_in[13];
    const float* ow2   = (const float*)d_in[14];
    const float* ob2   = (const float*)d_in[15];
    float* out = (float*)d_out;

    float *hp, *x1p, *aggp;
    cudaGetSymbolAddress((void**)&hp,   g_h);
    cudaGetSymbolAddress((void**)&x1p,  g_x1);
    cudaGetSymbolAddress((void**)&aggp, g_agg);
    unsigned char *w1h, *w1l, *w2h, *w2l;
    cudaGetSymbolAddress((void**)&w1h, g_w1_hi);
    cudaGetSymbolAddress((void**)&w1l, g_w1_lo);
    cudaGetSymbolAddress((void**)&w2h, g_w2_hi);
    cudaGetSymbolAddress((void**)&w2l, g_w2_lo);

    cudaFuncSetAttribute(filter_mma_kernel, cudaFuncAttributeMaxDynamicSharedMemorySize,
                         FILT_SMEM_BYTES);
    cudaFuncSetAttribute(out_kernel, cudaFuncAttributeMaxDynamicSharedMemorySize,
                         OUT_SMEM_FLOATS * (int)sizeof(float));

    build_graph_kernel<<<NTOT / 4, 128>>>(pos, batch);
    prep_all_kernel<<<(PREP_TOTAL + 255) / 256, 256>>>(mw1, mw2, z, emb);

    for (int l = 0; l < LAYERS; l++) {
        linear_kernel<<<NTOT / 8, 128>>>(hp, l1w + l * HID * FIL, l1b + l * FIL, x1p, 0);
        filter_mma_kernel<<<148, 1024, FILT_SMEM_BYTES>>>(
            mb1 + l * FIL, mb2 + l * FIL,
            w1h + l * 16384, w1l + l * 16384,
            w2h + l * 32768, w2l + l * 32768);
        linear_kernel<<<NTOT / 8, 128>>>(aggp, l2w + l * FIL * HID, l2b + l * HID, hp, 1);
    }

    out_kernel<<<NUM_G, 256, OUT_SMEM_FLOATS * sizeof(float)>>>(ow1, ob1, ow2, ob2, out);
}

// round 9
// speedup vs baseline: 1.8719x; 1.1612x over previous
#include <cuda_runtime.h>
#include <cuda_bf16.h>
#include <math.h>
#include <stdint.h>

// ---------------- problem constants ----------------
#define NG        50
#define KNB       32
#define NUM_G     64
#define ATOMS     128
#define NTOT      (NUM_G * ATOMS)     // 8192
#define HID       128
#define FIL       128
#define LAYERS    6
#define EDGES     (NTOT * KNB)        // 262144
#define NTILES    (EDGES / 128)       // 2048
#define CUTOFF    10.0f
#define PI_C      3.14159265f

#define INVALID_KEY 0xFFFFFFFFFFFFFFFFULL
typedef unsigned long long ull;

// ---------------- device scratch ----------------
__device__ int   g_idx [EDGES];
__device__ float g_dist[EDGES];
__device__ float g_cval[EDGES];
__device__ float g_h   [NTOT * HID];
__device__ float g_x1  [NTOT * FIL];
__device__ float g_agg [NTOT * FIL];

// ldmatrix-layout bf16 tile images
__device__ unsigned char g_rbf_hi[NTILES * 16384];   // per tile: [128 e][64 k]
__device__ unsigned char g_rbf_lo[NTILES * 16384];
__device__ unsigned char g_w1_hi [LAYERS * 16384];   // [128 n][64 k]
__device__ unsigned char g_w2_hi [LAYERS * 32768];   // [128 n][128 k], n-permuted

__device__ __forceinline__ float silu_f(float v) {
    return v / (1.0f + __expf(-v));
}

// ---------------- packed f32x2 helpers ----------------
__device__ __forceinline__ ull pack2(float x, float y) {
    ull r; asm("mov.b64 %0, {%1,%2};" : "=l"(r) : "f"(x), "f"(y)); return r;
}
__device__ __forceinline__ void unpack2(ull v, float& x, float& y) {
    asm("mov.b64 {%0,%1}, %2;" : "=f"(x), "=f"(y) : "l"(v));
}
__device__ __forceinline__ ull fma2(ull a, ull b, ull c) {
    ull d; asm("fma.rn.f32x2 %0, %1, %2, %3;" : "=l"(d) : "l"(a), "l"(b), "l"(c));
    return d;
}
__device__ __forceinline__ void red_add_v4(float* p, float a, float b, float c, float d) {
    asm volatile("red.global.add.v4.f32 [%0], {%1,%2,%3,%4};"
                 :: "l"(p), "f"(a), "f"(b), "f"(c), "f"(d) : "memory");
}

__device__ __forceinline__ uint32_t smem_u32(const void* p) {
    uint32_t a;
    asm("{ .reg .u64 t; cvta.to.shared.u64 t, %1; cvt.u32.u64 %0, t; }" : "=r"(a) : "l"(p));
    return a;
}

// ---------------- cp.async helpers ----------------
__device__ __forceinline__ void cp_async16(uint32_t saddr, const void* gaddr) {
    asm volatile("cp.async.cg.shared.global [%0], [%1], 16;" :: "r"(saddr), "l"(gaddr));
}
#define CP_COMMIT() asm volatile("cp.async.commit_group;" ::: "memory")
#define CP_WAIT0()  asm volatile("cp.async.wait_group 0;" ::: "memory")

// ---------------- mma.sync / ldmatrix helpers ----------------
__device__ __forceinline__ void ldsm4(uint32_t* r, uint32_t addr) {
    asm volatile("ldmatrix.sync.aligned.m8n8.x4.shared.b16 {%0,%1,%2,%3}, [%4];"
                 : "=r"(r[0]), "=r"(r[1]), "=r"(r[2]), "=r"(r[3]) : "r"(addr));
}
__device__ __forceinline__ void mma16816(float* c, const uint32_t* a, uint32_t b0, uint32_t b1) {
    asm volatile("mma.sync.aligned.m16n8k16.row.col.f32.bf16.bf16.f32 "
                 "{%0,%1,%2,%3}, {%4,%5,%6,%7}, {%8,%9}, {%0,%1,%2,%3};"
                 : "+f"(c[0]), "+f"(c[1]), "+f"(c[2]), "+f"(c[3])
                 : "r"(a[0]), "r"(a[1]), "r"(a[2]), "r"(a[3]), "r"(b0), "r"(b1));
}

// swizzled byte offsets
__device__ __forceinline__ uint32_t off1(int r, int k) {
    return (uint32_t)(r * 128 + (((k >> 3) ^ (r & 7)) << 4) + (k & 7) * 2);
}
__device__ __forceinline__ uint32_t off2(int r, int k) {
    return (uint32_t)(r * 256 + (((k >> 3) ^ (r & 7)) << 4) + (k & 7) * 2);
}
// output-channel permutation for red.v4-friendly epilogue
__device__ __forceinline__ int perm_n(int n) {
    const int a = n >> 3, q = (n >> 1) & 3, h = n & 1;
    return ((a >> 1) << 4) + (q << 2) + ((a & 1) << 1) + h;
}

// ---------------- graph build: warp-per-node, shfl min-reduce ----------------
__global__ void build_graph_kernel(const float* __restrict__ pos,
                                   const int* __restrict__ batch)
{
    const int wid  = threadIdx.x >> 5;
    const int lane = threadIdx.x & 31;
    const int i    = blockIdx.x * 4 + wid;
    const int base = (i >> 7) << 7;

    const float px = pos[3*i], py = pos[3*i+1], pz = pos[3*i+2];

    ull key[4];
    #pragma unroll
    for (int c = 0; c < 4; c++) {
        const int j = base + c * 32 + lane;
        const float dx = pos[3*j]   - px;
        const float dy = pos[3*j+1] - py;
        const float dz = pos[3*j+2] - pz;
        const float d2 = dx*dx + dy*dy + dz*dz;
        key[c] = (j != i && d2 < CUTOFF*CUTOFF)
            ? ((((ull)__float_as_uint(d2)) << 32) | (unsigned int)j)
            : INVALID_KEY;
    }

    for (int k = 0; k < KNB; k++) {
        ull m0 = key[0] < key[1] ? key[0] : key[1];
        ull m1 = key[2] < key[3] ? key[2] : key[3];
        ull m  = m0 < m1 ? m0 : m1;
        #pragma unroll
        for (int s = 16; s >= 1; s >>= 1) {
            ull o = __shfl_xor_sync(0xffffffffu, m, s);
            if (o < m) m = o;
        }
        #pragma unroll
        for (int c = 0; c < 4; c++)
            if (key[c] == m) key[c] = INVALID_KEY;
        if (lane == k) {
            const int eo = i * KNB + k;
            if (m != INVALID_KEY) {
                const int   jj = (int)(m & 0xffffffffu);
                const float d  = sqrtf(__uint_as_float((unsigned int)(m >> 32)));
                g_idx[eo]  = jj;
                g_dist[eo] = d;
                const float cv = 0.5f * (cosf(d * (PI_C / CUTOFF)) + 1.0f);
                g_cval[eo] = (d < CUTOFF) ? cv : 0.0f;
            } else {
                g_idx[eo]  = i;
                g_dist[eo] = 1.0f;
                g_cval[eo] = 0.0f;
            }
        }
    }
}

// ---------------- fused prep: rbf(hi+lo) + w1(hi) + w2(hi,perm) + embed ----------------
#define PREP_RBF   (EDGES * 64)
#define PREP_W1    (LAYERS * 128 * 64)
#define PREP_W2    (LAYERS * 128 * 128)
#define PREP_EMB   (NTOT * HID)
#define PREP_TOTAL (PREP_RBF + PREP_W1 + PREP_W2 + PREP_EMB)

__global__ void prep_all_kernel(const float* __restrict__ mw1,
                                const float* __restrict__ mw2,
                                const int* __restrict__ z,
                                const float* __restrict__ emb)
{
    const int id = blockIdx.x * blockDim.x + threadIdx.x;
    if (id < PREP_RBF) {
        const int e = id >> 6;
        const int k = id & 63;
        const int tile = e >> 7;
        const int r    = e & 127;
        float val = 0.0f;
        if (k < NG) {
            const float w = CUTOFF / (float)(NG - 1);
            const float t = (g_dist[e] - (float)k * w) / w;
            val = expf(-0.5f * t * t);
        }
        const __nv_bfloat16 hi = __float2bfloat16(val);
        const __nv_bfloat16 lo = __float2bfloat16(val - __bfloat162float(hi));
        const uint32_t o = (uint32_t)tile * 16384u + off1(r, k);
        *(unsigned short*)(g_rbf_hi + o) = __bfloat16_as_ushort(hi);
        *(unsigned short*)(g_rbf_lo + o) = __bfloat16_as_ushort(lo);
    } else if (id < PREP_RBF + PREP_W1) {
        const int t = id - PREP_RBF;
        const int l = t >> 13;
        const int n = (t >> 6) & 127;
        const int k = t & 63;
        const float val = (k < NG) ? mw1[l * NG * FIL + k * FIL + n] : 0.0f;
        const uint32_t o = (uint32_t)l * 16384u + off1(n, k);
        *(unsigned short*)(g_w1_hi + o) = __bfloat16_as_ushort(__float2bfloat16(val));
    } else if (id < PREP_RBF + PREP_W1 + PREP_W2) {
        const int t = id - PREP_RBF - PREP_W1;
        const int l = t >> 14;
        const int n = (t >> 7) & 127;
        const int k = t & 127;
        const float val = mw2[l * FIL * FIL + k * FIL + perm_n(n)];
        const uint32_t o = (uint32_t)l * 32768u + off2(n, k);
        *(unsigned short*)(g_w2_hi + o) = __bfloat16_as_ushort(__float2bfloat16(val));
    } else if (id < PREP_TOTAL) {
        const int t = id - PREP_RBF - PREP_W1 - PREP_W2;
        const int n = t >> 7;
        const int c = t & 127;
        g_h[t] = emb[z[n] * HID + c];
    }
}

// ---------------- node linear (f32x2, 8 rows/block); mode0 also zeroes g_agg ----
__global__ void linear_kernel(const float* __restrict__ x,
                              const float* __restrict__ W,
                              const float* __restrict__ b,
                              float* __restrict__ y,
                              int mode)
{
    __shared__ float xs[128 * 8];       // [k][e]
    const int c  = threadIdx.x;
    const int r0 = blockIdx.x * 8;

    #pragma unroll
    for (int e = 0; e < 8; e++)
        xs[c * 8 + e] = x[(r0 + e) * 128 + c];
    __syncthreads();

    ull acc[4];
    #pragma unroll
    for (int p = 0; p < 4; p++) acc[p] = 0ULL;

    #pragma unroll 4
    for (int k = 0; k < 128; k++) {
        const float w = W[k * 128 + c];
        const ull wp = pack2(w, w);
        const float* xp = &xs[k * 8];
        #pragma unroll
        for (int p = 0; p < 4; p++) {
            const ull xv = *(const ull*)(xp + 2 * p);
            acc[p] = fma2(xv, wp, acc[p]);
        }
    }
    const float bias = b[c];
    if (mode == 0) {
        #pragma unroll
        for (int p = 0; p < 4; p++) {
            float lo, hi; unpack2(acc[p], lo, hi);
            y[(r0 + 2*p)     * 128 + c] = lo + bias;
            y[(r0 + 2*p + 1) * 128 + c] = hi + bias;
        }
        #pragma unroll
        for (int e = 0; e < 8; e++) g_agg[(r0 + e) * 128 + c] = 0.0f;
    } else {
        #pragma unroll
        for (int p = 0; p < 4; p++) {
            float lo, hi; unpack2(acc[p], lo, hi);
            y[(r0 + 2*p)     * 128 + c] += silu_f(lo + bias);
            y[(r0 + 2*p + 1) * 128 + c] += silu_f(hi + bias);
        }
    }
}

// ---------------- tensor-core (mma.sync) filter kernel, 1024 threads, 2-term split ----
#define SO_A1HI 0
#define SO_A1LO 16384
#define SO_A2HI 32768
#define SO_A2LO 65536
#define SO_B1HI 98304
#define SO_B2HI 114688
#define SO_AUX  147456
// per-parity aux block (5120 B each): X1P 2048 | X1Q 2048 | CV 512 | DST 512
#define AUXB_X1P 0
#define AUXB_X1Q 2048
#define AUXB_CV  4096
#define AUXB_DST 4608
#define AUX_B1   10240            // shared bias (512 B)
#define FILT_SMEM_BYTES (SO_AUX + 10752)

__global__ void __launch_bounds__(1024, 1)
filter_mma_kernel(const float* __restrict__ b1g, const float* __restrict__ b2g,
                  const unsigned char* __restrict__ w1hi,
                  const unsigned char* __restrict__ w2hi)
{
    extern __shared__ unsigned char base[];
    const uint32_t base32 = smem_u32(base);

    const int tid  = threadIdx.x;
    const int lane = tid & 31;
    const int wid  = tid >> 5;
    const int wm   = wid & 7;          // warp m-tile: 16 edges (0..7)
    const int wn   = wid >> 3;         // warp n-tile: 32 channels (0..3)
    const int m0w  = wm * 16;
    const int n0w  = wn * 32;

    float* sb1 = (float*)(base + SO_AUX + AUX_B1);

    // resident weight copies (hi only)
    {
        const uint4* s1h = (const uint4*)w1hi;
        const uint4* s2h = (const uint4*)w2hi;
        uint4* d1h = (uint4*)(base + SO_B1HI);
        uint4* d2h = (uint4*)(base + SO_B2HI);
        if (tid < 1024) d1h[tid] = s1h[tid];
        for (int i = tid; i < 2048; i += 1024) d2h[i] = s2h[i];
        if (tid < 128) sb1[tid] = b1g[tid];
    }

    // prefetch first tile's A1 via cp.async
    if (blockIdx.x < NTILES) {
        const size_t tb = (size_t)blockIdx.x * 16384;
        if (tid < 1024) {
            cp_async16(base32 + SO_A1HI + tid * 16, g_rbf_hi + tb + tid * 16);
            cp_async16(base32 + SO_A1LO + tid * 16, g_rbf_lo + tb + tid * 16);
        }
    }
    CP_COMMIT();

    const int lr = lane & 15;          // row within 16
    const int lk = (lane >> 4) * 8;    // k-block 0/8

    int par = 0;
    for (int tile = blockIdx.x; tile < NTILES; tile += gridDim.x, par ^= 1) {
        const int e0 = tile * 128;
        unsigned char* aux = base + SO_AUX + par * 5120;
        float* sx1p = (float*)(aux + AUXB_X1P);
        float* sx1q = (float*)(aux + AUXB_X1Q);
        float* scv  = (float*)(aux + AUXB_CV);
        int*   sdst = (int*)  (aux + AUXB_DST);

        // ---- aux stage (parity buffer) ----
        if (tid < 128) { scv[tid] = g_cval[e0 + tid]; sdst[tid] = g_idx[e0 + tid]; }
        if (tid < 512) {
            const int jj = tid >> 7, c = tid & 127;
            const float v = g_x1[(4 * tile + jj) * 128 + c];
            sx1p[tid] = v;
            sx1q[tid] = v * b2g[c];
        }
        CP_WAIT0();
        __syncthreads();

        float acc[4][4];
        #pragma unroll
        for (int nj = 0; nj < 4; nj++)
            #pragma unroll
            for (int q = 0; q < 4; q++) acc[nj][q] = 0.0f;

        // ---- GEMM1: K=64, 2-term (A hi+lo, B hi) ----
        #pragma unroll
        for (int ks = 0; ks < 4; ks++) {
            const int kb = ks * 16 + lk;
            uint32_t Ah[4], Al[4];
            {
                const uint32_t o = off1(m0w + lr, kb);
                ldsm4(Ah, base32 + SO_A1HI + o);
                ldsm4(Al, base32 + SO_A1LO + o);
            }
            #pragma unroll
            for (int nt = 0; nt < 2; nt++) {
                uint32_t Bh[4];
                const uint32_t o = off1(n0w + nt * 16 + lr, kb);
                ldsm4(Bh, base32 + SO_B1HI + o);
                #pragma unroll
                for (int h = 0; h < 2; h++) {
                    const int nj = nt * 2 + h;
                    mma16816(acc[nj], Ah, Bh[h], Bh[2 + h]);
                    mma16816(acc[nj], Al, Bh[h], Bh[2 + h]);
                }
            }
        }

        // ---- epilogue1: silu, split, store A2 ----
        {
            unsigned char* a2h = base + SO_A2HI;
            unsigned char* a2l = base + SO_A2LO;
            const int rbase = m0w + (lane >> 2);
            const int cbase = n0w + (lane & 3) * 2;
            #pragma unroll
            for (int nj = 0; nj < 4; nj++) {
                const int col = cbase + nj * 8;
                const float bb0 = sb1[col], bb1 = sb1[col + 1];
                #pragma unroll
                for (int half = 0; half < 2; half++) {
                    const int row = rbase + half * 8;
                    const float s0 = silu_f(acc[nj][half * 2]     + bb0);
                    const float s1 = silu_f(acc[nj][half * 2 + 1] + bb1);
                    const __nv_bfloat16 h0 = __float2bfloat16(s0);
                    const __nv_bfloat16 h1 = __float2bfloat16(s1);
                    const __nv_bfloat16 l0 = __float2bfloat16(s0 - __bfloat162float(h0));
                    const __nv_bfloat16 l1 = __float2bfloat16(s1 - __bfloat162float(h1));
                    const uint32_t o = off2(row, col);
                    *(uint32_t*)(a2h + o) = (uint32_t)__bfloat16_as_ushort(h0) |
                                            ((uint32_t)__bfloat16_as_ushort(h1) << 16);
                    *(uint32_t*)(a2l + o) = (uint32_t)__bfloat16_as_ushort(l0) |
                                            ((uint32_t)__bfloat16_as_ushort(l1) << 16);
                }
            }
        }
        __syncthreads();

        // ---- prefetch next tile's A1 (A1 dead; overlaps GEMM2+epi2) ----
        {
            const int tnext = tile + gridDim.x;
            if (tnext < NTILES) {
                const size_t tb = (size_t)tnext * 16384;
                if (tid < 1024) {
                    cp_async16(base32 + SO_A1HI + tid * 16, g_rbf_hi + tb + tid * 16);
                    cp_async16(base32 + SO_A1LO + tid * 16, g_rbf_lo + tb + tid * 16);
                }
            }
            CP_COMMIT();
        }

        #pragma unroll
        for (int nj = 0; nj < 4; nj++)
            #pragma unroll
            for (int q = 0; q < 4; q++) acc[nj][q] = 0.0f;

        // ---- GEMM2: K=128, 2-term ----
        #pragma unroll
        for (int ks = 0; ks < 8; ks++) {
            const int kb = ks * 16 + lk;
            uint32_t Ah[4], Al[4];
            {
                const uint32_t o = off2(m0w + lr, kb);
                ldsm4(Ah, base32 + SO_A2HI + o);
                ldsm4(Al, base32 + SO_A2LO + o);
            }
            #pragma unroll
            for (int nt = 0; nt < 2; nt++) {
                uint32_t Bh[4];
                const uint32_t o = off2(n0w + nt * 16 + lr, kb);
                ldsm4(Bh, base32 + SO_B2HI + o);
                #pragma unroll
                for (int h = 0; h < 2; h++) {
                    const int nj = nt * 2 + h;
                    mma16816(acc[nj], Ah, Bh[h], Bh[2 + h]);
                    mma16816(acc[nj], Al, Bh[h], Bh[2 + h]);
                }
            }
        }

        // ---- epilogue2: permuted channels -> red.v4 (no trailing sync) ----
        {
            const int q4 = (lane & 3) << 2;
            const int rbase = m0w + (lane >> 2);
            const int j4 = m0w >> 5;                  // warp-uniform source row group
            const float* pv = &sx1p[j4 * 128];
            const float* qv = &sx1q[j4 * 128];
            #pragma unroll
            for (int half = 0; half < 2; half++) {
                const int row = rbase + half * 8;
                const float cv = scv[row];
                const int   dst = sdst[row];
                float* aggp = &g_agg[dst * 128];
                #pragma unroll
                for (int pj = 0; pj < 2; pj++) {
                    const int pb = n0w + (pj << 4) + q4;      // physical base, 16B aligned
                    const float4 pvv = *(const float4*)&pv[pb];
                    const float4 qvv = *(const float4*)&qv[pb];
                    const float m0 = cv * fmaf(acc[2*pj    ][half * 2],     pvv.x, qvv.x);
                    const float m1 = cv * fmaf(acc[2*pj    ][half * 2 + 1], pvv.y, qvv.y);
                    const float m2 = cv * fmaf(acc[2*pj + 1][half * 2],     pvv.z, qvv.z);
                    const float m3 = cv * fmaf(acc[2*pj + 1][half * 2 + 1], pvv.w, qvv.w);
                    red_add_v4(aggp + pb, m0, m1, m2, m3);
                }
            }
        }
        // no trailing __syncthreads: aux is parity double-buffered.
    }
}

// ---------------- output head + per-graph sum ----------------
#define OUT_SMEM_FLOATS (128*128 + 128*65)

__global__ void out_kernel(const float* __restrict__ ow1, const float* __restrict__ ob1,
                           const float* __restrict__ ow2, const float* __restrict__ ob2,
                           float* __restrict__ out)
{
    extern __shared__ float sm[];
    float* sh = sm;
    float* st = sh + 128*128;
    __shared__ float rsum[256];

    const int g    = blockIdx.x;
    const int tid  = threadIdx.x;
    const int base = g * ATOMS;

    for (int idx = tid; idx < 128 * 128; idx += 256)
        sh[idx] = g_h[base * 128 + idx];
    __syncthreads();

    const int d   = tid & 63;
    const int grp = tid >> 6;
    float acc[32];
    #pragma unroll
    for (int e = 0; e < 32; e++) acc[e] = 0.0f;
    const float* hh = sh + grp * 32 * 128;
    #pragma unroll 2
    for (int k = 0; k < 128; k++) {
        const float w = ow1[k * 64 + d];
        #pragma unroll
        for (int e = 0; e < 32; e++) acc[e] += hh[e * 128 + k] * w;
    }
    const float bb = ob1[d];
    #pragma unroll
    for (int e = 0; e < 32; e++) {
        const float v = acc[e] + bb;
        st[(grp * 32 + e) * 65 + d] = silu_f(v);
    }
    __syncthreads();

    float o = 0.0f;
    if (tid < 128) {
        float s = ob2[0];
        #pragma unroll 4
        for (int dd = 0; dd < 64; dd++) s += st[tid * 65 + dd] * ow2[dd];
        o = s;
    }
    rsum[tid] = o;
    __syncthreads();
    for (int s = 128; s >= 1; s >>= 1) {
        if (tid < s) rsum[tid] += rsum[tid + s];
        __syncthreads();
    }
    if (tid == 0) out[g] = rsum[0];
}

// ---------------- launch ----------------
extern "C" void kernel_launch(void* const* d_in, const int* in_sizes, int n_in,
                              void* d_out, int out_size)
{
    const float* pos   = (const float*)d_in[0];
    const int*   z     = (const int*)  d_in[1];
    const int*   batch = (const int*)  d_in[2];
    const float* emb   = (const float*)d_in[3];
    const float* mw1   = (const float*)d_in[4];
    const float* mb1   = (const float*)d_in[5];
    const float* mw2   = (const float*)d_in[6];
    const float* mb2   = (const float*)d_in[7];
    const float* l1w   = (const float*)d_in[8];
    const float* l1b   = (const float*)d_in[9];
    const float* l2w   = (const float*)d_in[10];
    const float* l2b   = (const float*)d_in[11];
    const float* ow1   = (const float*)d_in[12];
    const float* ob1   = (const float*)d_in[13];
    const float* ow2   = (const float*)d_in[14];
    const float* ob2   = (const float*)d_in[15];
    float* out = (float*)d_out;

    float *hp, *x1p, *aggp;
    cudaGetSymbolAddress((void**)&hp,   g_h);
    cudaGetSymbolAddress((void**)&x1p,  g_x1);
    cudaGetSymbolAddress((void**)&aggp, g_agg);
    unsigned char *w1h, *w2h;
    cudaGetSymbolAddress((void**)&w1h, g_w1_hi);
    cudaGetSymbolAddress((void**)&w2h, g_w2_hi);

    cudaFuncSetAttribute(filter_mma_kernel, cudaFuncAttributeMaxDynamicSharedMemorySize,
                         FILT_SMEM_BYTES);
    cudaFuncSetAttribute(out_kernel, cudaFuncAttributeMaxDynamicSharedMemorySize,
                         OUT_SMEM_FLOATS * (int)sizeof(float));

    build_graph_kernel<<<NTOT / 4, 128>>>(pos, batch);
    prep_all_kernel<<<(PREP_TOTAL + 255) / 256, 256>>>(mw1, mw2, z, emb);

    for (int l = 0; l < LAYERS; l++) {
        linear_kernel<<<NTOT / 8, 128>>>(hp, l1w + l * HID * FIL, l1b + l * FIL, x1p, 0);
        filter_mma_kernel<<<148, 1024, FILT_SMEM_BYTES>>>(
            mb1 + l * FIL, mb2 + l * FIL,
            w1h + l * 16384, w2h + l * 32768);
        linear_kernel<<<NTOT / 8, 128>>>(aggp, l2w + l * FIL * HID, l2b + l * HID, hp, 1);
    }

    out_kernel<<<NUM_G, 256, OUT_SMEM_FLOATS * sizeof(float)>>>(ow1, ob1, ow2, ob2, out);
}

// round 10
// speedup vs baseline: 2.2375x; 1.1953x over previous
#include <cuda_runtime.h>
#include <cuda_bf16.h>
#include <math.h>
#include <stdint.h>

// ---------------- problem constants ----------------
#define NG        50
#define KNB       32
#define NUM_G     64
#define ATOMS     128
#define NTOT      (NUM_G * ATOMS)     // 8192
#define HID       128
#define FIL       128
#define LAYERS    6
#define EDGES     (NTOT * KNB)        // 262144
#define NTILES    (EDGES / 128)       // 2048
#define CUTOFF    10.0f
#define PI_C      3.14159265f

#define INVALID_KEY 0xFFFFFFFFFFFFFFFFULL
typedef unsigned long long ull;

// ---------------- device scratch ----------------
__device__ int   g_idx [EDGES];
__device__ float g_dist[EDGES];
__device__ float g_cval[EDGES];
__device__ float g_h   [NTOT * HID];
__device__ float g_x1  [NTOT * FIL];
__device__ float g_agg [NTOT * FIL];

// ldmatrix-layout bf16 tile images
__device__ unsigned char g_rbf_hi[NTILES * 16384];   // per tile: [128 e][64 k]
__device__ unsigned char g_w1_hi [LAYERS * 16384];   // [128 n][64 k]
__device__ unsigned char g_w2_hi [LAYERS * 32768];   // [128 n][128 k], n-permuted
__device__ unsigned char g_l1img [LAYERS * 32768];   // [128 n][128 k]
__device__ unsigned char g_l2img [LAYERS * 32768];   // [128 n][128 k]

__device__ __forceinline__ float silu_f(float v) {
    return v / (1.0f + __expf(-v));
}

__device__ __forceinline__ void red_add_v4(float* p, float a, float b, float c, float d) {
    asm volatile("red.global.add.v4.f32 [%0], {%1,%2,%3,%4};"
                 :: "l"(p), "f"(a), "f"(b), "f"(c), "f"(d) : "memory");
}

__device__ __forceinline__ uint32_t smem_u32(const void* p) {
    uint32_t a;
    asm("{ .reg .u64 t; cvta.to.shared.u64 t, %1; cvt.u32.u64 %0, t; }" : "=r"(a) : "l"(p));
    return a;
}

// ---------------- cp.async helpers ----------------
__device__ __forceinline__ void cp_async16(uint32_t saddr, const void* gaddr) {
    asm volatile("cp.async.cg.shared.global [%0], [%1], 16;" :: "r"(saddr), "l"(gaddr));
}
#define CP_COMMIT() asm volatile("cp.async.commit_group;" ::: "memory")
#define CP_WAIT0()  asm volatile("cp.async.wait_group 0;" ::: "memory")

// ---------------- mma.sync / ldmatrix helpers ----------------
__device__ __forceinline__ void ldsm4(uint32_t* r, uint32_t addr) {
    asm volatile("ldmatrix.sync.aligned.m8n8.x4.shared.b16 {%0,%1,%2,%3}, [%4];"
                 : "=r"(r[0]), "=r"(r[1]), "=r"(r[2]), "=r"(r[3]) : "r"(addr));
}
__device__ __forceinline__ void mma16816(float* c, const uint32_t* a, uint32_t b0, uint32_t b1) {
    asm volatile("mma.sync.aligned.m16n8k16.row.col.f32.bf16.bf16.f32 "
                 "{%0,%1,%2,%3}, {%4,%5,%6,%7}, {%8,%9}, {%0,%1,%2,%3};"
                 : "+f"(c[0]), "+f"(c[1]), "+f"(c[2]), "+f"(c[3])
                 : "r"(a[0]), "r"(a[1]), "r"(a[2]), "r"(a[3]), "r"(b0), "r"(b1));
}

// swizzled byte offsets
__device__ __forceinline__ uint32_t off1(int r, int k) {
    return (uint32_t)(r * 128 + (((k >> 3) ^ (r & 7)) << 4) + (k & 7) * 2);
}
__device__ __forceinline__ uint32_t off2(int r, int k) {
    return (uint32_t)(r * 256 + (((k >> 3) ^ (r & 7)) << 4) + (k & 7) * 2);
}
// output-channel permutation for red.v4-friendly epilogue
__device__ __forceinline__ int perm_n(int n) {
    const int a = n >> 3, q = (n >> 1) & 3, h = n & 1;
    return ((a >> 1) << 4) + (q << 2) + ((a & 1) << 1) + h;
}

__device__ __forceinline__ uint32_t packbf2(float a, float b) {
    return (uint32_t)__bfloat16_as_ushort(__float2bfloat16(a)) |
           ((uint32_t)__bfloat16_as_ushort(__float2bfloat16(b)) << 16);
}

// ---------------- graph build: warp-per-node, shfl min-reduce ----------------
__global__ void build_graph_kernel(const float* __restrict__ pos,
                                   const int* __restrict__ batch)
{
    const int wid  = threadIdx.x >> 5;
    const int lane = threadIdx.x & 31;
    const int i    = blockIdx.x * 4 + wid;
    const int base = (i >> 7) << 7;

    const float px = pos[3*i], py = pos[3*i+1], pz = pos[3*i+2];

    ull key[4];
    #pragma unroll
    for (int c = 0; c < 4; c++) {
        const int j = base + c * 32 + lane;
        const float dx = pos[3*j]   - px;
        const float dy = pos[3*j+1] - py;
        const float dz = pos[3*j+2] - pz;
        const float d2 = dx*dx + dy*dy + dz*dz;
        key[c] = (j != i && d2 < CUTOFF*CUTOFF)
            ? ((((ull)__float_as_uint(d2)) << 32) | (unsigned int)j)
            : INVALID_KEY;
    }

    for (int k = 0; k < KNB; k++) {
        ull m0 = key[0] < key[1] ? key[0] : key[1];
        ull m1 = key[2] < key[3] ? key[2] : key[3];
        ull m  = m0 < m1 ? m0 : m1;
        #pragma unroll
        for (int s = 16; s >= 1; s >>= 1) {
            ull o = __shfl_xor_sync(0xffffffffu, m, s);
            if (o < m) m = o;
        }
        #pragma unroll
        for (int c = 0; c < 4; c++)
            if (key[c] == m) key[c] = INVALID_KEY;
        if (lane == k) {
            const int eo = i * KNB + k;
            if (m != INVALID_KEY) {
                const int   jj = (int)(m & 0xffffffffu);
                const float d  = sqrtf(__uint_as_float((unsigned int)(m >> 32)));
                g_idx[eo]  = jj;
                g_dist[eo] = d;
                const float cv = 0.5f * (cosf(d * (PI_C / CUTOFF)) + 1.0f);
                g_cval[eo] = (d < CUTOFF) ? cv : 0.0f;
            } else {
                g_idx[eo]  = i;
                g_dist[eo] = 1.0f;
                g_cval[eo] = 0.0f;
            }
        }
    }
}

// ---------------- fused prep: rbf(hi) + w1 + w2(perm) + l1img + l2img + embed ----
#define PREP_RBF   (EDGES * 64)
#define PREP_W1    (LAYERS * 128 * 64)
#define PREP_W2    (LAYERS * 128 * 128)
#define PREP_L1    (LAYERS * 128 * 128)
#define PREP_L2    (LAYERS * 128 * 128)
#define PREP_EMB   (NTOT * HID)
#define PREP_TOTAL (PREP_RBF + PREP_W1 + PREP_W2 + PREP_L1 + PREP_L2 + PREP_EMB)

__global__ void prep_all_kernel(const float* __restrict__ mw1,
                                const float* __restrict__ mw2,
                                const float* __restrict__ l1w,
                                const float* __restrict__ l2w,
                                const int* __restrict__ z,
                                const float* __restrict__ emb)
{
    const int id = blockIdx.x * blockDim.x + threadIdx.x;
    if (id < PREP_RBF) {
        const int e = id >> 6;
        const int k = id & 63;
        const int tile = e >> 7;
        const int r    = e & 127;
        float val = 0.0f;
        if (k < NG) {
            const float w = CUTOFF / (float)(NG - 1);
            const float t = (g_dist[e] - (float)k * w) / w;
            val = expf(-0.5f * t * t);
        }
        const uint32_t o = (uint32_t)tile * 16384u + off1(r, k);
        *(unsigned short*)(g_rbf_hi + o) = __bfloat16_as_ushort(__float2bfloat16(val));
    } else if (id < PREP_RBF + PREP_W1) {
        const int t = id - PREP_RBF;
        const int l = t >> 13;
        const int n = (t >> 6) & 127;
        const int k = t & 63;
        const float val = (k < NG) ? mw1[l * NG * FIL + k * FIL + n] : 0.0f;
        const uint32_t o = (uint32_t)l * 16384u + off1(n, k);
        *(unsigned short*)(g_w1_hi + o) = __bfloat16_as_ushort(__float2bfloat16(val));
    } else if (id < PREP_RBF + PREP_W1 + PREP_W2) {
        const int t = id - PREP_RBF - PREP_W1;
        const int l = t >> 14;
        const int n = (t >> 7) & 127;
        const int k = t & 127;
        const float val = mw2[l * FIL * FIL + k * FIL + perm_n(n)];
        const uint32_t o = (uint32_t)l * 32768u + off2(n, k);
        *(unsigned short*)(g_w2_hi + o) = __bfloat16_as_ushort(__float2bfloat16(val));
    } else if (id < PREP_RBF + PREP_W1 + PREP_W2 + PREP_L1) {
        const int t = id - PREP_RBF - PREP_W1 - PREP_W2;
        const int l = t >> 14;
        const int n = (t >> 7) & 127;
        const int k = t & 127;
        const float val = l1w[l * HID * FIL + k * FIL + n];
        const uint32_t o = (uint32_t)l * 32768u + off2(n, k);
        *(unsigned short*)(g_l1img + o) = __bfloat16_as_ushort(__float2bfloat16(val));
    } else if (id < PREP_RBF + PREP_W1 + PREP_W2 + PREP_L1 + PREP_L2) {
        const int t = id - PREP_RBF - PREP_W1 - PREP_W2 - PREP_L1;
        const int l = t >> 14;
        const int n = (t >> 7) & 127;
        const int k = t & 127;
        const float val = l2w[l * FIL * HID + k * HID + n];
        const uint32_t o = (uint32_t)l * 32768u + off2(n, k);
        *(unsigned short*)(g_l2img + o) = __bfloat16_as_ushort(__float2bfloat16(val));
    } else if (id < PREP_TOTAL) {
        const int t = id - PREP_RBF - PREP_W1 - PREP_W2 - PREP_L1 - PREP_L2;
        const int n = t >> 7;
        const int c = t & 127;
        g_h[t] = emb[z[n] * HID + c];
    }
}

// ---------------- node linear via mma.sync (512 thr, 64-row tile) ----------------
// mode 0: y = x@W + b, and zero g_agg rows.  mode 1: y += silu(x@W + b).
#define LIN_A_HI 0
#define LIN_A_LO 16384
#define LIN_W    32768
#define LIN_B    65536
#define LIN_SMEM_BYTES (65536 + 512)

__global__ void __launch_bounds__(512, 1)
linear_mma_kernel(const float* __restrict__ x,
                  const unsigned char* __restrict__ wimg,
                  const float* __restrict__ b,
                  float* __restrict__ y,
                  int mode)
{
    extern __shared__ unsigned char base[];
    const uint32_t base32 = smem_u32(base);

    const int tid  = threadIdx.x;
    const int lane = tid & 31;
    const int wid  = tid >> 5;
    const int m0w  = (wid & 3) * 16;     // 16 rows
    const int n0w  = (wid >> 2) * 32;    // 32 cols
    const int r0   = blockIdx.x * 64;

    // weights + bias to smem
    {
        const uint4* sw = (const uint4*)wimg;
        uint4* dw = (uint4*)(base + LIN_W);
        for (int i = tid; i < 2048; i += 512) dw[i] = sw[i];
        float* sb = (float*)(base + LIN_B);
        if (tid < 128) sb[tid] = b[tid];
    }

    // stage x rows -> bf16 hi/lo swizzled
    {
        const int r  = tid >> 3;
        const int k0 = (tid & 7) * 16;
        const float4* xp = (const float4*)(x + (r0 + r) * 128 + k0);
        float4 v0 = xp[0], v1 = xp[1], v2 = xp[2], v3 = xp[3];
        const float* vf = (const float*)&v0;   // v0..v3 contiguous in regs? use array
        float vv[16];
        *(float4*)&vv[0]  = v0; *(float4*)&vv[4]  = v1;
        *(float4*)&vv[8]  = v2; *(float4*)&vv[12] = v3;
        (void)vf;
        #pragma unroll
        for (int g = 0; g < 2; g++) {
            uint4 hi, lo;
            uint32_t* hp = (uint32_t*)&hi;
            uint32_t* lp = (uint32_t*)&lo;
            #pragma unroll
            for (int j = 0; j < 4; j++) {
                const float a = vv[g*8 + 2*j], c = vv[g*8 + 2*j + 1];
                const __nv_bfloat16 h0 = __float2bfloat16(a);
                const __nv_bfloat16 h1 = __float2bfloat16(c);
                hp[j] = (uint32_t)__bfloat16_as_ushort(h0) |
                        ((uint32_t)__bfloat16_as_ushort(h1) << 16);
                lp[j] = packbf2(a - __bfloat162float(h0), c - __bfloat162float(h1));
            }
            const uint32_t o = off2(r, k0 + g * 8);
            *(uint4*)(base + LIN_A_HI + o) = hi;
            *(uint4*)(base + LIN_A_LO + o) = lo;
        }
    }
    __syncthreads();

    const int lr = lane & 15;
    const int lk = (lane >> 4) * 8;

    float acc[4][4];
    #pragma unroll
    for (int nj = 0; nj < 4; nj++)
        #pragma unroll
        for (int q = 0; q < 4; q++) acc[nj][q] = 0.0f;

    #pragma unroll
    for (int ks = 0; ks < 8; ks++) {
        const int kb = ks * 16 + lk;
        uint32_t Ah[4], Al[4];
        {
            const uint32_t o = off2(m0w + lr, kb);
            ldsm4(Ah, base32 + LIN_A_HI + o);
            ldsm4(Al, base32 + LIN_A_LO + o);
        }
        #pragma unroll
        for (int nt = 0; nt < 2; nt++) {
            uint32_t Bh[4];
            const uint32_t o = off2(n0w + nt * 16 + lr, kb);
            ldsm4(Bh, base32 + LIN_W + o);
            #pragma unroll
            for (int h = 0; h < 2; h++) {
                const int nj = nt * 2 + h;
                mma16816(acc[nj], Ah, Bh[h], Bh[2 + h]);
                mma16816(acc[nj], Al, Bh[h], Bh[2 + h]);
            }
        }
    }

    // epilogue
    {
        float* sb = (float*)(base + LIN_B);
        const int rbase = m0w + (lane >> 2);
        const int cbase = n0w + (lane & 3) * 2;
        #pragma unroll
        for (int nj = 0; nj < 4; nj++) {
            const int col = cbase + nj * 8;
            const float bb0 = sb[col], bb1 = sb[col + 1];
            #pragma unroll
            for (int half = 0; half < 2; half++) {
                const int row = r0 + rbase + half * 8;
                const float v0 = acc[nj][half * 2]     + bb0;
                const float v1 = acc[nj][half * 2 + 1] + bb1;
                float2* yp = (float2*)(y + row * 128 + col);
                if (mode == 0) {
                    float2 v; v.x = v0; v.y = v1;
                    *yp = v;
                } else {
                    float2 v = *yp;
                    v.x += silu_f(v0);
                    v.y += silu_f(v1);
                    *yp = v;
                }
            }
        }
    }
    if (mode == 0) {
        const int r  = r0 + (tid >> 3);
        const int k0 = (tid & 7) * 16;
        float4 zz; zz.x = zz.y = zz.z = zz.w = 0.0f;
        float4* ap = (float4*)(g_agg + r * 128 + k0);
        ap[0] = zz; ap[1] = zz; ap[2] = zz; ap[3] = zz;
    }
}

// ---------------- tensor-core filter kernel, 1024 threads ----------------
// GEMM1: single-term bf16 (rbf hi x w1 hi). GEMM2: 2-term (A2 hi+lo x w2 hi).
#define SO_A1HI 0
#define SO_A2HI 16384
#define SO_A2LO 49152
#define SO_B1HI 81920
#define SO_B2HI 98304
#define SO_AUX  131072
// per-parity aux block (5120 B each): X1P 2048 | X1Q 2048 | CV 512 | DST 512
#define AUXB_X1P 0
#define AUXB_X1Q 2048
#define AUXB_CV  4096
#define AUXB_DST 4608
#define AUX_B1   10240            // shared bias (512 B)
#define FILT_SMEM_BYTES (SO_AUX + 10752)

__global__ void __launch_bounds__(1024, 1)
filter_mma_kernel(const float* __restrict__ b1g, const float* __restrict__ b2g,
                  const unsigned char* __restrict__ w1hi,
                  const unsigned char* __restrict__ w2hi)
{
    extern __shared__ unsigned char base[];
    const uint32_t base32 = smem_u32(base);

    const int tid  = threadIdx.x;
    const int lane = tid & 31;
    const int wid  = tid >> 5;
    const int wm   = wid & 7;          // warp m-tile: 16 edges (0..7)
    const int wn   = wid >> 3;         // warp n-tile: 32 channels (0..3)
    const int m0w  = wm * 16;
    const int n0w  = wn * 32;

    float* sb1 = (float*)(base + SO_AUX + AUX_B1);

    // resident weight copies
    {
        const uint4* s1h = (const uint4*)w1hi;
        const uint4* s2h = (const uint4*)w2hi;
        uint4* d1h = (uint4*)(base + SO_B1HI);
        uint4* d2h = (uint4*)(base + SO_B2HI);
        if (tid < 1024) d1h[tid] = s1h[tid];
        for (int i = tid; i < 2048; i += 1024) d2h[i] = s2h[i];
        if (tid < 128) sb1[tid] = b1g[tid];
    }

    // prefetch first tile's A1 (hi only)
    if (blockIdx.x < NTILES) {
        const size_t tb = (size_t)blockIdx.x * 16384;
        if (tid < 1024)
            cp_async16(base32 + SO_A1HI + tid * 16, g_rbf_hi + tb + tid * 16);
    }
    CP_COMMIT();

    const int lr = lane & 15;          // row within 16
    const int lk = (lane >> 4) * 8;    // k-block 0/8

    int par = 0;
    for (int tile = blockIdx.x; tile < NTILES; tile += gridDim.x, par ^= 1) {
        const int e0 = tile * 128;
        unsigned char* aux = base + SO_AUX + par * 5120;
        float* sx1p = (float*)(aux + AUXB_X1P);
        float* sx1q = (float*)(aux + AUXB_X1Q);
        float* scv  = (float*)(aux + AUXB_CV);
        int*   sdst = (int*)  (aux + AUXB_DST);

        // ---- aux stage (parity buffer) ----
        if (tid < 128) { scv[tid] = g_cval[e0 + tid]; sdst[tid] = g_idx[e0 + tid]; }
        if (tid < 512) {
            const int jj = tid >> 7, c = tid & 127;
            const float v = g_x1[(4 * tile + jj) * 128 + c];
            sx1p[tid] = v;
            sx1q[tid] = v * b2g[c];
        }
        CP_WAIT0();
        __syncthreads();

        float acc[4][4];
        #pragma unroll
        for (int nj = 0; nj < 4; nj++)
            #pragma unroll
            for (int q = 0; q < 4; q++) acc[nj][q] = 0.0f;

        // ---- GEMM1: K=64, single-term bf16 ----
        #pragma unroll
        for (int ks = 0; ks < 4; ks++) {
            const int kb = ks * 16 + lk;
            uint32_t Ah[4];
            ldsm4(Ah, base32 + SO_A1HI + off1(m0w + lr, kb));
            #pragma unroll
            for (int nt = 0; nt < 2; nt++) {
                uint32_t Bh[4];
                ldsm4(Bh, base32 + SO_B1HI + off1(n0w + nt * 16 + lr, kb));
                #pragma unroll
                for (int h = 0; h < 2; h++)
                    mma16816(acc[nt * 2 + h], Ah, Bh[h], Bh[2 + h]);
            }
        }

        // ---- epilogue1: silu, split, store A2 ----
        {
            unsigned char* a2h = base + SO_A2HI;
            unsigned char* a2l = base + SO_A2LO;
            const int rbase = m0w + (lane >> 2);
            const int cbase = n0w + (lane & 3) * 2;
            #pragma unroll
            for (int nj = 0; nj < 4; nj++) {
                const int col = cbase + nj * 8;
                const float bb0 = sb1[col], bb1 = sb1[col + 1];
                #pragma unroll
                for (int half = 0; half < 2; half++) {
                    const int row = rbase + half * 8;
                    const float s0 = silu_f(acc[nj][half * 2]     + bb0);
                    const float s1 = silu_f(acc[nj][half * 2 + 1] + bb1);
                    const __nv_bfloat16 h0 = __float2bfloat16(s0);
                    const __nv_bfloat16 h1 = __float2bfloat16(s1);
                    const uint32_t o = off2(row, col);
                    *(uint32_t*)(a2h + o) = (uint32_t)__bfloat16_as_ushort(h0) |
                                            ((uint32_t)__bfloat16_as_ushort(h1) << 16);
                    *(uint32_t*)(a2l + o) = packbf2(s0 - __bfloat162float(h0),
                                                    s1 - __bfloat162float(h1));
                }
            }
        }
        __syncthreads();

        // ---- prefetch next tile's A1 (A1 dead; overlaps GEMM2+epi2) ----
        {
            const int tnext = tile + gridDim.x;
            if (tnext < NTILES) {
                const size_t tb = (size_t)tnext * 16384;
                if (tid < 1024)
                    cp_async16(base32 + SO_A1HI + tid * 16, g_rbf_hi + tb + tid * 16);
            }
            CP_COMMIT();
        }

        #pragma unroll
        for (int nj = 0; nj < 4; nj++)
            #pragma unroll
            for (int q = 0; q < 4; q++) acc[nj][q] = 0.0f;

        // ---- GEMM2: K=128, 2-term ----
        #pragma unroll
        for (int ks = 0; ks < 8; ks++) {
            const int kb = ks * 16 + lk;
            uint32_t Ah[4], Al[4];
            {
                const uint32_t o = off2(m0w + lr, kb);
                ldsm4(Ah, base32 + SO_A2HI + o);
                ldsm4(Al, base32 + SO_A2LO + o);
            }
            #pragma unroll
            for (int nt = 0; nt < 2; nt++) {
                uint32_t Bh[4];
                ldsm4(Bh, base32 + SO_B2HI + off2(n0w + nt * 16 + lr, kb));
                #pragma unroll
                for (int h = 0; h < 2; h++) {
                    const int nj = nt * 2 + h;
                    mma16816(acc[nj], Ah, Bh[h], Bh[2 + h]);
                    mma16816(acc[nj], Al, Bh[h], Bh[2 + h]);
                }
            }
        }

        // ---- epilogue2: permuted channels -> red.v4 (no trailing sync) ----
        {
            const int q4 = (lane & 3) << 2;
            const int rbase = m0w + (lane >> 2);
            const int j4 = m0w >> 5;                  // warp-uniform source row group
            const float* pv = &sx1p[j4 * 128];
            const float* qv = &sx1q[j4 * 128];
            #pragma unroll
            for (int half = 0; half < 2; half++) {
                const int row = rbase + half * 8;
                const float cv = scv[row];
                const int   dst = sdst[row];
                float* aggp = &g_agg[dst * 128];
                #pragma unroll
                for (int pj = 0; pj < 2; pj++) {
                    const int pb = n0w + (pj << 4) + q4;      // 16B aligned physical base
                    const float4 pvv = *(const float4*)&pv[pb];
                    const float4 qvv = *(const float4*)&qv[pb];
                    const float m0 = cv * fmaf(acc[2*pj    ][half * 2],     pvv.x, qvv.x);
                    const float m1 = cv * fmaf(acc[2*pj    ][half * 2 + 1], pvv.y, qvv.y);
                    const float m2 = cv * fmaf(acc[2*pj + 1][half * 2],     pvv.z, qvv.z);
                    const float m3 = cv * fmaf(acc[2*pj + 1][half * 2 + 1], pvv.w, qvv.w);
                    red_add_v4(aggp + pb, m0, m1, m2, m3);
                }
            }
        }
        // no trailing __syncthreads: aux is parity double-buffered.
    }
}

// ---------------- output head + per-graph sum ----------------
#define OUT_SMEM_FLOATS (128*128 + 128*65)

__global__ void out_kernel(const float* __restrict__ ow1, const float* __restrict__ ob1,
                           const float* __restrict__ ow2, const float* __restrict__ ob2,
                           float* __restrict__ out)
{
    extern __shared__ float sm[];
    float* sh = sm;
    float* st = sh + 128*128;
    __shared__ float rsum[256];

    const int g    = blockIdx.x;
    const int tid  = threadIdx.x;
    const int base = g * ATOMS;

    for (int idx = tid; idx < 128 * 128; idx += 256)
        sh[idx] = g_h[base * 128 + idx];
    __syncthreads();

    const int d   = tid & 63;
    const int grp = tid >> 6;
    float acc[32];
    #pragma unroll
    for (int e = 0; e < 32; e++) acc[e] = 0.0f;
    const float* hh = sh + grp * 32 * 128;
    #pragma unroll 2
    for (int k = 0; k < 128; k++) {
        const float w = ow1[k * 64 + d];
        #pragma unroll
        for (int e = 0; e < 32; e++) acc[e] += hh[e * 128 + k] * w;
    }
    const float bb = ob1[d];
    #pragma unroll
    for (int e = 0; e < 32; e++) {
        const float v = acc[e] + bb;
        st[(grp * 32 + e) * 65 + d] = silu_f(v);
    }
    __syncthreads();

    float o = 0.0f;
    if (tid < 128) {
        float s = ob2[0];
        #pragma unroll 4
        for (int dd = 0; dd < 64; dd++) s += st[tid * 65 + dd] * ow2[dd];
        o = s;
    }
    rsum[tid] = o;
    __syncthreads();
    for (int s = 128; s >= 1; s >>= 1) {
        if (tid < s) rsum[tid] += rsum[tid + s];
        __syncthreads();
    }
    if (tid == 0) out[g] = rsum[0];
}

// ---------------- launch ----------------
extern "C" void kernel_launch(void* const* d_in, const int* in_sizes, int n_in,
                              void* d_out, int out_size)
{
    const float* pos   = (const float*)d_in[0];
    const int*   z     = (const int*)  d_in[1];
    const int*   batch = (const int*)  d_in[2];
    const float* emb   = (const float*)d_in[3];
    const float* mw1   = (const float*)d_in[4];
    const float* mb1   = (const float*)d_in[5];
    const float* mw2   = (const float*)d_in[6];
    const float* mb2   = (const float*)d_in[7];
    const float* l1w   = (const float*)d_in[8];
    const float* l1b   = (const float*)d_in[9];
    const float* l2w   = (const float*)d_in[10];
    const float* l2b   = (const float*)d_in[11];
    const float* ow1   = (const float*)d_in[12];
    const float* ob1   = (const float*)d_in[13];
    const float* ow2   = (const float*)d_in[14];
    const float* ob2   = (const float*)d_in[15];
    float* out = (float*)d_out;

    float *hp, *x1p, *aggp;
    cudaGetSymbolAddress((void**)&hp,   g_h);
    cudaGetSymbolAddress((void**)&x1p,  g_x1);
    cudaGetSymbolAddress((void**)&aggp, g_agg);
    unsigned char *w1h, *w2h, *l1i, *l2i;
    cudaGetSymbolAddress((void**)&w1h, g_w1_hi);
    cudaGetSymbolAddress((void**)&w2h, g_w2_hi);
    cudaGetSymbolAddress((void**)&l1i, g_l1img);
    cudaGetSymbolAddress((void**)&l2i, g_l2img);

    cudaFuncSetAttribute(filter_mma_kernel, cudaFuncAttributeMaxDynamicSharedMemorySize,
                         FILT_SMEM_BYTES);
    cudaFuncSetAttribute(linear_mma_kernel, cudaFuncAttributeMaxDynamicSharedMemorySize,
                         LIN_SMEM_BYTES);
    cudaFuncSetAttribute(out_kernel, cudaFuncAttributeMaxDynamicSharedMemorySize,
                         OUT_SMEM_FLOATS * (int)sizeof(float));

    build_graph_kernel<<<NTOT / 4, 128>>>(pos, batch);
    prep_all_kernel<<<(PREP_TOTAL + 255) / 256, 256>>>(mw1, mw2, l1w, l2w, z, emb);

    for (int l = 0; l < LAYERS; l++) {
        linear_mma_kernel<<<NTOT / 64, 512, LIN_SMEM_BYTES>>>(
            hp, l1i + l * 32768, l1b + l * FIL, x1p, 0);
        filter_mma_kernel<<<148, 1024, FILT_SMEM_BYTES>>>(
            mb1 + l * FIL, mb2 + l * FIL,
            w1h + l * 16384, w2h + l * 32768);
        linear_mma_kernel<<<NTOT / 64, 512, LIN_SMEM_BYTES>>>(
            aggp, l2i + l * 32768, l2b + l * HID, hp, 1);
    }

    out_kernel<<<NUM_G, 256, OUT_SMEM_FLOATS * sizeof(float)>>>(ow1, ob1, ow2, ob2, out);
}

// round 11
// speedup vs baseline: 2.5175x; 1.1251x over previous
#include <cuda_runtime.h>
#include <cuda_bf16.h>
#include <math.h>
#include <stdint.h>

// ---------------- problem constants ----------------
#define NG        50
#define KNB       32
#define NUM_G     64
#define ATOMS     128
#define NTOT      (NUM_G * ATOMS)     // 8192
#define HID       128
#define FIL       128
#define LAYERS    6
#define EDGES     (NTOT * KNB)        // 262144
#define NTILES    (EDGES / 128)       // 2048
#define CUTOFF    10.0f
#define PI_C      3.14159265f

#define INVALID_KEY 0xFFFFFFFFFFFFFFFFULL
typedef unsigned long long ull;

// ---------------- device scratch ----------------
__device__ int   g_idx [EDGES];
__device__ float g_dist[EDGES];
__device__ float g_cval[EDGES];
__device__ float g_h   [NTOT * HID];
__device__ float g_x1  [NTOT * FIL];
__device__ float g_agg [NTOT * FIL];

// ldmatrix-layout bf16 tile images
__device__ unsigned char g_rbf_hi[NTILES * 16384];   // per tile: [128 e][64 k]
__device__ unsigned char g_w1_hi [LAYERS * 16384];   // [128 n][64 k]
__device__ unsigned char g_w2_hi [LAYERS * 32768];   // [128 n][128 k], n-permuted
__device__ unsigned char g_l1img [LAYERS * 32768];   // [128 n][128 k]
__device__ unsigned char g_l2img [LAYERS * 32768];   // [128 n][128 k]

__device__ __forceinline__ float silu_f(float v) {
    return v / (1.0f + __expf(-v));
}

__device__ __forceinline__ void red_add_v4(float* p, float a, float b, float c, float d) {
    asm volatile("red.global.add.v4.f32 [%0], {%1,%2,%3,%4};"
                 :: "l"(p), "f"(a), "f"(b), "f"(c), "f"(d) : "memory");
}

__device__ __forceinline__ uint32_t smem_u32(const void* p) {
    uint32_t a;
    asm("{ .reg .u64 t; cvta.to.shared.u64 t, %1; cvt.u32.u64 %0, t; }" : "=r"(a) : "l"(p));
    return a;
}

// ---------------- cp.async helpers ----------------
__device__ __forceinline__ void cp_async16(uint32_t saddr, const void* gaddr) {
    asm volatile("cp.async.cg.shared.global [%0], [%1], 16;" :: "r"(saddr), "l"(gaddr));
}
#define CP_COMMIT() asm volatile("cp.async.commit_group;" ::: "memory")
#define CP_WAIT0()  asm volatile("cp.async.wait_group 0;" ::: "memory")

// ---------------- mma.sync / ldmatrix helpers ----------------
__device__ __forceinline__ void ldsm4(uint32_t* r, uint32_t addr) {
    asm volatile("ldmatrix.sync.aligned.m8n8.x4.shared.b16 {%0,%1,%2,%3}, [%4];"
                 : "=r"(r[0]), "=r"(r[1]), "=r"(r[2]), "=r"(r[3]) : "r"(addr));
}
__device__ __forceinline__ void mma16816(float* c, const uint32_t* a, uint32_t b0, uint32_t b1) {
    asm volatile("mma.sync.aligned.m16n8k16.row.col.f32.bf16.bf16.f32 "
                 "{%0,%1,%2,%3}, {%4,%5,%6,%7}, {%8,%9}, {%0,%1,%2,%3};"
                 : "+f"(c[0]), "+f"(c[1]), "+f"(c[2]), "+f"(c[3])
                 : "r"(a[0]), "r"(a[1]), "r"(a[2]), "r"(a[3]), "r"(b0), "r"(b1));
}

// swizzled byte offsets
__device__ __forceinline__ uint32_t off1(int r, int k) {
    return (uint32_t)(r * 128 + (((k >> 3) ^ (r & 7)) << 4) + (k & 7) * 2);
}
__device__ __forceinline__ uint32_t off2(int r, int k) {
    return (uint32_t)(r * 256 + (((k >> 3) ^ (r & 7)) << 4) + (k & 7) * 2);
}
// output-channel permutation for red.v4-friendly epilogue
__device__ __forceinline__ int perm_n(int n) {
    const int a = n >> 3, q = (n >> 1) & 3, h = n & 1;
    return ((a >> 1) << 4) + (q << 2) + ((a & 1) << 1) + h;
}

__device__ __forceinline__ uint32_t packbf2(float a, float b) {
    return (uint32_t)__bfloat16_as_ushort(__float2bfloat16(a)) |
           ((uint32_t)__bfloat16_as_ushort(__float2bfloat16(b)) << 16);
}

// ---------------- graph build: warp-per-node, shfl min-reduce ----------------
__global__ void build_graph_kernel(const float* __restrict__ pos,
                                   const int* __restrict__ batch)
{
    const int wid  = threadIdx.x >> 5;
    const int lane = threadIdx.x & 31;
    const int i    = blockIdx.x * 4 + wid;
    const int base = (i >> 7) << 7;

    const float px = pos[3*i], py = pos[3*i+1], pz = pos[3*i+2];

    ull key[4];
    #pragma unroll
    for (int c = 0; c < 4; c++) {
        const int j = base + c * 32 + lane;
        const float dx = pos[3*j]   - px;
        const float dy = pos[3*j+1] - py;
        const float dz = pos[3*j+2] - pz;
        const float d2 = dx*dx + dy*dy + dz*dz;
        key[c] = (j != i && d2 < CUTOFF*CUTOFF)
            ? ((((ull)__float_as_uint(d2)) << 32) | (unsigned int)j)
            : INVALID_KEY;
    }

    for (int k = 0; k < KNB; k++) {
        ull m0 = key[0] < key[1] ? key[0] : key[1];
        ull m1 = key[2] < key[3] ? key[2] : key[3];
        ull m  = m0 < m1 ? m0 : m1;
        #pragma unroll
        for (int s = 16; s >= 1; s >>= 1) {
            ull o = __shfl_xor_sync(0xffffffffu, m, s);
            if (o < m) m = o;
        }
        #pragma unroll
        for (int c = 0; c < 4; c++)
            if (key[c] == m) key[c] = INVALID_KEY;
        if (lane == k) {
            const int eo = i * KNB + k;
            if (m != INVALID_KEY) {
                const int   jj = (int)(m & 0xffffffffu);
                const float d  = sqrtf(__uint_as_float((unsigned int)(m >> 32)));
                g_idx[eo]  = jj;
                g_dist[eo] = d;
                const float cv = 0.5f * (cosf(d * (PI_C / CUTOFF)) + 1.0f);
                g_cval[eo] = (d < CUTOFF) ? cv : 0.0f;
            } else {
                g_idx[eo]  = i;
                g_dist[eo] = 1.0f;
                g_cval[eo] = 0.0f;
            }
        }
    }
}

// ---------------- fused prep: rbf(hi) + w1 + w2(perm) + l1img + l2img + embed ----
#define PREP_RBF   (EDGES * 64)
#define PREP_W1    (LAYERS * 128 * 64)
#define PREP_W2    (LAYERS * 128 * 128)
#define PREP_L1    (LAYERS * 128 * 128)
#define PREP_L2    (LAYERS * 128 * 128)
#define PREP_EMB   (NTOT * HID)
#define PREP_TOTAL (PREP_RBF + PREP_W1 + PREP_W2 + PREP_L1 + PREP_L2 + PREP_EMB)

__global__ void prep_all_kernel(const float* __restrict__ mw1,
                                const float* __restrict__ mw2,
                                const float* __restrict__ l1w,
                                const float* __restrict__ l2w,
                                const int* __restrict__ z,
                                const float* __restrict__ emb)
{
    const int id = blockIdx.x * blockDim.x + threadIdx.x;
    if (id < PREP_RBF) {
        const int e = id >> 6;
        const int k = id & 63;
        const int tile = e >> 7;
        const int r    = e & 127;
        float val = 0.0f;
        if (k < NG) {
            const float w = CUTOFF / (float)(NG - 1);
            const float t = (g_dist[e] - (float)k * w) / w;
            val = expf(-0.5f * t * t);
        }
        const uint32_t o = (uint32_t)tile * 16384u + off1(r, k);
        *(unsigned short*)(g_rbf_hi + o) = __bfloat16_as_ushort(__float2bfloat16(val));
    } else if (id < PREP_RBF + PREP_W1) {
        const int t = id - PREP_RBF;
        const int l = t >> 13;
        const int n = (t >> 6) & 127;
        const int k = t & 63;
        const float val = (k < NG) ? mw1[l * NG * FIL + k * FIL + n] : 0.0f;
        const uint32_t o = (uint32_t)l * 16384u + off1(n, k);
        *(unsigned short*)(g_w1_hi + o) = __bfloat16_as_ushort(__float2bfloat16(val));
    } else if (id < PREP_RBF + PREP_W1 + PREP_W2) {
        const int t = id - PREP_RBF - PREP_W1;
        const int l = t >> 14;
        const int n = (t >> 7) & 127;
        const int k = t & 127;
        const float val = mw2[l * FIL * FIL + k * FIL + perm_n(n)];
        const uint32_t o = (uint32_t)l * 32768u + off2(n, k);
        *(unsigned short*)(g_w2_hi + o) = __bfloat16_as_ushort(__float2bfloat16(val));
    } else if (id < PREP_RBF + PREP_W1 + PREP_W2 + PREP_L1) {
        const int t = id - PREP_RBF - PREP_W1 - PREP_W2;
        const int l = t >> 14;
        const int n = (t >> 7) & 127;
        const int k = t & 127;
        const float val = l1w[l * HID * FIL + k * FIL + n];
        const uint32_t o = (uint32_t)l * 32768u + off2(n, k);
        *(unsigned short*)(g_l1img + o) = __bfloat16_as_ushort(__float2bfloat16(val));
    } else if (id < PREP_RBF + PREP_W1 + PREP_W2 + PREP_L1 + PREP_L2) {
        const int t = id - PREP_RBF - PREP_W1 - PREP_W2 - PREP_L1;
        const int l = t >> 14;
        const int n = (t >> 7) & 127;
        const int k = t & 127;
        const float val = l2w[l * FIL * HID + k * HID + n];
        const uint32_t o = (uint32_t)l * 32768u + off2(n, k);
        *(unsigned short*)(g_l2img + o) = __bfloat16_as_ushort(__float2bfloat16(val));
    } else if (id < PREP_TOTAL) {
        const int t = id - PREP_RBF - PREP_W1 - PREP_W2 - PREP_L1 - PREP_L2;
        const int n = t >> 7;
        const int c = t & 127;
        g_h[t] = emb[z[n] * HID + c];
    }
}

// ---------------- node linear via mma.sync (512 thr, 64-row tile) ----------------
// mode 0: y = x@W + b, and zero g_agg rows.  mode 1: y += silu(x@W + b).
#define LIN_A_HI 0
#define LIN_A_LO 16384
#define LIN_W    32768
#define LIN_B    65536
#define LIN_SMEM_BYTES (65536 + 512)

__global__ void __launch_bounds__(512, 1)
linear_mma_kernel(const float* __restrict__ x,
                  const unsigned char* __restrict__ wimg,
                  const float* __restrict__ b,
                  float* __restrict__ y,
                  int mode)
{
    extern __shared__ unsigned char base[];
    const uint32_t base32 = smem_u32(base);

    const int tid  = threadIdx.x;
    const int lane = tid & 31;
    const int wid  = tid >> 5;
    const int m0w  = (wid & 3) * 16;     // 16 rows
    const int n0w  = (wid >> 2) * 32;    // 32 cols
    const int r0   = blockIdx.x * 64;

    // weights + bias to smem
    {
        const uint4* sw = (const uint4*)wimg;
        uint4* dw = (uint4*)(base + LIN_W);
        for (int i = tid; i < 2048; i += 512) dw[i] = sw[i];
        float* sb = (float*)(base + LIN_B);
        if (tid < 128) sb[tid] = b[tid];
    }

    // stage x rows -> bf16 hi/lo swizzled
    {
        const int r  = tid >> 3;
        const int k0 = (tid & 7) * 16;
        const float4* xp = (const float4*)(x + (r0 + r) * 128 + k0);
        float4 v0 = xp[0], v1 = xp[1], v2 = xp[2], v3 = xp[3];
        float vv[16];
        *(float4*)&vv[0]  = v0; *(float4*)&vv[4]  = v1;
        *(float4*)&vv[8]  = v2; *(float4*)&vv[12] = v3;
        #pragma unroll
        for (int g = 0; g < 2; g++) {
            uint4 hi, lo;
            uint32_t* hp = (uint32_t*)&hi;
            uint32_t* lp = (uint32_t*)&lo;
            #pragma unroll
            for (int j = 0; j < 4; j++) {
                const float a = vv[g*8 + 2*j], c = vv[g*8 + 2*j + 1];
                const __nv_bfloat16 h0 = __float2bfloat16(a);
                const __nv_bfloat16 h1 = __float2bfloat16(c);
                hp[j] = (uint32_t)__bfloat16_as_ushort(h0) |
                        ((uint32_t)__bfloat16_as_ushort(h1) << 16);
                lp[j] = packbf2(a - __bfloat162float(h0), c - __bfloat162float(h1));
            }
            const uint32_t o = off2(r, k0 + g * 8);
            *(uint4*)(base + LIN_A_HI + o) = hi;
            *(uint4*)(base + LIN_A_LO + o) = lo;
        }
    }
    __syncthreads();

    const int lr = lane & 15;
    const int lk = (lane >> 4) * 8;

    float acc[4][4];
    #pragma unroll
    for (int nj = 0; nj < 4; nj++)
        #pragma unroll
        for (int q = 0; q < 4; q++) acc[nj][q] = 0.0f;

    #pragma unroll
    for (int ks = 0; ks < 8; ks++) {
        const int kb = ks * 16 + lk;
        uint32_t Ah[4], Al[4];
        {
            const uint32_t o = off2(m0w + lr, kb);
            ldsm4(Ah, base32 + LIN_A_HI + o);
            ldsm4(Al, base32 + LIN_A_LO + o);
        }
        #pragma unroll
        for (int nt = 0; nt < 2; nt++) {
            uint32_t Bh[4];
            const uint32_t o = off2(n0w + nt * 16 + lr, kb);
            ldsm4(Bh, base32 + LIN_W + o);
            #pragma unroll
            for (int h = 0; h < 2; h++) {
                const int nj = nt * 2 + h;
                mma16816(acc[nj], Ah, Bh[h], Bh[2 + h]);
                mma16816(acc[nj], Al, Bh[h], Bh[2 + h]);
            }
        }
    }

    // epilogue
    {
        float* sb = (float*)(base + LIN_B);
        const int rbase = m0w + (lane >> 2);
        const int cbase = n0w + (lane & 3) * 2;
        #pragma unroll
        for (int nj = 0; nj < 4; nj++) {
            const int col = cbase + nj * 8;
            const float bb0 = sb[col], bb1 = sb[col + 1];
            #pragma unroll
            for (int half = 0; half < 2; half++) {
                const int row = r0 + rbase + half * 8;
                const float v0 = acc[nj][half * 2]     + bb0;
                const float v1 = acc[nj][half * 2 + 1] + bb1;
                float2* yp = (float2*)(y + row * 128 + col);
                if (mode == 0) {
                    float2 v; v.x = v0; v.y = v1;
                    *yp = v;
                } else {
                    float2 v = *yp;
                    v.x += silu_f(v0);
                    v.y += silu_f(v1);
                    *yp = v;
                }
            }
        }
    }
    if (mode == 0) {
        const int r  = r0 + (tid >> 3);
        const int k0 = (tid & 7) * 16;
        float4 zz; zz.x = zz.y = zz.z = zz.w = 0.0f;
        float4* ap = (float4*)(g_agg + r * 128 + k0);
        ap[0] = zz; ap[1] = zz; ap[2] = zz; ap[3] = zz;
    }
}

// ---------------- tensor-core filter kernel, 1024 threads ----------------
// GEMM1: single-term bf16 (rbf x w1). GEMM2: single-term bf16 (hidden x w2).
#define SO_A1HI 0
#define SO_A2HI 16384
#define SO_B1HI 49152
#define SO_B2HI 65536
#define SO_AUX  98304
// per-parity aux block (5120 B each): X1P 2048 | X1Q 2048 | CV 512 | DST 512
#define AUXB_X1P 0
#define AUXB_X1Q 2048
#define AUXB_CV  4096
#define AUXB_DST 4608
#define AUX_B1   10240            // shared bias (512 B)
#define FILT_SMEM_BYTES (SO_AUX + 10752)

__global__ void __launch_bounds__(1024, 1)
filter_mma_kernel(const float* __restrict__ b1g, const float* __restrict__ b2g,
                  const unsigned char* __restrict__ w1hi,
                  const unsigned char* __restrict__ w2hi)
{
    extern __shared__ unsigned char base[];
    const uint32_t base32 = smem_u32(base);

    const int tid  = threadIdx.x;
    const int lane = tid & 31;
    const int wid  = tid >> 5;
    const int wm   = wid & 7;          // warp m-tile: 16 edges (0..7)
    const int wn   = wid >> 3;         // warp n-tile: 32 channels (0..3)
    const int m0w  = wm * 16;
    const int n0w  = wn * 32;

    float* sb1 = (float*)(base + SO_AUX + AUX_B1);

    // resident weight copies
    {
        const uint4* s1h = (const uint4*)w1hi;
        const uint4* s2h = (const uint4*)w2hi;
        uint4* d1h = (uint4*)(base + SO_B1HI);
        uint4* d2h = (uint4*)(base + SO_B2HI);
        if (tid < 1024) d1h[tid] = s1h[tid];
        for (int i = tid; i < 2048; i += 1024) d2h[i] = s2h[i];
        if (tid < 128) sb1[tid] = b1g[tid];
    }

    // prefetch first tile's A1
    if (blockIdx.x < NTILES) {
        const size_t tb = (size_t)blockIdx.x * 16384;
        if (tid < 1024)
            cp_async16(base32 + SO_A1HI + tid * 16, g_rbf_hi + tb + tid * 16);
    }
    CP_COMMIT();

    const int lr = lane & 15;          // row within 16
    const int lk = (lane >> 4) * 8;    // k-block 0/8

    int par = 0;
    for (int tile = blockIdx.x; tile < NTILES; tile += gridDim.x, par ^= 1) {
        const int e0 = tile * 128;
        unsigned char* aux = base + SO_AUX + par * 5120;
        float* sx1p = (float*)(aux + AUXB_X1P);
        float* sx1q = (float*)(aux + AUXB_X1Q);
        float* scv  = (float*)(aux + AUXB_CV);
        int*   sdst = (int*)  (aux + AUXB_DST);

        // ---- aux stage (parity buffer) ----
        if (tid < 128) { scv[tid] = g_cval[e0 + tid]; sdst[tid] = g_idx[e0 + tid]; }
        if (tid < 512) {
            const int jj = tid >> 7, c = tid & 127;
            const float v = g_x1[(4 * tile + jj) * 128 + c];
            sx1p[tid] = v;
            sx1q[tid] = v * b2g[c];
        }
        CP_WAIT0();
        __syncthreads();

        float acc[4][4];
        #pragma unroll
        for (int nj = 0; nj < 4; nj++)
            #pragma unroll
            for (int q = 0; q < 4; q++) acc[nj][q] = 0.0f;

        // ---- GEMM1: K=64, single-term bf16 ----
        #pragma unroll
        for (int ks = 0; ks < 4; ks++) {
            const int kb = ks * 16 + lk;
            uint32_t Ah[4];
            ldsm4(Ah, base32 + SO_A1HI + off1(m0w + lr, kb));
            #pragma unroll
            for (int nt = 0; nt < 2; nt++) {
                uint32_t Bh[4];
                ldsm4(Bh, base32 + SO_B1HI + off1(n0w + nt * 16 + lr, kb));
                #pragma unroll
                for (int h = 0; h < 2; h++)
                    mma16816(acc[nt * 2 + h], Ah, Bh[h], Bh[2 + h]);
            }
        }

        // ---- epilogue1: silu -> bf16 -> A2 ----
        {
            unsigned char* a2h = base + SO_A2HI;
            const int rbase = m0w + (lane >> 2);
            const int cbase = n0w + (lane & 3) * 2;
            #pragma unroll
            for (int nj = 0; nj < 4; nj++) {
                const int col = cbase + nj * 8;
                const float bb0 = sb1[col], bb1 = sb1[col + 1];
                #pragma unroll
                for (int half = 0; half < 2; half++) {
                    const int row = rbase + half * 8;
                    const float s0 = silu_f(acc[nj][half * 2]     + bb0);
                    const float s1 = silu_f(acc[nj][half * 2 + 1] + bb1);
                    *(uint32_t*)(a2h + off2(row, col)) = packbf2(s0, s1);
                }
            }
        }
        __syncthreads();

        // ---- prefetch next tile's A1 (A1 dead; overlaps GEMM2+epi2) ----
        {
            const int tnext = tile + gridDim.x;
            if (tnext < NTILES) {
                const size_t tb = (size_t)tnext * 16384;
                if (tid < 1024)
                    cp_async16(base32 + SO_A1HI + tid * 16, g_rbf_hi + tb + tid * 16);
            }
            CP_COMMIT();
        }

        #pragma unroll
        for (int nj = 0; nj < 4; nj++)
            #pragma unroll
            for (int q = 0; q < 4; q++) acc[nj][q] = 0.0f;

        // ---- GEMM2: K=128, single-term bf16 ----
        #pragma unroll
        for (int ks = 0; ks < 8; ks++) {
            const int kb = ks * 16 + lk;
            uint32_t Ah[4];
            ldsm4(Ah, base32 + SO_A2HI + off2(m0w + lr, kb));
            #pragma unroll
            for (int nt = 0; nt < 2; nt++) {
                uint32_t Bh[4];
                ldsm4(Bh, base32 + SO_B2HI + off2(n0w + nt * 16 + lr, kb));
                #pragma unroll
                for (int h = 0; h < 2; h++)
                    mma16816(acc[nt * 2 + h], Ah, Bh[h], Bh[2 + h]);
            }
        }

        // ---- epilogue2: permuted channels -> red.v4 (no trailing sync) ----
        {
            const int q4 = (lane & 3) << 2;
            const int rbase = m0w + (lane >> 2);
            const int j4 = m0w >> 5;                  // warp-uniform source row group
            const float* pv = &sx1p[j4 * 128];
            const float* qv = &sx1q[j4 * 128];
            #pragma unroll
            for (int half = 0; half < 2; half++) {
                const int row = rbase + half * 8;
                const float cv = scv[row];
                const int   dst = sdst[row];
                float* aggp = &g_agg[dst * 128];
                #pragma unroll
                for (int pj = 0; pj < 2; pj++) {
                    const int pb = n0w + (pj << 4) + q4;      // 16B aligned physical base
                    const float4 pvv = *(const float4*)&pv[pb];
                    const float4 qvv = *(const float4*)&qv[pb];
                    const float m0 = cv * fmaf(acc[2*pj    ][half * 2],     pvv.x, qvv.x);
                    const float m1 = cv * fmaf(acc[2*pj    ][half * 2 + 1], pvv.y, qvv.y);
                    const float m2 = cv * fmaf(acc[2*pj + 1][half * 2],     pvv.z, qvv.z);
                    const float m3 = cv * fmaf(acc[2*pj + 1][half * 2 + 1], pvv.w, qvv.w);
                    red_add_v4(aggp + pb, m0, m1, m2, m3);
                }
            }
        }
        // no trailing __syncthreads: aux is parity double-buffered.
    }
}

// ---------------- output head + per-graph sum ----------------
#define OUT_SMEM_FLOATS (128*128 + 128*65)

__global__ void out_kernel(const float* __restrict__ ow1, const float* __restrict__ ob1,
                           const float* __restrict__ ow2, const float* __restrict__ ob2,
                           float* __restrict__ out)
{
    extern __shared__ float sm[];
    float* sh = sm;
    float* st = sh + 128*128;
    __shared__ float rsum[256];

    const int g    = blockIdx.x;
    const int tid  = threadIdx.x;
    const int base = g * ATOMS;

    for (int idx = tid; idx < 128 * 128; idx += 256)
        sh[idx] = g_h[base * 128 + idx];
    __syncthreads();

    const int d   = tid & 63;
    const int grp = tid >> 6;
    float acc[32];
    #pragma unroll
    for (int e = 0; e < 32; e++) acc[e] = 0.0f;
    const float* hh = sh + grp * 32 * 128;
    #pragma unroll 2
    for (int k = 0; k < 128; k++) {
        const float w = ow1[k * 64 + d];
        #pragma unroll
        for (int e = 0; e < 32; e++) acc[e] += hh[e * 128 + k] * w;
    }
    const float bb = ob1[d];
    #pragma unroll
    for (int e = 0; e < 32; e++) {
        const float v = acc[e] + bb;
        st[(grp * 32 + e) * 65 + d] = silu_f(v);
    }
    __syncthreads();

    float o = 0.0f;
    if (tid < 128) {
        float s = ob2[0];
        #pragma unroll 4
        for (int dd = 0; dd < 64; dd++) s += st[tid * 65 + dd] * ow2[dd];
        o = s;
    }
    rsum[tid] = o;
    __syncthreads();
    for (int s = 128; s >= 1; s >>= 1) {
        if (tid < s) rsum[tid] += rsum[tid + s];
        __syncthreads();
    }
    if (tid == 0) out[g] = rsum[0];
}

// ---------------- launch ----------------
extern "C" void kernel_launch(void* const* d_in, const int* in_sizes, int n_in,
                              void* d_out, int out_size)
{
    const float* pos   = (const float*)d_in[0];
    const int*   z     = (const int*)  d_in[1];
    const int*   batch = (const int*)  d_in[2];
    const float* emb   = (const float*)d_in[3];
    const float* mw1   = (const float*)d_in[4];
    const float* mb1   = (const float*)d_in[5];
    const float* mw2   = (const float*)d_in[6];
    const float* mb2   = (const float*)d_in[7];
    const float* l1w   = (const float*)d_in[8];
    const float* l1b   = (const float*)d_in[9];
    const float* l2w   = (const float*)d_in[10];
    const float* l2b   = (const float*)d_in[11];
    const float* ow1   = (const float*)d_in[12];
    const float* ob1   = (const float*)d_in[13];
    const float* ow2   = (const float*)d_in[14];
    const float* ob2   = (const float*)d_in[15];
    float* out = (float*)d_out;

    float *hp, *x1p, *aggp;
    cudaGetSymbolAddress((void**)&hp,   g_h);
    cudaGetSymbolAddress((void**)&x1p,  g_x1);
    cudaGetSymbolAddress((void**)&aggp, g_agg);
    unsigned char *w1h, *w2h, *l1i, *l2i;
    cudaGetSymbolAddress((void**)&w1h, g_w1_hi);
    cudaGetSymbolAddress((void**)&w2h, g_w2_hi);
    cudaGetSymbolAddress((void**)&l1i, g_l1img);
    cudaGetSymbolAddress((void**)&l2i, g_l2img);

    cudaFuncSetAttribute(filter_mma_kernel, cudaFuncAttributeMaxDynamicSharedMemorySize,
                         FILT_SMEM_BYTES);
    cudaFuncSetAttribute(linear_mma_kernel, cudaFuncAttributeMaxDynamicSharedMemorySize,
                         LIN_SMEM_BYTES);
    cudaFuncSetAttribute(out_kernel, cudaFuncAttributeMaxDynamicSharedMemorySize,
                         OUT_SMEM_FLOATS * (int)sizeof(float));

    build_graph_kernel<<<NTOT / 4, 128>>>(pos, batch);
    prep_all_kernel<<<(PREP_TOTAL + 255) / 256, 256>>>(mw1, mw2, l1w, l2w, z, emb);

    for (int l = 0; l < LAYERS; l++) {
        linear_mma_kernel<<<NTOT / 64, 512, LIN_SMEM_BYTES>>>(
            hp, l1i + l * 32768, l1b + l * FIL, x1p, 0);
        filter_mma_kernel<<<148, 1024, FILT_SMEM_BYTES>>>(
            mb1 + l * FIL, mb2 + l * FIL,
            w1h + l * 16384, w2h + l * 32768);
        linear_mma_kernel<<<NTOT / 64, 512, LIN_SMEM_BYTES>>>(
            aggp, l2i + l * 32768, l2b + l * HID, hp, 1);
    }

    out_kernel<<<NUM_G, 256, OUT_SMEM_FLOATS * sizeof(float)>>>(ow1, ob1, ow2, ob2, out);
}

// round 12
// speedup vs baseline: 2.5770x; 1.0237x over previous
#include <cuda_runtime.h>
#include <cuda_bf16.h>
#include <math.h>
#include <stdint.h>

// ---------------- problem constants ----------------
#define NG        50
#define KNB       32
#define NUM_G     64
#define ATOMS     128
#define NTOT      (NUM_G * ATOMS)     // 8192
#define HID       128
#define FIL       128
#define LAYERS    6
#define EDGES     (NTOT * KNB)        // 262144
#define NTILES    (EDGES / 128)       // 2048
#define CUTOFF    10.0f
#define PI_C      3.14159265f

#define INVALID_KEY 0xFFFFFFFFFFFFFFFFULL
typedef unsigned long long ull;

// ---------------- device scratch ----------------
__device__ int   g_idx [EDGES];
__device__ float g_dist[EDGES];
__device__ float g_cval[EDGES];
__device__ float g_h   [NTOT * HID];
__device__ float g_x1  [NTOT * FIL];
__device__ float g_agg [NTOT * FIL];

// ldmatrix-layout bf16 tile images
__device__ unsigned char g_rbf_hi[NTILES * 16384];   // per tile: [128 e][64 k]
__device__ unsigned char g_w1_hi [LAYERS * 16384];   // [128 n][64 k]
__device__ unsigned char g_w2_hi [LAYERS * 32768];   // [128 n][128 k], n-permuted
__device__ unsigned char g_l1img [LAYERS * 32768];   // [128 n][128 k]
__device__ unsigned char g_l2img [LAYERS * 32768];   // [128 n][128 k]

__device__ __forceinline__ float silu_f(float v) {
    return v / (1.0f + __expf(-v));
}

__device__ __forceinline__ void red_add_v4(float* p, float a, float b, float c, float d) {
    asm volatile("red.global.add.v4.f32 [%0], {%1,%2,%3,%4};"
                 :: "l"(p), "f"(a), "f"(b), "f"(c), "f"(d) : "memory");
}

__device__ __forceinline__ uint32_t smem_u32(const void* p) {
    uint32_t a;
    asm("{ .reg .u64 t; cvta.to.shared.u64 t, %1; cvt.u32.u64 %0, t; }" : "=r"(a) : "l"(p));
    return a;
}

// ---------------- cp.async helpers ----------------
__device__ __forceinline__ void cp_async16(uint32_t saddr, const void* gaddr) {
    asm volatile("cp.async.cg.shared.global [%0], [%1], 16;" :: "r"(saddr), "l"(gaddr));
}
#define CP_COMMIT() asm volatile("cp.async.commit_group;" ::: "memory")
#define CP_WAIT0()  asm volatile("cp.async.wait_group 0;" ::: "memory")

// ---------------- mma.sync / ldmatrix helpers ----------------
__device__ __forceinline__ void ldsm4(uint32_t* r, uint32_t addr) {
    asm volatile("ldmatrix.sync.aligned.m8n8.x4.shared.b16 {%0,%1,%2,%3}, [%4];"
                 : "=r"(r[0]), "=r"(r[1]), "=r"(r[2]), "=r"(r[3]) : "r"(addr));
}
__device__ __forceinline__ void mma16816(float* c, const uint32_t* a, uint32_t b0, uint32_t b1) {
    asm volatile("mma.sync.aligned.m16n8k16.row.col.f32.bf16.bf16.f32 "
                 "{%0,%1,%2,%3}, {%4,%5,%6,%7}, {%8,%9}, {%0,%1,%2,%3};"
                 : "+f"(c[0]), "+f"(c[1]), "+f"(c[2]), "+f"(c[3])
                 : "r"(a[0]), "r"(a[1]), "r"(a[2]), "r"(a[3]), "r"(b0), "r"(b1));
}

// swizzled byte offsets
__device__ __forceinline__ uint32_t off1(int r, int k) {
    return (uint32_t)(r * 128 + (((k >> 3) ^ (r & 7)) << 4) + (k & 7) * 2);
}
__device__ __forceinline__ uint32_t off2(int r, int k) {
    return (uint32_t)(r * 256 + (((k >> 3) ^ (r & 7)) << 4) + (k & 7) * 2);
}
// output-channel permutation for red.v4-friendly epilogue
__device__ __forceinline__ int perm_n(int n) {
    const int a = n >> 3, q = (n >> 1) & 3, h = n & 1;
    return ((a >> 1) << 4) + (q << 2) + ((a & 1) << 1) + h;
}

__device__ __forceinline__ uint32_t packbf2(float a, float b) {
    return (uint32_t)__bfloat16_as_ushort(__float2bfloat16(a)) |
           ((uint32_t)__bfloat16_as_ushort(__float2bfloat16(b)) << 16);
}

// ---------------- graph build: warp-per-node, shfl min-reduce ----------------
__global__ void build_graph_kernel(const float* __restrict__ pos,
                                   const int* __restrict__ batch)
{
    const int wid  = threadIdx.x >> 5;
    const int lane = threadIdx.x & 31;
    const int i    = blockIdx.x * 4 + wid;
    const int base = (i >> 7) << 7;

    const float px = pos[3*i], py = pos[3*i+1], pz = pos[3*i+2];

    ull key[4];
    #pragma unroll
    for (int c = 0; c < 4; c++) {
        const int j = base + c * 32 + lane;
        const float dx = pos[3*j]   - px;
        const float dy = pos[3*j+1] - py;
        const float dz = pos[3*j+2] - pz;
        const float d2 = dx*dx + dy*dy + dz*dz;
        key[c] = (j != i && d2 < CUTOFF*CUTOFF)
            ? ((((ull)__float_as_uint(d2)) << 32) | (unsigned int)j)
            : INVALID_KEY;
    }

    for (int k = 0; k < KNB; k++) {
        ull m0 = key[0] < key[1] ? key[0] : key[1];
        ull m1 = key[2] < key[3] ? key[2] : key[3];
        ull m  = m0 < m1 ? m0 : m1;
        #pragma unroll
        for (int s = 16; s >= 1; s >>= 1) {
            ull o = __shfl_xor_sync(0xffffffffu, m, s);
            if (o < m) m = o;
        }
        #pragma unroll
        for (int c = 0; c < 4; c++)
            if (key[c] == m) key[c] = INVALID_KEY;
        if (lane == k) {
            const int eo = i * KNB + k;
            if (m != INVALID_KEY) {
                const int   jj = (int)(m & 0xffffffffu);
                const float d  = sqrtf(__uint_as_float((unsigned int)(m >> 32)));
                g_idx[eo]  = jj;
                g_dist[eo] = d;
                const float cv = 0.5f * (cosf(d * (PI_C / CUTOFF)) + 1.0f);
                g_cval[eo] = (d < CUTOFF) ? cv : 0.0f;
            } else {
                g_idx[eo]  = i;
                g_dist[eo] = 1.0f;
                g_cval[eo] = 0.0f;
            }
        }
    }
}

// ---------------- fused prep: rbf(hi) + w1 + w2(perm) + l1img + l2img + embed ----
#define PREP_RBF   (EDGES * 64)
#define PREP_W1    (LAYERS * 128 * 64)
#define PREP_W2    (LAYERS * 128 * 128)
#define PREP_L1    (LAYERS * 128 * 128)
#define PREP_L2    (LAYERS * 128 * 128)
#define PREP_EMB   (NTOT * HID)
#define PREP_TOTAL (PREP_RBF + PREP_W1 + PREP_W2 + PREP_L1 + PREP_L2 + PREP_EMB)

__global__ void prep_all_kernel(const float* __restrict__ mw1,
                                const float* __restrict__ mw2,
                                const float* __restrict__ l1w,
                                const float* __restrict__ l2w,
                                const int* __restrict__ z,
                                const float* __restrict__ emb)
{
    const int id = blockIdx.x * blockDim.x + threadIdx.x;
    if (id < PREP_RBF) {
        const int e = id >> 6;
        const int k = id & 63;
        const int tile = e >> 7;
        const int r    = e & 127;
        float val = 0.0f;
        if (k < NG) {
            const float w = CUTOFF / (float)(NG - 1);
            const float t = (g_dist[e] - (float)k * w) / w;
            val = expf(-0.5f * t * t);
        }
        const uint32_t o = (uint32_t)tile * 16384u + off1(r, k);
        *(unsigned short*)(g_rbf_hi + o) = __bfloat16_as_ushort(__float2bfloat16(val));
    } else if (id < PREP_RBF + PREP_W1) {
        const int t = id - PREP_RBF;
        const int l = t >> 13;
        const int n = (t >> 6) & 127;
        const int k = t & 63;
        const float val = (k < NG) ? mw1[l * NG * FIL + k * FIL + n] : 0.0f;
        const uint32_t o = (uint32_t)l * 16384u + off1(n, k);
        *(unsigned short*)(g_w1_hi + o) = __bfloat16_as_ushort(__float2bfloat16(val));
    } else if (id < PREP_RBF + PREP_W1 + PREP_W2) {
        const int t = id - PREP_RBF - PREP_W1;
        const int l = t >> 14;
        const int n = (t >> 7) & 127;
        const int k = t & 127;
        const float val = mw2[l * FIL * FIL + k * FIL + perm_n(n)];
        const uint32_t o = (uint32_t)l * 32768u + off2(n, k);
        *(unsigned short*)(g_w2_hi + o) = __bfloat16_as_ushort(__float2bfloat16(val));
    } else if (id < PREP_RBF + PREP_W1 + PREP_W2 + PREP_L1) {
        const int t = id - PREP_RBF - PREP_W1 - PREP_W2;
        const int l = t >> 14;
        const int n = (t >> 7) & 127;
        const int k = t & 127;
        const float val = l1w[l * HID * FIL + k * FIL + n];
        const uint32_t o = (uint32_t)l * 32768u + off2(n, k);
        *(unsigned short*)(g_l1img + o) = __bfloat16_as_ushort(__float2bfloat16(val));
    } else if (id < PREP_RBF + PREP_W1 + PREP_W2 + PREP_L1 + PREP_L2) {
        const int t = id - PREP_RBF - PREP_W1 - PREP_W2 - PREP_L1;
        const int l = t >> 14;
        const int n = (t >> 7) & 127;
        const int k = t & 127;
        const float val = l2w[l * FIL * HID + k * HID + n];
        const uint32_t o = (uint32_t)l * 32768u + off2(n, k);
        *(unsigned short*)(g_l2img + o) = __bfloat16_as_ushort(__float2bfloat16(val));
    } else if (id < PREP_TOTAL) {
        const int t = id - PREP_RBF - PREP_W1 - PREP_W2 - PREP_L1 - PREP_L2;
        const int n = t >> 7;
        const int c = t & 127;
        g_h[t] = emb[z[n] * HID + c];
    }
}

// ---------------- node linear via mma.sync (512 thr, 64-row tile) ----------------
// mode 0: y = x@W + b, and zero g_agg rows.  mode 1: y += silu(x@W + b).
#define LIN_A_HI 0
#define LIN_A_LO 16384
#define LIN_W    32768
#define LIN_B    65536
#define LIN_SMEM_BYTES (65536 + 512)

__global__ void __launch_bounds__(512, 1)
linear_mma_kernel(const float* __restrict__ x,
                  const unsigned char* __restrict__ wimg,
                  const float* __restrict__ b,
                  float* __restrict__ y,
                  int mode)
{
    extern __shared__ unsigned char base[];
    const uint32_t base32 = smem_u32(base);

    const int tid  = threadIdx.x;
    const int lane = tid & 31;
    const int wid  = tid >> 5;
    const int m0w  = (wid & 3) * 16;
    const int n0w  = (wid >> 2) * 32;
    const int r0   = blockIdx.x * 64;

    {
        const uint4* sw = (const uint4*)wimg;
        uint4* dw = (uint4*)(base + LIN_W);
        for (int i = tid; i < 2048; i += 512) dw[i] = sw[i];
        float* sb = (float*)(base + LIN_B);
        if (tid < 128) sb[tid] = b[tid];
    }

    {
        const int r  = tid >> 3;
        const int k0 = (tid & 7) * 16;
        const float4* xp = (const float4*)(x + (r0 + r) * 128 + k0);
        float4 v0 = xp[0], v1 = xp[1], v2 = xp[2], v3 = xp[3];
        float vv[16];
        *(float4*)&vv[0]  = v0; *(float4*)&vv[4]  = v1;
        *(float4*)&vv[8]  = v2; *(float4*)&vv[12] = v3;
        #pragma unroll
        for (int g = 0; g < 2; g++) {
            uint4 hi, lo;
            uint32_t* hp = (uint32_t*)&hi;
            uint32_t* lp = (uint32_t*)&lo;
            #pragma unroll
            for (int j = 0; j < 4; j++) {
                const float a = vv[g*8 + 2*j], c = vv[g*8 + 2*j + 1];
                const __nv_bfloat16 h0 = __float2bfloat16(a);
                const __nv_bfloat16 h1 = __float2bfloat16(c);
                hp[j] = (uint32_t)__bfloat16_as_ushort(h0) |
                        ((uint32_t)__bfloat16_as_ushort(h1) << 16);
                lp[j] = packbf2(a - __bfloat162float(h0), c - __bfloat162float(h1));
            }
            const uint32_t o = off2(r, k0 + g * 8);
            *(uint4*)(base + LIN_A_HI + o) = hi;
            *(uint4*)(base + LIN_A_LO + o) = lo;
        }
    }
    __syncthreads();

    const int lr = lane & 15;
    const int lk = (lane >> 4) * 8;

    float acc[4][4];
    #pragma unroll
    for (int nj = 0; nj < 4; nj++)
        #pragma unroll
        for (int q = 0; q < 4; q++) acc[nj][q] = 0.0f;

    #pragma unroll
    for (int ks = 0; ks < 8; ks++) {
        const int kb = ks * 16 + lk;
        uint32_t Ah[4], Al[4];
        {
            const uint32_t o = off2(m0w + lr, kb);
            ldsm4(Ah, base32 + LIN_A_HI + o);
            ldsm4(Al, base32 + LIN_A_LO + o);
        }
        #pragma unroll
        for (int nt = 0; nt < 2; nt++) {
            uint32_t Bh[4];
            ldsm4(Bh, base32 + LIN_W + off2(n0w + nt * 16 + lr, kb));
            #pragma unroll
            for (int h = 0; h < 2; h++) {
                const int nj = nt * 2 + h;
                mma16816(acc[nj], Ah, Bh[h], Bh[2 + h]);
                mma16816(acc[nj], Al, Bh[h], Bh[2 + h]);
            }
        }
    }

    {
        float* sb = (float*)(base + LIN_B);
        const int rbase = m0w + (lane >> 2);
        const int cbase = n0w + (lane & 3) * 2;
        #pragma unroll
        for (int nj = 0; nj < 4; nj++) {
            const int col = cbase + nj * 8;
            const float bb0 = sb[col], bb1 = sb[col + 1];
            #pragma unroll
            for (int half = 0; half < 2; half++) {
                const int row = r0 + rbase + half * 8;
                const float v0 = acc[nj][half * 2]     + bb0;
                const float v1 = acc[nj][half * 2 + 1] + bb1;
                float2* yp = (float2*)(y + row * 128 + col);
                if (mode == 0) {
                    float2 v; v.x = v0; v.y = v1;
                    *yp = v;
                } else {
                    float2 v = *yp;
                    v.x += silu_f(v0);
                    v.y += silu_f(v1);
                    *yp = v;
                }
            }
        }
    }
    if (mode == 0) {
        const int r  = r0 + (tid >> 3);
        const int k0 = (tid & 7) * 16;
        float4 zz; zz.x = zz.y = zz.z = zz.w = 0.0f;
        float4* ap = (float4*)(g_agg + r * 128 + k0);
        ap[0] = zz; ap[1] = zz; ap[2] = zz; ap[3] = zz;
    }
}

// ---------------- fused linear pair: h += silu(agg@W2+b2); x1 = h@W1+b1; zero agg ----
#define FL_A_HI 0
#define FL_A_LO 16384
#define FL_W2   32768
#define FL_W1   65536
#define FL_B2   98304
#define FL_B1   98816
#define FL_SMEM_BYTES 99328

__global__ void __launch_bounds__(512, 1)
fused_linear_kernel(const unsigned char* __restrict__ w2img, const float* __restrict__ b2,
                    const unsigned char* __restrict__ w1img, const float* __restrict__ b1)
{
    extern __shared__ unsigned char base[];
    const uint32_t base32 = smem_u32(base);

    const int tid  = threadIdx.x;
    const int lane = tid & 31;
    const int wid  = tid >> 5;
    const int m0w  = (wid & 3) * 16;
    const int n0w  = (wid >> 2) * 32;
    const int r0   = blockIdx.x * 64;

    // load both weight images + biases
    {
        const uint4* s2 = (const uint4*)w2img;
        const uint4* s1 = (const uint4*)w1img;
        uint4* d2 = (uint4*)(base + FL_W2);
        uint4* d1 = (uint4*)(base + FL_W1);
        for (int i = tid; i < 2048; i += 512) { d2[i] = s2[i]; d1[i] = s1[i]; }
        float* sb2 = (float*)(base + FL_B2);
        float* sb1 = (float*)(base + FL_B1);
        if (tid < 128) { sb2[tid] = b2[tid]; sb1[tid] = b1[tid]; }
    }

    // stage agg rows -> bf16 hi/lo swizzled
    {
        const int r  = tid >> 3;
        const int k0 = (tid & 7) * 16;
        const float4* xp = (const float4*)(g_agg + (r0 + r) * 128 + k0);
        float4 v0 = xp[0], v1 = xp[1], v2 = xp[2], v3 = xp[3];
        float vv[16];
        *(float4*)&vv[0]  = v0; *(float4*)&vv[4]  = v1;
        *(float4*)&vv[8]  = v2; *(float4*)&vv[12] = v3;
        #pragma unroll
        for (int g = 0; g < 2; g++) {
            uint4 hi, lo;
            uint32_t* hp = (uint32_t*)&hi;
            uint32_t* lp = (uint32_t*)&lo;
            #pragma unroll
            for (int j = 0; j < 4; j++) {
                const float a = vv[g*8 + 2*j], c = vv[g*8 + 2*j + 1];
                const __nv_bfloat16 h0 = __float2bfloat16(a);
                const __nv_bfloat16 h1 = __float2bfloat16(c);
                hp[j] = (uint32_t)__bfloat16_as_ushort(h0) |
                        ((uint32_t)__bfloat16_as_ushort(h1) << 16);
                lp[j] = packbf2(a - __bfloat162float(h0), c - __bfloat162float(h1));
            }
            const uint32_t o = off2(r, k0 + g * 8);
            *(uint4*)(base + FL_A_HI + o) = hi;
            *(uint4*)(base + FL_A_LO + o) = lo;
        }
    }
    __syncthreads();

    const int lr = lane & 15;
    const int lk = (lane >> 4) * 8;

    float acc[4][4];
    #pragma unroll
    for (int nj = 0; nj < 4; nj++)
        #pragma unroll
        for (int q = 0; q < 4; q++) acc[nj][q] = 0.0f;

    // GEMM A: agg @ W2 (2-term)
    #pragma unroll
    for (int ks = 0; ks < 8; ks++) {
        const int kb = ks * 16 + lk;
        uint32_t Ah[4], Al[4];
        {
            const uint32_t o = off2(m0w + lr, kb);
            ldsm4(Ah, base32 + FL_A_HI + o);
            ldsm4(Al, base32 + FL_A_LO + o);
        }
        #pragma unroll
        for (int nt = 0; nt < 2; nt++) {
            uint32_t Bh[4];
            ldsm4(Bh, base32 + FL_W2 + off2(n0w + nt * 16 + lr, kb));
            #pragma unroll
            for (int h = 0; h < 2; h++) {
                const int nj = nt * 2 + h;
                mma16816(acc[nj], Ah, Bh[h], Bh[2 + h]);
                mma16816(acc[nj], Al, Bh[h], Bh[2 + h]);
            }
        }
    }
    __syncthreads();   // A buffers dead; safe to overwrite after this

    // epilogue A: h_new = h_old + silu(acc + b2); write g_h; restage h_new into A hi/lo
    {
        float* sb2 = (float*)(base + FL_B2);
        const int rbase = m0w + (lane >> 2);
        const int cbase = n0w + (lane & 3) * 2;
        #pragma unroll
        for (int nj = 0; nj < 4; nj++) {
            const int col = cbase + nj * 8;
            const float bb0 = sb2[col], bb1 = sb2[col + 1];
            #pragma unroll
            for (int half = 0; half < 2; half++) {
                const int rloc = rbase + half * 8;
                const int row  = r0 + rloc;
                float2* hptr = (float2*)(g_h + row * 128 + col);
                float2 hv = *hptr;
                const float v0 = hv.x + silu_f(acc[nj][half * 2]     + bb0);
                const float v1 = hv.y + silu_f(acc[nj][half * 2 + 1] + bb1);
                float2 nv; nv.x = v0; nv.y = v1;
                *hptr = nv;
                const __nv_bfloat16 h0 = __float2bfloat16(v0);
                const __nv_bfloat16 h1 = __float2bfloat16(v1);
                const uint32_t o = off2(rloc, col);
                *(uint32_t*)(base + FL_A_HI + o) =
                    (uint32_t)__bfloat16_as_ushort(h0) |
                    ((uint32_t)__bfloat16_as_ushort(h1) << 16);
                *(uint32_t*)(base + FL_A_LO + o) =
                    packbf2(v0 - __bfloat162float(h0), v1 - __bfloat162float(h1));
            }
        }
    }
    __syncthreads();

    #pragma unroll
    for (int nj = 0; nj < 4; nj++)
        #pragma unroll
        for (int q = 0; q < 4; q++) acc[nj][q] = 0.0f;

    // GEMM B: h_new @ W1 (2-term)
    #pragma unroll
    for (int ks = 0; ks < 8; ks++) {
        const int kb = ks * 16 + lk;
        uint32_t Ah[4], Al[4];
        {
            const uint32_t o = off2(m0w + lr, kb);
            ldsm4(Ah, base32 + FL_A_HI + o);
            ldsm4(Al, base32 + FL_A_LO + o);
        }
        #pragma unroll
        for (int nt = 0; nt < 2; nt++) {
            uint32_t Bh[4];
            ldsm4(Bh, base32 + FL_W1 + off2(n0w + nt * 16 + lr, kb));
            #pragma unroll
            for (int h = 0; h < 2; h++) {
                const int nj = nt * 2 + h;
                mma16816(acc[nj], Ah, Bh[h], Bh[2 + h]);
                mma16816(acc[nj], Al, Bh[h], Bh[2 + h]);
            }
        }
    }

    // epilogue B: x1 = acc + b1; zero agg rows
    {
        float* sb1 = (float*)(base + FL_B1);
        const int rbase = m0w + (lane >> 2);
        const int cbase = n0w + (lane & 3) * 2;
        #pragma unroll
        for (int nj = 0; nj < 4; nj++) {
            const int col = cbase + nj * 8;
            const float bb0 = sb1[col], bb1 = sb1[col + 1];
            #pragma unroll
            for (int half = 0; half < 2; half++) {
                const int row = r0 + rbase + half * 8;
                float2 v;
                v.x = acc[nj][half * 2]     + bb0;
                v.y = acc[nj][half * 2 + 1] + bb1;
                *(float2*)(g_x1 + row * 128 + col) = v;
            }
        }
    }
    {
        const int r  = r0 + (tid >> 3);
        const int k0 = (tid & 7) * 16;
        float4 zz; zz.x = zz.y = zz.z = zz.w = 0.0f;
        float4* ap = (float4*)(g_agg + r * 128 + k0);
        ap[0] = zz; ap[1] = zz; ap[2] = zz; ap[3] = zz;
    }
}

// ---------------- tensor-core filter kernel, 1024 threads ----------------
// A1 parity double-buffered; mid-tile barrier scoped to 4-warp wm-groups.
#define SO_A1   0                 // 2 x 16384
#define SO_A2   32768             // 32768
#define SO_B1   65536             // 16384
#define SO_B2   81920             // 32768
#define SO_AUX  114688
#define AUXB_X1P 0
#define AUXB_X1Q 2048
#define AUXB_CV  4096
#define AUXB_DST 4608
#define AUX_B1   10240
#define FILT_SMEM_BYTES (SO_AUX + 10752)

__global__ void __launch_bounds__(1024, 1)
filter_mma_kernel(const float* __restrict__ b1g, const float* __restrict__ b2g,
                  const unsigned char* __restrict__ w1hi,
                  const unsigned char* __restrict__ w2hi)
{
    extern __shared__ unsigned char base[];
    const uint32_t base32 = smem_u32(base);

    const int tid  = threadIdx.x;
    const int lane = tid & 31;
    const int wid  = tid >> 5;
    const int wm   = wid & 7;          // warp m-tile: 16 edges (0..7)
    const int wn   = wid >> 3;         // warp n-tile: 32 channels (0..3)
    const int m0w  = wm * 16;
    const int n0w  = wn * 32;

    float* sb1 = (float*)(base + SO_AUX + AUX_B1);

    // resident weight copies
    {
        const uint4* s1h = (const uint4*)w1hi;
        const uint4* s2h = (const uint4*)w2hi;
        uint4* d1h = (uint4*)(base + SO_B1);
        uint4* d2h = (uint4*)(base + SO_B2);
        if (tid < 1024) d1h[tid] = s1h[tid];
        for (int i = tid; i < 2048; i += 1024) d2h[i] = s2h[i];
        if (tid < 128) sb1[tid] = b1g[tid];
    }

    // prefetch first tile's A1 into parity 0
    if (blockIdx.x < NTILES) {
        const size_t tb = (size_t)blockIdx.x * 16384;
        cp_async16(base32 + SO_A1 + tid * 16, g_rbf_hi + tb + tid * 16);
    }
    CP_COMMIT();

    const int lr = lane & 15;
    const int lk = (lane >> 4) * 8;

    int par = 0;
    for (int tile = blockIdx.x; tile < NTILES; tile += gridDim.x, par ^= 1) {
        const int e0 = tile * 128;
        unsigned char* aux = base + SO_AUX + par * 5120;
        float* sx1p = (float*)(aux + AUXB_X1P);
        float* sx1q = (float*)(aux + AUXB_X1Q);
        float* scv  = (float*)(aux + AUXB_CV);
        int*   sdst = (int*)  (aux + AUXB_DST);

        // ---- aux stage (parity buffer) ----
        if (tid < 128) { scv[tid] = g_cval[e0 + tid]; sdst[tid] = g_idx[e0 + tid]; }
        if (tid < 512) {
            const int jj = tid >> 7, c = tid & 127;
            const float v = g_x1[(4 * tile + jj) * 128 + c];
            sx1p[tid] = v;
            sx1q[tid] = v * b2g[c];
        }
        CP_WAIT0();
        __syncthreads();

        // ---- prefetch next tile's A1 into other parity (runs under GEMM1+GEMM2) ----
        {
            const int tnext = tile + gridDim.x;
            if (tnext < NTILES) {
                const size_t tb = (size_t)tnext * 16384;
                cp_async16(base32 + SO_A1 + (par ^ 1) * 16384 + tid * 16,
                           g_rbf_hi + tb + tid * 16);
            }
            CP_COMMIT();
        }

        float acc[4][4];
        #pragma unroll
        for (int nj = 0; nj < 4; nj++)
            #pragma unroll
            for (int q = 0; q < 4; q++) acc[nj][q] = 0.0f;

        // ---- GEMM1: K=64, single-term bf16, from A1[par] ----
        const uint32_t a1b = base32 + SO_A1 + par * 16384;
        #pragma unroll
        for (int ks = 0; ks < 4; ks++) {
            const int kb = ks * 16 + lk;
            uint32_t Ah[4];
            ldsm4(Ah, a1b + off1(m0w + lr, kb));
            #pragma unroll
            for (int nt = 0; nt < 2; nt++) {
                uint32_t Bh[4];
                ldsm4(Bh, base32 + SO_B1 + off1(n0w + nt * 16 + lr, kb));
                #pragma unroll
                for (int h = 0; h < 2; h++)
                    mma16816(acc[nt * 2 + h], Ah, Bh[h], Bh[2 + h]);
            }
        }

        // ---- epilogue1: silu -> bf16 -> A2 (own wm-group rows) ----
        {
            unsigned char* a2h = base + SO_A2;
            const int rbase = m0w + (lane >> 2);
            const int cbase = n0w + (lane & 3) * 2;
            #pragma unroll
            for (int nj = 0; nj < 4; nj++) {
                const int col = cbase + nj * 8;
                const float bb0 = sb1[col], bb1 = sb1[col + 1];
                #pragma unroll
                for (int half = 0; half < 2; half++) {
                    const int row = rbase + half * 8;
                    const float s0 = silu_f(acc[nj][half * 2]     + bb0);
                    const float s1 = silu_f(acc[nj][half * 2 + 1] + bb1);
                    *(uint32_t*)(a2h + off2(row, col)) = packbf2(s0, s1);
                }
            }
        }
        // scoped barrier: only the 4 warps sharing wm (they produce/consume A2 rows m0w..+15)
        asm volatile("bar.sync %0, %1;" :: "r"(1 + wm), "r"(128) : "memory");

        #pragma unroll
        for (int nj = 0; nj < 4; nj++)
            #pragma unroll
            for (int q = 0; q < 4; q++) acc[nj][q] = 0.0f;

        // ---- GEMM2: K=128, single-term bf16 ----
        #pragma unroll
        for (int ks = 0; ks < 8; ks++) {
            const int kb = ks * 16 + lk;
            uint32_t Ah[4];
            ldsm4(Ah, base32 + SO_A2 + off2(m0w + lr, kb));
            #pragma unroll
            for (int nt = 0; nt < 2; nt++) {
                uint32_t Bh[4];
                ldsm4(Bh, base32 + SO_B2 + off2(n0w + nt * 16 + lr, kb));
                #pragma unroll
                for (int h = 0; h < 2; h++)
                    mma16816(acc[nt * 2 + h], Ah, Bh[h], Bh[2 + h]);
            }
        }

        // ---- epilogue2: permuted channels -> red.v4 ----
        {
            const int q4 = (lane & 3) << 2;
            const int rbase = m0w + (lane >> 2);
            const int j4 = m0w >> 5;
            const float* pv = &sx1p[j4 * 128];
            const float* qv = &sx1q[j4 * 128];
            #pragma unroll
            for (int half = 0; half < 2; half++) {
                const int row = rbase + half * 8;
                const float cv = scv[row];
                const int   dst = sdst[row];
                float* aggp = &g_agg[dst * 128];
                #pragma unroll
                for (int pj = 0; pj < 2; pj++) {
                    const int pb = n0w + (pj << 4) + q4;
                    const float4 pvv = *(const float4*)&pv[pb];
                    const float4 qvv = *(const float4*)&qv[pb];
                    const float m0 = cv * fmaf(acc[2*pj    ][half * 2],     pvv.x, qvv.x);
                    const float m1 = cv * fmaf(acc[2*pj    ][half * 2 + 1], pvv.y, qvv.y);
                    const float m2 = cv * fmaf(acc[2*pj + 1][half * 2],     pvv.z, qvv.z);
                    const float m3 = cv * fmaf(acc[2*pj + 1][half * 2 + 1], pvv.w, qvv.w);
                    red_add_v4(aggp + pb, m0, m1, m2, m3);
                }
            }
        }
        // A2 WAR across tiles is protected by the tile-start full __syncthreads.
    }
}

// ---------------- output head + per-graph sum ----------------
#define OUT_SMEM_FLOATS (128*128 + 128*65)

__global__ void out_kernel(const float* __restrict__ ow1, const float* __restrict__ ob1,
                           const float* __restrict__ ow2, const float* __restrict__ ob2,
                           float* __restrict__ out)
{
    extern __shared__ float sm[];
    float* sh = sm;
    float* st = sh + 128*128;
    __shared__ float rsum[256];

    const int g    = blockIdx.x;
    const int tid  = threadIdx.x;
    const int base = g * ATOMS;

    for (int idx = tid; idx < 128 * 128; idx += 256)
        sh[idx] = g_h[base * 128 + idx];
    __syncthreads();

    const int d   = tid & 63;
    const int grp = tid >> 6;
    float acc[32];
    #pragma unroll
    for (int e = 0; e < 32; e++) acc[e] = 0.0f;
    const float* hh = sh + grp * 32 * 128;
    #pragma unroll 2
    for (int k = 0; k < 128; k++) {
        const float w = ow1[k * 64 + d];
        #pragma unroll
        for (int e = 0; e < 32; e++) acc[e] += hh[e * 128 + k] * w;
    }
    const float bb = ob1[d];
    #pragma unroll
    for (int e = 0; e < 32; e++) {
        const float v = acc[e] + bb;
        st[(grp * 32 + e) * 65 + d] = silu_f(v);
    }
    __syncthreads();

    float o = 0.0f;
    if (tid < 128) {
        float s = ob2[0];
        #pragma unroll 4
        for (int dd = 0; dd < 64; dd++) s += st[tid * 65 + dd] * ow2[dd];
        o = s;
    }
    rsum[tid] = o;
    __syncthreads();
    for (int s = 128; s >= 1; s >>= 1) {
        if (tid < s) rsum[tid] += rsum[tid + s];
        __syncthreads();
    }
    if (tid == 0) out[g] = rsum[0];
}

// ---------------- launch ----------------
extern "C" void kernel_launch(void* const* d_in, const int* in_sizes, int n_in,
                              void* d_out, int out_size)
{
    const float* pos   = (const float*)d_in[0];
    const int*   z     = (const int*)  d_in[1];
    const int*   batch = (const int*)  d_in[2];
    const float* emb   = (const float*)d_in[3];
    const float* mw1   = (const float*)d_in[4];
    const float* mb1   = (const float*)d_in[5];
    const float* mw2   = (const float*)d_in[6];
    const float* mb2   = (const float*)d_in[7];
    const float* l1w   = (const float*)d_in[8];
    const float* l1b   = (const float*)d_in[9];
    const float* l2w   = (const float*)d_in[10];
    const float* l2b   = (const float*)d_in[11];
    const float* ow1   = (const float*)d_in[12];
    const float* ob1   = (const float*)d_in[13];
    const float* ow2   = (const float*)d_in[14];
    const float* ob2   = (const float*)d_in[15];
    float* out = (float*)d_out;

    float *hp, *x1p, *aggp;
    cudaGetSymbolAddress((void**)&hp,   g_h);
    cudaGetSymbolAddress((void**)&x1p,  g_x1);
    cudaGetSymbolAddress((void**)&aggp, g_agg);
    unsigned char *w1h, *w2h, *l1i, *l2i;
    cudaGetSymbolAddress((void**)&w1h, g_w1_hi);
    cudaGetSymbolAddress((void**)&w2h, g_w2_hi);
    cudaGetSymbolAddress((void**)&l1i, g_l1img);
    cudaGetSymbolAddress((void**)&l2i, g_l2img);

    cudaFuncSetAttribute(filter_mma_kernel, cudaFuncAttributeMaxDynamicSharedMemorySize,
                         FILT_SMEM_BYTES);
    cudaFuncSetAttribute(linear_mma_kernel, cudaFuncAttributeMaxDynamicSharedMemorySize,
                         LIN_SMEM_BYTES);
    cudaFuncSetAttribute(fused_linear_kernel, cudaFuncAttributeMaxDynamicSharedMemorySize,
                         FL_SMEM_BYTES);
    cudaFuncSetAttribute(out_kernel, cudaFuncAttributeMaxDynamicSharedMemorySize,
                         OUT_SMEM_FLOATS * (int)sizeof(float));

    build_graph_kernel<<<NTOT / 4, 128>>>(pos, batch);
    prep_all_kernel<<<(PREP_TOTAL + 255) / 256, 256>>>(mw1, mw2, l1w, l2w, z, emb);

    linear_mma_kernel<<<NTOT / 64, 512, LIN_SMEM_BYTES>>>(
        hp, l1i, l1b, x1p, 0);

    for (int l = 0; l < LAYERS; l++) {
        filter_mma_kernel<<<148, 1024, FILT_SMEM_BYTES>>>(
            mb1 + l * FIL, mb2 + l * FIL,
            w1h + l * 16384, w2h + l * 32768);
        if (l < LAYERS - 1) {
            fused_linear_kernel<<<NTOT / 64, 512, FL_SMEM_BYTES>>>(
                l2i + l * 32768, l2b + l * HID,
                l1i + (l + 1) * 32768, l1b + (l + 1) * FIL);
        } else {
            linear_mma_kernel<<<NTOT / 64, 512, LIN_SMEM_BYTES>>>(
                aggp, l2i + l * 32768, l2b + l * HID, hp, 1);
        }
    }

    out_kernel<<<NUM_G, 256, OUT_SMEM_FLOATS * sizeof(float)>>>(ow1, ob1, ow2, ob2, out);
}

// round 13
// speedup vs baseline: 3.1852x; 1.2360x over previous
#include <cuda_runtime.h>
#include <cuda_bf16.h>
#include <math.h>
#include <stdint.h>

// ---------------- problem constants ----------------
#define NG        50
#define KNB       32
#define NUM_G     64
#define ATOMS     128
#define NTOT      (NUM_G * ATOMS)     // 8192
#define HID       128
#define FIL       128
#define LAYERS    6
#define EDGES     (NTOT * KNB)        // 262144
#define NTILES    (EDGES / 128)       // 2048
#define CUTOFF    10.0f
#define PI_C      3.14159265f

#define INVALID_KEY 0xFFFFFFFFFFFFFFFFULL
typedef unsigned long long ull;

// ---------------- device scratch ----------------
__device__ int   g_idx [EDGES];
__device__ float g_dist[EDGES];
__device__ float g_cval[EDGES];
__device__ float g_h   [NTOT * HID];
__device__ float g_x1  [NTOT * FIL];
__device__ float g_agg [NTOT * FIL];

// ldmatrix-layout bf16 tile images
__device__ unsigned char g_rbf_hi[NTILES * 16384];   // per tile: [128 e][64 k], k=50 column = 1.0
__device__ unsigned char g_w1_hi [LAYERS * 16384];   // [128 n][64 k], k=50 row = b1
__device__ unsigned char g_w2_hi [LAYERS * 32768];   // [128 n][128 k], n-permuted
__device__ unsigned char g_l1img [LAYERS * 32768];   // [128 n][128 k]
__device__ unsigned char g_l2img [LAYERS * 32768];   // [128 n][128 k]

// fast silu: v * rcp(1 + 2^(-v*log2e)), approx ops (err ~2^-21, negligible here)
__device__ __forceinline__ float silu_f(float v) {
    float e;
    asm("ex2.approx.f32 %0, %1;" : "=f"(e) : "f"(-1.442695041f * v));
    float r;
    asm("rcp.approx.f32 %0, %1;" : "=f"(r) : "f"(1.0f + e));
    return v * r;
}

__device__ __forceinline__ void red_add_v4(float* p, float a, float b, float c, float d) {
    asm volatile("red.global.add.v4.f32 [%0], {%1,%2,%3,%4};"
                 :: "l"(p), "f"(a), "f"(b), "f"(c), "f"(d) : "memory");
}

__device__ __forceinline__ uint32_t smem_u32(const void* p) {
    uint32_t a;
    asm("{ .reg .u64 t; cvta.to.shared.u64 t, %1; cvt.u32.u64 %0, t; }" : "=r"(a) : "l"(p));
    return a;
}

// ---------------- cp.async helpers ----------------
__device__ __forceinline__ void cp_async16(uint32_t saddr, const void* gaddr) {
    asm volatile("cp.async.cg.shared.global [%0], [%1], 16;" :: "r"(saddr), "l"(gaddr));
}
#define CP_COMMIT() asm volatile("cp.async.commit_group;" ::: "memory")
#define CP_WAIT0()  asm volatile("cp.async.wait_group 0;" ::: "memory")

// ---------------- mma.sync / ldmatrix helpers ----------------
__device__ __forceinline__ void ldsm4(uint32_t* r, uint32_t addr) {
    asm volatile("ldmatrix.sync.aligned.m8n8.x4.shared.b16 {%0,%1,%2,%3}, [%4];"
                 : "=r"(r[0]), "=r"(r[1]), "=r"(r[2]), "=r"(r[3]) : "r"(addr));
}
__device__ __forceinline__ void mma16816(float* c, const uint32_t* a, uint32_t b0, uint32_t b1) {
    asm volatile("mma.sync.aligned.m16n8k16.row.col.f32.bf16.bf16.f32 "
                 "{%0,%1,%2,%3}, {%4,%5,%6,%7}, {%8,%9}, {%0,%1,%2,%3};"
                 : "+f"(c[0]), "+f"(c[1]), "+f"(c[2]), "+f"(c[3])
                 : "r"(a[0]), "r"(a[1]), "r"(a[2]), "r"(a[3]), "r"(b0), "r"(b1));
}

// swizzled byte offsets
__device__ __forceinline__ uint32_t off1(int r, int k) {
    return (uint32_t)(r * 128 + (((k >> 3) ^ (r & 7)) << 4) + (k & 7) * 2);
}
__device__ __forceinline__ uint32_t off2(int r, int k) {
    return (uint32_t)(r * 256 + (((k >> 3) ^ (r & 7)) << 4) + (k & 7) * 2);
}
// output-channel permutation for red.v4-friendly epilogue
__device__ __forceinline__ int perm_n(int n) {
    const int a = n >> 3, q = (n >> 1) & 3, h = n & 1;
    return ((a >> 1) << 4) + (q << 2) + ((a & 1) << 1) + h;
}

__device__ __forceinline__ uint32_t packbf2(float a, float b) {
    return (uint32_t)__bfloat16_as_ushort(__float2bfloat16(a)) |
           ((uint32_t)__bfloat16_as_ushort(__float2bfloat16(b)) << 16);
}

// ---------------- graph build: warp-per-node, shfl min-reduce ----------------
__global__ void build_graph_kernel(const float* __restrict__ pos,
                                   const int* __restrict__ batch)
{
    const int wid  = threadIdx.x >> 5;
    const int lane = threadIdx.x & 31;
    const int i    = blockIdx.x * 4 + wid;
    const int base = (i >> 7) << 7;

    const float px = pos[3*i], py = pos[3*i+1], pz = pos[3*i+2];

    ull key[4];
    #pragma unroll
    for (int c = 0; c < 4; c++) {
        const int j = base + c * 32 + lane;
        const float dx = pos[3*j]   - px;
        const float dy = pos[3*j+1] - py;
        const float dz = pos[3*j+2] - pz;
        const float d2 = dx*dx + dy*dy + dz*dz;
        key[c] = (j != i && d2 < CUTOFF*CUTOFF)
            ? ((((ull)__float_as_uint(d2)) << 32) | (unsigned int)j)
            : INVALID_KEY;
    }

    for (int k = 0; k < KNB; k++) {
        ull m0 = key[0] < key[1] ? key[0] : key[1];
        ull m1 = key[2] < key[3] ? key[2] : key[3];
        ull m  = m0 < m1 ? m0 : m1;
        #pragma unroll
        for (int s = 16; s >= 1; s >>= 1) {
            ull o = __shfl_xor_sync(0xffffffffu, m, s);
            if (o < m) m = o;
        }
        #pragma unroll
        for (int c = 0; c < 4; c++)
            if (key[c] == m) key[c] = INVALID_KEY;
        if (lane == k) {
            const int eo = i * KNB + k;
            if (m != INVALID_KEY) {
                const int   jj = (int)(m & 0xffffffffu);
                const float d  = sqrtf(__uint_as_float((unsigned int)(m >> 32)));
                g_idx[eo]  = jj;
                g_dist[eo] = d;
                const float cv = 0.5f * (cosf(d * (PI_C / CUTOFF)) + 1.0f);
                g_cval[eo] = (d < CUTOFF) ? cv : 0.0f;
            } else {
                g_idx[eo]  = i;
                g_dist[eo] = 1.0f;
                g_cval[eo] = 0.0f;
            }
        }
    }
}

// ---------------- fused prep ----------------
#define PREP_RBF   (EDGES * 64)
#define PREP_W1    (LAYERS * 128 * 64)
#define PREP_W2    (LAYERS * 128 * 128)
#define PREP_L1    (LAYERS * 128 * 128)
#define PREP_L2    (LAYERS * 128 * 128)
#define PREP_EMB   (NTOT * HID)
#define PREP_TOTAL (PREP_RBF + PREP_W1 + PREP_W2 + PREP_L1 + PREP_L2 + PREP_EMB)

__global__ void prep_all_kernel(const float* __restrict__ mw1,
                                const float* __restrict__ mb1,
                                const float* __restrict__ mw2,
                                const float* __restrict__ l1w,
                                const float* __restrict__ l2w,
                                const int* __restrict__ z,
                                const float* __restrict__ emb)
{
    const int id = blockIdx.x * blockDim.x + threadIdx.x;
    if (id < PREP_RBF) {
        const int e = id >> 6;
        const int k = id & 63;
        const int tile = e >> 7;
        const int r    = e & 127;
        float val;
        if (k < NG) {
            const float w = CUTOFF / (float)(NG - 1);
            const float t = (g_dist[e] - (float)k * w) / w;
            val = expf(-0.5f * t * t);
        } else {
            val = (k == NG) ? 1.0f : 0.0f;     // bias column
        }
        const uint32_t o = (uint32_t)tile * 16384u + off1(r, k);
        *(unsigned short*)(g_rbf_hi + o) = __bfloat16_as_ushort(__float2bfloat16(val));
    } else if (id < PREP_RBF + PREP_W1) {
        const int t = id - PREP_RBF;
        const int l = t >> 13;
        const int n = (t >> 6) & 127;
        const int k = t & 63;
        float val;
        if (k < NG)       val = mw1[l * NG * FIL + k * FIL + n];
        else if (k == NG) val = mb1[l * FIL + n];   // folded bias row
        else              val = 0.0f;
        const uint32_t o = (uint32_t)l * 16384u + off1(n, k);
        *(unsigned short*)(g_w1_hi + o) = __bfloat16_as_ushort(__float2bfloat16(val));
    } else if (id < PREP_RBF + PREP_W1 + PREP_W2) {
        const int t = id - PREP_RBF - PREP_W1;
        const int l = t >> 14;
        const int n = (t >> 7) & 127;
        const int k = t & 127;
        const float val = mw2[l * FIL * FIL + k * FIL + perm_n(n)];
        const uint32_t o = (uint32_t)l * 32768u + off2(n, k);
        *(unsigned short*)(g_w2_hi + o) = __bfloat16_as_ushort(__float2bfloat16(val));
    } else if (id < PREP_RBF + PREP_W1 + PREP_W2 + PREP_L1) {
        const int t = id - PREP_RBF - PREP_W1 - PREP_W2;
        const int l = t >> 14;
        const int n = (t >> 7) & 127;
        const int k = t & 127;
        const float val = l1w[l * HID * FIL + k * FIL + n];
        const uint32_t o = (uint32_t)l * 32768u + off2(n, k);
        *(unsigned short*)(g_l1img + o) = __bfloat16_as_ushort(__float2bfloat16(val));
    } else if (id < PREP_RBF + PREP_W1 + PREP_W2 + PREP_L1 + PREP_L2) {
        const int t = id - PREP_RBF - PREP_W1 - PREP_W2 - PREP_L1;
        const int l = t >> 14;
        const int n = (t >> 7) & 127;
        const int k = t & 127;
        const float val = l2w[l * FIL * HID + k * HID + n];
        const uint32_t o = (uint32_t)l * 32768u + off2(n, k);
        *(unsigned short*)(g_l2img + o) = __bfloat16_as_ushort(__float2bfloat16(val));
    } else if (id < PREP_TOTAL) {
        const int t = id - PREP_RBF - PREP_W1 - PREP_W2 - PREP_L1 - PREP_L2;
        const int n = t >> 7;
        const int c = t & 127;
        g_h[t] = emb[z[n] * HID + c];
    }
}

// ---------------- node linear via mma.sync (512 thr, 64-row tile) ----------------
#define LIN_A_HI 0
#define LIN_A_LO 16384
#define LIN_W    32768
#define LIN_B    65536
#define LIN_SMEM_BYTES (65536 + 512)

__global__ void __launch_bounds__(512, 1)
linear_mma_kernel(const float* __restrict__ x,
                  const unsigned char* __restrict__ wimg,
                  const float* __restrict__ b,
                  float* __restrict__ y,
                  int mode)
{
    extern __shared__ unsigned char base[];
    const uint32_t base32 = smem_u32(base);

    const int tid  = threadIdx.x;
    const int lane = tid & 31;
    const int wid  = tid >> 5;
    const int m0w  = (wid & 3) * 16;
    const int n0w  = (wid >> 2) * 32;
    const int r0   = blockIdx.x * 64;

    {
        const uint4* sw = (const uint4*)wimg;
        uint4* dw = (uint4*)(base + LIN_W);
        for (int i = tid; i < 2048; i += 512) dw[i] = sw[i];
        float* sb = (float*)(base + LIN_B);
        if (tid < 128) sb[tid] = b[tid];
    }

    {
        const int r  = tid >> 3;
        const int k0 = (tid & 7) * 16;
        const float4* xp = (const float4*)(x + (r0 + r) * 128 + k0);
        float4 v0 = xp[0], v1 = xp[1], v2 = xp[2], v3 = xp[3];
        float vv[16];
        *(float4*)&vv[0]  = v0; *(float4*)&vv[4]  = v1;
        *(float4*)&vv[8]  = v2; *(float4*)&vv[12] = v3;
        #pragma unroll
        for (int g = 0; g < 2; g++) {
            uint4 hi, lo;
            uint32_t* hp = (uint32_t*)&hi;
            uint32_t* lp = (uint32_t*)&lo;
            #pragma unroll
            for (int j = 0; j < 4; j++) {
                const float a = vv[g*8 + 2*j], c = vv[g*8 + 2*j + 1];
                const __nv_bfloat16 h0 = __float2bfloat16(a);
                const __nv_bfloat16 h1 = __float2bfloat16(c);
                hp[j] = (uint32_t)__bfloat16_as_ushort(h0) |
                        ((uint32_t)__bfloat16_as_ushort(h1) << 16);
                lp[j] = packbf2(a - __bfloat162float(h0), c - __bfloat162float(h1));
            }
            const uint32_t o = off2(r, k0 + g * 8);
            *(uint4*)(base + LIN_A_HI + o) = hi;
            *(uint4*)(base + LIN_A_LO + o) = lo;
        }
    }
    __syncthreads();

    const int lr = lane & 15;
    const int lk = (lane >> 4) * 8;

    float acc[4][4];
    #pragma unroll
    for (int nj = 0; nj < 4; nj++)
        #pragma unroll
        for (int q = 0; q < 4; q++) acc[nj][q] = 0.0f;

    #pragma unroll
    for (int ks = 0; ks < 8; ks++) {
        const int kb = ks * 16 + lk;
        uint32_t Ah[4], Al[4];
        {
            const uint32_t o = off2(m0w + lr, kb);
            ldsm4(Ah, base32 + LIN_A_HI + o);
            ldsm4(Al, base32 + LIN_A_LO + o);
        }
        #pragma unroll
        for (int nt = 0; nt < 2; nt++) {
            uint32_t Bh[4];
            ldsm4(Bh, base32 + LIN_W + off2(n0w + nt * 16 + lr, kb));
            #pragma unroll
            for (int h = 0; h < 2; h++) {
                const int nj = nt * 2 + h;
                mma16816(acc[nj], Ah, Bh[h], Bh[2 + h]);
                mma16816(acc[nj], Al, Bh[h], Bh[2 + h]);
            }
        }
    }

    {
        float* sb = (float*)(base + LIN_B);
        const int rbase = m0w + (lane >> 2);
        const int cbase = n0w + (lane & 3) * 2;
        #pragma unroll
        for (int nj = 0; nj < 4; nj++) {
            const int col = cbase + nj * 8;
            const float bb0 = sb[col], bb1 = sb[col + 1];
            #pragma unroll
            for (int half = 0; half < 2; half++) {
                const int row = r0 + rbase + half * 8;
                const float v0 = acc[nj][half * 2]     + bb0;
                const float v1 = acc[nj][half * 2 + 1] + bb1;
                float2* yp = (float2*)(y + row * 128 + col);
                if (mode == 0) {
                    float2 v; v.x = v0; v.y = v1;
                    *yp = v;
                } else {
                    float2 v = *yp;
                    v.x += silu_f(v0);
                    v.y += silu_f(v1);
                    *yp = v;
                }
            }
        }
    }
    if (mode == 0) {
        const int r  = r0 + (tid >> 3);
        const int k0 = (tid & 7) * 16;
        float4 zz; zz.x = zz.y = zz.z = zz.w = 0.0f;
        float4* ap = (float4*)(g_agg + r * 128 + k0);
        ap[0] = zz; ap[1] = zz; ap[2] = zz; ap[3] = zz;
    }
}

// ---------------- fused linear pair: h += silu(agg@W2+b2); x1 = h@W1+b1; zero agg ----
#define FL_A_HI 0
#define FL_A_LO 16384
#define FL_W2   32768
#define FL_W1   65536
#define FL_B2   98304
#define FL_B1   98816
#define FL_SMEM_BYTES 99328

__global__ void __launch_bounds__(512, 1)
fused_linear_kernel(const unsigned char* __restrict__ w2img, const float* __restrict__ b2,
                    const unsigned char* __restrict__ w1img, const float* __restrict__ b1)
{
    extern __shared__ unsigned char base[];
    const uint32_t base32 = smem_u32(base);

    const int tid  = threadIdx.x;
    const int lane = tid & 31;
    const int wid  = tid >> 5;
    const int m0w  = (wid & 3) * 16;
    const int n0w  = (wid >> 2) * 32;
    const int r0   = blockIdx.x * 64;

    {
        const uint4* s2 = (const uint4*)w2img;
        const uint4* s1 = (const uint4*)w1img;
        uint4* d2 = (uint4*)(base + FL_W2);
        uint4* d1 = (uint4*)(base + FL_W1);
        for (int i = tid; i < 2048; i += 512) { d2[i] = s2[i]; d1[i] = s1[i]; }
        float* sb2 = (float*)(base + FL_B2);
        float* sb1 = (float*)(base + FL_B1);
        if (tid < 128) { sb2[tid] = b2[tid]; sb1[tid] = b1[tid]; }
    }

    {
        const int r  = tid >> 3;
        const int k0 = (tid & 7) * 16;
        const float4* xp = (const float4*)(g_agg + (r0 + r) * 128 + k0);
        float4 v0 = xp[0], v1 = xp[1], v2 = xp[2], v3 = xp[3];
        float vv[16];
        *(float4*)&vv[0]  = v0; *(float4*)&vv[4]  = v1;
        *(float4*)&vv[8]  = v2; *(float4*)&vv[12] = v3;
        #pragma unroll
        for (int g = 0; g < 2; g++) {
            uint4 hi, lo;
            uint32_t* hp = (uint32_t*)&hi;
            uint32_t* lp = (uint32_t*)&lo;
            #pragma unroll
            for (int j = 0; j < 4; j++) {
                const float a = vv[g*8 + 2*j], c = vv[g*8 + 2*j + 1];
                const __nv_bfloat16 h0 = __float2bfloat16(a);
                const __nv_bfloat16 h1 = __float2bfloat16(c);
                hp[j] = (uint32_t)__bfloat16_as_ushort(h0) |
                        ((uint32_t)__bfloat16_as_ushort(h1) << 16);
                lp[j] = packbf2(a - __bfloat162float(h0), c - __bfloat162float(h1));
            }
            const uint32_t o = off2(r, k0 + g * 8);
            *(uint4*)(base + FL_A_HI + o) = hi;
            *(uint4*)(base + FL_A_LO + o) = lo;
        }
    }
    __syncthreads();

    const int lr = lane & 15;
    const int lk = (lane >> 4) * 8;

    float acc[4][4];
    #pragma unroll
    for (int nj = 0; nj < 4; nj++)
        #pragma unroll
        for (int q = 0; q < 4; q++) acc[nj][q] = 0.0f;

    // GEMM A: agg @ W2 (2-term)
    #pragma unroll
    for (int ks = 0; ks < 8; ks++) {
        const int kb = ks * 16 + lk;
        uint32_t Ah[4], Al[4];
        {
            const uint32_t o = off2(m0w + lr, kb);
            ldsm4(Ah, base32 + FL_A_HI + o);
            ldsm4(Al, base32 + FL_A_LO + o);
        }
        #pragma unroll
        for (int nt = 0; nt < 2; nt++) {
            uint32_t Bh[4];
            ldsm4(Bh, base32 + FL_W2 + off2(n0w + nt * 16 + lr, kb));
            #pragma unroll
            for (int h = 0; h < 2; h++) {
                const int nj = nt * 2 + h;
                mma16816(acc[nj], Ah, Bh[h], Bh[2 + h]);
                mma16816(acc[nj], Al, Bh[h], Bh[2 + h]);
            }
        }
    }
    __syncthreads();

    // epilogue A
    {
        float* sb2 = (float*)(base + FL_B2);
        const int rbase = m0w + (lane >> 2);
        const int cbase = n0w + (lane & 3) * 2;
        #pragma unroll
        for (int nj = 0; nj < 4; nj++) {
            const int col = cbase + nj * 8;
            const float bb0 = sb2[col], bb1 = sb2[col + 1];
            #pragma unroll
            for (int half = 0; half < 2; half++) {
                const int rloc = rbase + half * 8;
                const int row  = r0 + rloc;
                float2* hptr = (float2*)(g_h + row * 128 + col);
                float2 hv = *hptr;
                const float v0 = hv.x + silu_f(acc[nj][half * 2]     + bb0);
                const float v1 = hv.y + silu_f(acc[nj][half * 2 + 1] + bb1);
                float2 nv; nv.x = v0; nv.y = v1;
                *hptr = nv;
                const __nv_bfloat16 h0 = __float2bfloat16(v0);
                const __nv_bfloat16 h1 = __float2bfloat16(v1);
                const uint32_t o = off2(rloc, col);
                *(uint32_t*)(base + FL_A_HI + o) =
                    (uint32_t)__bfloat16_as_ushort(h0) |
                    ((uint32_t)__bfloat16_as_ushort(h1) << 16);
                *(uint32_t*)(base + FL_A_LO + o) =
                    packbf2(v0 - __bfloat162float(h0), v1 - __bfloat162float(h1));
            }
        }
    }
    __syncthreads();

    #pragma unroll
    for (int nj = 0; nj < 4; nj++)
        #pragma unroll
        for (int q = 0; q < 4; q++) acc[nj][q] = 0.0f;

    // GEMM B: h_new @ W1 (2-term)
    #pragma unroll
    for (int ks = 0; ks < 8; ks++) {
        const int kb = ks * 16 + lk;
        uint32_t Ah[4], Al[4];
        {
            const uint32_t o = off2(m0w + lr, kb);
            ldsm4(Ah, base32 + FL_A_HI + o);
            ldsm4(Al, base32 + FL_A_LO + o);
        }
        #pragma unroll
        for (int nt = 0; nt < 2; nt++) {
            uint32_t Bh[4];
            ldsm4(Bh, base32 + FL_W1 + off2(n0w + nt * 16 + lr, kb));
            #pragma unroll
            for (int h = 0; h < 2; h++) {
                const int nj = nt * 2 + h;
                mma16816(acc[nj], Ah, Bh[h], Bh[2 + h]);
                mma16816(acc[nj], Al, Bh[h], Bh[2 + h]);
            }
        }
    }

    // epilogue B
    {
        float* sb1 = (float*)(base + FL_B1);
        const int rbase = m0w + (lane >> 2);
        const int cbase = n0w + (lane & 3) * 2;
        #pragma unroll
        for (int nj = 0; nj < 4; nj++) {
            const int col = cbase + nj * 8;
            const float bb0 = sb1[col], bb1 = sb1[col + 1];
            #pragma unroll
            for (int half = 0; half < 2; half++) {
                const int row = r0 + rbase + half * 8;
                float2 v;
                v.x = acc[nj][half * 2]     + bb0;
                v.y = acc[nj][half * 2 + 1] + bb1;
                *(float2*)(g_x1 + row * 128 + col) = v;
            }
        }
    }
    {
        const int r  = r0 + (tid >> 3);
        const int k0 = (tid & 7) * 16;
        float4 zz; zz.x = zz.y = zz.z = zz.w = 0.0f;
        float4* ap = (float4*)(g_agg + r * 128 + k0);
        ap[0] = zz; ap[1] = zz; ap[2] = zz; ap[3] = zz;
    }
}

// ---------------- tensor-core filter kernel, 512 threads ----------------
// warp tile: 32 edges x 32 channels. B1 fragments register-resident.
// b1 folded into GEMM1 (rbf k=50 column = 1, w1 row 50 = b1).
#define SO_A1   0                 // 2 x 16384 (parity)
#define SO_A2   32768             // 32768
#define SO_B1   65536             // 16384
#define SO_B2   81920             // 32768
#define SO_AUX  114688
#define AUXB_X1P 0
#define AUXB_X1Q 2048
#define AUXB_CV  4096
#define AUXB_DST 4608
#define FILT_SMEM_BYTES (SO_AUX + 10240)

__global__ void __launch_bounds__(512, 1)
filter_mma_kernel(const float* __restrict__ b2g,
                  const unsigned char* __restrict__ w1hi,
                  const unsigned char* __restrict__ w2hi)
{
    extern __shared__ unsigned char base[];
    const uint32_t base32 = smem_u32(base);

    const int tid  = threadIdx.x;
    const int lane = tid & 31;
    const int wid  = tid >> 5;
    const int wm   = wid & 3;          // warp m-tile: 32 edges (0..3)
    const int wn   = wid >> 2;         // warp n-tile: 32 channels (0..3)
    const int m0w  = wm * 32;
    const int n0w  = wn * 32;

    // resident weight copies
    {
        const uint4* s1h = (const uint4*)w1hi;
        const uint4* s2h = (const uint4*)w2hi;
        uint4* d1h = (uint4*)(base + SO_B1);
        uint4* d2h = (uint4*)(base + SO_B2);
        for (int i = tid; i < 1024; i += 512) d1h[i] = s1h[i];
        for (int i = tid; i < 2048; i += 512) d2h[i] = s2h[i];
    }

    // prefetch first tile's A1 into parity 0
    if (blockIdx.x < NTILES) {
        const size_t tb = (size_t)blockIdx.x * 16384;
        for (int i = tid; i < 1024; i += 512)
            cp_async16(base32 + SO_A1 + i * 16, g_rbf_hi + tb + i * 16);
    }
    CP_COMMIT();

    const int lr = lane & 15;
    const int lk = (lane >> 4) * 8;

    __syncthreads();    // weights visible

    // hoist B1 fragments into registers (tile-invariant): 4 ks x 2 nt x 4 regs
    uint32_t B1r[4][2][4];
    #pragma unroll
    for (int ks = 0; ks < 4; ks++) {
        const int kb = ks * 16 + lk;
        #pragma unroll
        for (int nt = 0; nt < 2; nt++)
            ldsm4(B1r[ks][nt], base32 + SO_B1 + off1(n0w + nt * 16 + lr, kb));
    }

    int par = 0;
    for (int tile = blockIdx.x; tile < NTILES; tile += gridDim.x, par ^= 1) {
        const int e0 = tile * 128;
        unsigned char* aux = base + SO_AUX + par * 5120;
        float* sx1p = (float*)(aux + AUXB_X1P);
        float* sx1q = (float*)(aux + AUXB_X1Q);
        float* scv  = (float*)(aux + AUXB_CV);
        int*   sdst = (int*)  (aux + AUXB_DST);

        // ---- aux stage ----
        if (tid < 128) { scv[tid] = g_cval[e0 + tid]; sdst[tid] = g_idx[e0 + tid]; }
        {
            const int jj = tid >> 7, c = tid & 127;
            const float v = g_x1[(4 * tile + jj) * 128 + c];
            sx1p[tid] = v;
            sx1q[tid] = v * b2g[c];
        }
        CP_WAIT0();
        __syncthreads();

        // ---- prefetch next tile's A1 into other parity ----
        {
            const int tnext = tile + gridDim.x;
            if (tnext < NTILES) {
                const size_t tb = (size_t)tnext * 16384;
                for (int i = tid; i < 1024; i += 512)
                    cp_async16(base32 + SO_A1 + (par ^ 1) * 16384 + i * 16,
                               g_rbf_hi + tb + i * 16);
            }
            CP_COMMIT();
        }

        float acc[2][4][4];
        #pragma unroll
        for (int mi = 0; mi < 2; mi++)
            #pragma unroll
            for (int nj = 0; nj < 4; nj++)
                #pragma unroll
                for (int q = 0; q < 4; q++) acc[mi][nj][q] = 0.0f;

        // ---- GEMM1: K=64 (includes bias via k=50), B from registers ----
        const uint32_t a1b = base32 + SO_A1 + par * 16384;
        #pragma unroll
        for (int ks = 0; ks < 4; ks++) {
            const int kb = ks * 16 + lk;
            uint32_t Ah[2][4];
            #pragma unroll
            for (int mi = 0; mi < 2; mi++)
                ldsm4(Ah[mi], a1b + off1(m0w + mi * 16 + lr, kb));
            #pragma unroll
            for (int nt = 0; nt < 2; nt++)
                #pragma unroll
                for (int h = 0; h < 2; h++) {
                    const int nj = nt * 2 + h;
                    #pragma unroll
                    for (int mi = 0; mi < 2; mi++)
                        mma16816(acc[mi][nj], Ah[mi], B1r[ks][nt][h], B1r[ks][nt][2 + h]);
                }
        }

        // ---- epilogue1: silu -> bf16 -> A2 (no bias; folded) ----
        {
            unsigned char* a2h = base + SO_A2;
            const int rbase = m0w + (lane >> 2);
            const int cbase = n0w + (lane & 3) * 2;
            #pragma unroll
            for (int mi = 0; mi < 2; mi++)
                #pragma unroll
                for (int nj = 0; nj < 4; nj++) {
                    const int col = cbase + nj * 8;
                    #pragma unroll
                    for (int half = 0; half < 2; half++) {
                        const int row = rbase + mi * 16 + half * 8;
                        const float s0 = silu_f(acc[mi][nj][half * 2]);
                        const float s1 = silu_f(acc[mi][nj][half * 2 + 1]);
                        *(uint32_t*)(a2h + off2(row, col)) = packbf2(s0, s1);
                    }
                }
        }
        // scoped barrier: 4 warps sharing wm
        asm volatile("bar.sync %0, %1;" :: "r"(1 + wm), "r"(128) : "memory");

        #pragma unroll
        for (int mi = 0; mi < 2; mi++)
            #pragma unroll
            for (int nj = 0; nj < 4; nj++)
                #pragma unroll
                for (int q = 0; q < 4; q++) acc[mi][nj][q] = 0.0f;

        // ---- GEMM2: K=128 ----
        #pragma unroll
        for (int ks = 0; ks < 8; ks++) {
            const int kb = ks * 16 + lk;
            uint32_t Ah[2][4];
            #pragma unroll
            for (int mi = 0; mi < 2; mi++)
                ldsm4(Ah[mi], base32 + SO_A2 + off2(m0w + mi * 16 + lr, kb));
            #pragma unroll
            for (int nt = 0; nt < 2; nt++) {
                uint32_t Bh[4];
                ldsm4(Bh, base32 + SO_B2 + off2(n0w + nt * 16 + lr, kb));
                #pragma unroll
                for (int h = 0; h < 2; h++) {
                    const int nj = nt * 2 + h;
                    #pragma unroll
                    for (int mi = 0; mi < 2; mi++)
                        mma16816(acc[mi][nj], Ah[mi], Bh[h], Bh[2 + h]);
                }
            }
        }

        // ---- epilogue2: permuted channels -> red.v4 ----
        {
            const int q4 = (lane & 3) << 2;
            const int rbase = m0w + (lane >> 2);
            const int j4 = m0w >> 5;                  // warp-uniform (32-row groups)
            const float* pv = &sx1p[j4 * 128];
            const float* qv = &sx1q[j4 * 128];
            #pragma unroll
            for (int mi = 0; mi < 2; mi++)
                #pragma unroll
                for (int half = 0; half < 2; half++) {
                    const int row = rbase + mi * 16 + half * 8;
                    const float cv = scv[row];
                    const int   dst = sdst[row];
                    float* aggp = &g_agg[dst * 128];
                    #pragma unroll
                    for (int pj = 0; pj < 2; pj++) {
                        const int pb = n0w + (pj << 4) + q4;
                        const float4 pvv = *(const float4*)&pv[pb];
                        const float4 qvv = *(const float4*)&qv[pb];
                        const float m0 = cv * fmaf(acc[mi][2*pj    ][half * 2],     pvv.x, qvv.x);
                        const float m1 = cv * fmaf(acc[mi][2*pj    ][half * 2 + 1], pvv.y, qvv.y);
                        const float m2 = cv * fmaf(acc[mi][2*pj + 1][half * 2],     pvv.z, qvv.z);
                        const float m3 = cv * fmaf(acc[mi][2*pj + 1][half * 2 + 1], pvv.w, qvv.w);
                        red_add_v4(aggp + pb, m0, m1, m2, m3);
                    }
                }
        }
        // A2 WAR across tiles protected by the tile-start full __syncthreads.
    }
}

// ---------------- output head + per-graph sum ----------------
#define OUT_SMEM_FLOATS (128*128 + 128*65)

__global__ void out_kernel(const float* __restrict__ ow1, const float* __restrict__ ob1,
                           const float* __restrict__ ow2, const float* __restrict__ ob2,
                           float* __restrict__ out)
{
    extern __shared__ float sm[];
    float* sh = sm;
    float* st = sh + 128*128;
    __shared__ float rsum[256];

    const int g    = blockIdx.x;
    const int tid  = threadIdx.x;
    const int base = g * ATOMS;

    for (int idx = tid; idx < 128 * 128; idx += 256)
        sh[idx] = g_h[base * 128 + idx];
    __syncthreads();

    const int d   = tid & 63;
    const int grp = tid >> 6;
    float acc[32];
    #pragma unroll
    for (int e = 0; e < 32; e++) acc[e] = 0.0f;
    const float* hh = sh + grp * 32 * 128;
    #pragma unroll 2
    for (int k = 0; k < 128; k++) {
        const float w = ow1[k * 64 + d];
        #pragma unroll
        for (int e = 0; e < 32; e++) acc[e] += hh[e * 128 + k] * w;
    }
    const float bb = ob1[d];
    #pragma unroll
    for (int e = 0; e < 32; e++) {
        const float v = acc[e] + bb;
        st[(grp * 32 + e) * 65 + d] = silu_f(v);
    }
    __syncthreads();

    float o = 0.0f;
    if (tid < 128) {
        float s = ob2[0];
        #pragma unroll 4
        for (int dd = 0; dd < 64; dd++) s += st[tid * 65 + dd] * ow2[dd];
        o = s;
    }
    rsum[tid] = o;
    __syncthreads();
    for (int s = 128; s >= 1; s >>= 1) {
        if (tid < s) rsum[tid] += rsum[tid + s];
        __syncthreads();
    }
    if (tid == 0) out[g] = rsum[0];
}

// ---------------- launch ----------------
extern "C" void kernel_launch(void* const* d_in, const int* in_sizes, int n_in,
                              void* d_out, int out_size)
{
    const float* pos   = (const float*)d_in[0];
    const int*   z     = (const int*)  d_in[1];
    const int*   batch = (const int*)  d_in[2];
    const float* emb   = (const float*)d_in[3];
    const float* mw1   = (const float*)d_in[4];
    const float* mb1   = (const float*)d_in[5];
    const float* mw2   = (const float*)d_in[6];
    const float* mb2   = (const float*)d_in[7];
    const float* l1w   = (const float*)d_in[8];
    const float* l1b   = (const float*)d_in[9];
    const float* l2w   = (const float*)d_in[10];
    const float* l2b   = (const float*)d_in[11];
    const float* ow1   = (const float*)d_in[12];
    const float* ob1   = (const float*)d_in[13];
    const float* ow2   = (const float*)d_in[14];
    const float* ob2   = (const float*)d_in[15];
    float* out = (float*)d_out;

    float *hp, *x1p, *aggp;
    cudaGetSymbolAddress((void**)&hp,   g_h);
    cudaGetSymbolAddress((void**)&x1p,  g_x1);
    cudaGetSymbolAddress((void**)&aggp, g_agg);
    unsigned char *w1h, *w2h, *l1i, *l2i;
    cudaGetSymbolAddress((void**)&w1h, g_w1_hi);
    cudaGetSymbolAddress((void**)&w2h, g_w2_hi);
    cudaGetSymbolAddress((void**)&l1i, g_l1img);
    cudaGetSymbolAddress((void**)&l2i, g_l2img);

    cudaFuncSetAttribute(filter_mma_kernel, cudaFuncAttributeMaxDynamicSharedMemorySize,
                         FILT_SMEM_BYTES);
    cudaFuncSetAttribute(linear_mma_kernel, cudaFuncAttributeMaxDynamicSharedMemorySize,
                         LIN_SMEM_BYTES);
    cudaFuncSetAttribute(fused_linear_kernel, cudaFuncAttributeMaxDynamicSharedMemorySize,
                         FL_SMEM_BYTES);
    cudaFuncSetAttribute(out_kernel, cudaFuncAttributeMaxDynamicSharedMemorySize,
                         OUT_SMEM_FLOATS * (int)sizeof(float));

    build_graph_kernel<<<NTOT / 4, 128>>>(pos, batch);
    prep_all_kernel<<<(PREP_TOTAL + 255) / 256, 256>>>(mw1, mb1, mw2, l1w, l2w, z, emb);

    linear_mma_kernel<<<NTOT / 64, 512, LIN_SMEM_BYTES>>>(
        hp, l1i, l1b, x1p, 0);

    for (int l = 0; l < LAYERS; l++) {
        filter_mma_kernel<<<148, 512, FILT_SMEM_BYTES>>>(
            mb2 + l * FIL,
            w1h + l * 16384, w2h + l * 32768);
        if (l < LAYERS - 1) {
            fused_linear_kernel<<<NTOT / 64, 512, FL_SMEM_BYTES>>>(
                l2i + l * 32768, l2b + l * HID,
                l1i + (l + 1) * 32768, l1b + (l + 1) * FIL);
        } else {
            linear_mma_kernel<<<NTOT / 64, 512, LIN_SMEM_BYTES>>>(
                aggp, l2i + l * 32768, l2b + l * HID, hp, 1);
        }
    }

    out_kernel<<<NUM_G, 256, OUT_SMEM_FLOATS * sizeof(float)>>>(ow1, ob1, ow2, ob2, out);
}

// round 14
// speedup vs baseline: 3.2918x; 1.0335x over previous
#include <cuda_runtime.h>
#include <cuda_bf16.h>
#include <math.h>
#include <stdint.h>

// ---------------- problem constants ----------------
#define NG        50
#define KNB       32
#define NUM_G     64
#define ATOMS     128
#define NTOT      (NUM_G * ATOMS)     // 8192
#define HID       128
#define FIL       128
#define LAYERS    6
#define EDGES     (NTOT * KNB)        // 262144
#define NTILES    (EDGES / 128)       // 2048
#define CUTOFF    10.0f
#define PI_C      3.14159265f

#define INVALID_KEY 0xFFFFFFFFFFFFFFFFULL
typedef unsigned long long ull;

// ---------------- device scratch ----------------
__device__ int   g_idx [EDGES];
__device__ float g_dist[EDGES];
__device__ float g_cval[EDGES];
__device__ float g_h   [NTOT * HID];
__device__ float g_x1  [NTOT * FIL];
__device__ float g_x1q [NTOT * FIL];     // x1 * b2 (next filter layer), precomputed
__device__ float g_agg [NTOT * FIL];

// ldmatrix-layout bf16 tile images
__device__ unsigned char g_rbf_hi[NTILES * 16384];   // per tile: [128 e][64 k], k=50 column = 1.0
__device__ unsigned char g_w1_hi [LAYERS * 16384];   // [128 n][64 k], k=50 row = b1
__device__ unsigned char g_w2_hi [LAYERS * 32768];   // [128 n][128 k], n-permuted
__device__ unsigned char g_l1img [LAYERS * 32768];   // [128 n][128 k]
__device__ unsigned char g_l2img [LAYERS * 32768];   // [128 n][128 k]

// fast silu
__device__ __forceinline__ float silu_f(float v) {
    float e;
    asm("ex2.approx.f32 %0, %1;" : "=f"(e) : "f"(-1.442695041f * v));
    float r;
    asm("rcp.approx.f32 %0, %1;" : "=f"(r) : "f"(1.0f + e));
    return v * r;
}

__device__ __forceinline__ void red_add_v4(float* p, float a, float b, float c, float d) {
    asm volatile("red.global.add.v4.f32 [%0], {%1,%2,%3,%4};"
                 :: "l"(p), "f"(a), "f"(b), "f"(c), "f"(d) : "memory");
}

__device__ __forceinline__ uint32_t smem_u32(const void* p) {
    uint32_t a;
    asm("{ .reg .u64 t; cvta.to.shared.u64 t, %1; cvt.u32.u64 %0, t; }" : "=r"(a) : "l"(p));
    return a;
}

// ---------------- cp.async helpers ----------------
__device__ __forceinline__ void cp_async16(uint32_t saddr, const void* gaddr) {
    asm volatile("cp.async.cg.shared.global [%0], [%1], 16;" :: "r"(saddr), "l"(gaddr));
}
#define CP_COMMIT() asm volatile("cp.async.commit_group;" ::: "memory")
#define CP_WAIT0()  asm volatile("cp.async.wait_group 0;" ::: "memory")

// ---------------- mma.sync / ldmatrix helpers ----------------
__device__ __forceinline__ void ldsm4(uint32_t* r, uint32_t addr) {
    asm volatile("ldmatrix.sync.aligned.m8n8.x4.shared.b16 {%0,%1,%2,%3}, [%4];"
                 : "=r"(r[0]), "=r"(r[1]), "=r"(r[2]), "=r"(r[3]) : "r"(addr));
}
__device__ __forceinline__ void mma16816(float* c, const uint32_t* a, uint32_t b0, uint32_t b1) {
    asm volatile("mma.sync.aligned.m16n8k16.row.col.f32.bf16.bf16.f32 "
                 "{%0,%1,%2,%3}, {%4,%5,%6,%7}, {%8,%9}, {%0,%1,%2,%3};"
                 : "+f"(c[0]), "+f"(c[1]), "+f"(c[2]), "+f"(c[3])
                 : "r"(a[0]), "r"(a[1]), "r"(a[2]), "r"(a[3]), "r"(b0), "r"(b1));
}

// swizzled byte offsets
__device__ __forceinline__ uint32_t off1(int r, int k) {
    return (uint32_t)(r * 128 + (((k >> 3) ^ (r & 7)) << 4) + (k & 7) * 2);
}
__device__ __forceinline__ uint32_t off2(int r, int k) {
    return (uint32_t)(r * 256 + (((k >> 3) ^ (r & 7)) << 4) + (k & 7) * 2);
}
__device__ __forceinline__ int perm_n(int n) {
    const int a = n >> 3, q = (n >> 1) & 3, h = n & 1;
    return ((a >> 1) << 4) + (q << 2) + ((a & 1) << 1) + h;
}

__device__ __forceinline__ uint32_t packbf2(float a, float b) {
    return (uint32_t)__bfloat16_as_ushort(__float2bfloat16(a)) |
           ((uint32_t)__bfloat16_as_ushort(__float2bfloat16(b)) << 16);
}

// ---------------- graph build ----------------
__global__ void build_graph_kernel(const float* __restrict__ pos,
                                   const int* __restrict__ batch)
{
    const int wid  = threadIdx.x >> 5;
    const int lane = threadIdx.x & 31;
    const int i    = blockIdx.x * 4 + wid;
    const int base = (i >> 7) << 7;

    const float px = pos[3*i], py = pos[3*i+1], pz = pos[3*i+2];

    ull key[4];
    #pragma unroll
    for (int c = 0; c < 4; c++) {
        const int j = base + c * 32 + lane;
        const float dx = pos[3*j]   - px;
        const float dy = pos[3*j+1] - py;
        const float dz = pos[3*j+2] - pz;
        const float d2 = dx*dx + dy*dy + dz*dz;
        key[c] = (j != i && d2 < CUTOFF*CUTOFF)
            ? ((((ull)__float_as_uint(d2)) << 32) | (unsigned int)j)
            : INVALID_KEY;
    }

    for (int k = 0; k < KNB; k++) {
        ull m0 = key[0] < key[1] ? key[0] : key[1];
        ull m1 = key[2] < key[3] ? key[2] : key[3];
        ull m  = m0 < m1 ? m0 : m1;
        #pragma unroll
        for (int s = 16; s >= 1; s >>= 1) {
            ull o = __shfl_xor_sync(0xffffffffu, m, s);
            if (o < m) m = o;
        }
        #pragma unroll
        for (int c = 0; c < 4; c++)
            if (key[c] == m) key[c] = INVALID_KEY;
        if (lane == k) {
            const int eo = i * KNB + k;
            if (m != INVALID_KEY) {
                const int   jj = (int)(m & 0xffffffffu);
                const float d  = sqrtf(__uint_as_float((unsigned int)(m >> 32)));
                g_idx[eo]  = jj;
                g_dist[eo] = d;
                const float cv = 0.5f * (cosf(d * (PI_C / CUTOFF)) + 1.0f);
                g_cval[eo] = (d < CUTOFF) ? cv : 0.0f;
            } else {
                g_idx[eo]  = i;
                g_dist[eo] = 1.0f;
                g_cval[eo] = 0.0f;
            }
        }
    }
}

// ---------------- fused prep ----------------
#define PREP_RBF   (EDGES * 64)
#define PREP_W1    (LAYERS * 128 * 64)
#define PREP_W2    (LAYERS * 128 * 128)
#define PREP_L1    (LAYERS * 128 * 128)
#define PREP_L2    (LAYERS * 128 * 128)
#define PREP_EMB   (NTOT * HID)
#define PREP_TOTAL (PREP_RBF + PREP_W1 + PREP_W2 + PREP_L1 + PREP_L2 + PREP_EMB)

__global__ void prep_all_kernel(const float* __restrict__ mw1,
                                const float* __restrict__ mb1,
                                const float* __restrict__ mw2,
                                const float* __restrict__ l1w,
                                const float* __restrict__ l2w,
                                const int* __restrict__ z,
                                const float* __restrict__ emb)
{
    const int id = blockIdx.x * blockDim.x + threadIdx.x;
    if (id < PREP_RBF) {
        const int e = id >> 6;
        const int k = id & 63;
        const int tile = e >> 7;
        const int r    = e & 127;
        float val;
        if (k < NG) {
            const float w = CUTOFF / (float)(NG - 1);
            const float t = (g_dist[e] - (float)k * w) / w;
            val = expf(-0.5f * t * t);
        } else {
            val = (k == NG) ? 1.0f : 0.0f;
        }
        const uint32_t o = (uint32_t)tile * 16384u + off1(r, k);
        *(unsigned short*)(g_rbf_hi + o) = __bfloat16_as_ushort(__float2bfloat16(val));
    } else if (id < PREP_RBF + PREP_W1) {
        const int t = id - PREP_RBF;
        const int l = t >> 13;
        const int n = (t >> 6) & 127;
        const int k = t & 63;
        float val;
        if (k < NG)       val = mw1[l * NG * FIL + k * FIL + n];
        else if (k == NG) val = mb1[l * FIL + n];
        else              val = 0.0f;
        const uint32_t o = (uint32_t)l * 16384u + off1(n, k);
        *(unsigned short*)(g_w1_hi + o) = __bfloat16_as_ushort(__float2bfloat16(val));
    } else if (id < PREP_RBF + PREP_W1 + PREP_W2) {
        const int t = id - PREP_RBF - PREP_W1;
        const int l = t >> 14;
        const int n = (t >> 7) & 127;
        const int k = t & 127;
        const float val = mw2[l * FIL * FIL + k * FIL + perm_n(n)];
        const uint32_t o = (uint32_t)l * 32768u + off2(n, k);
        *(unsigned short*)(g_w2_hi + o) = __bfloat16_as_ushort(__float2bfloat16(val));
    } else if (id < PREP_RBF + PREP_W1 + PREP_W2 + PREP_L1) {
        const int t = id - PREP_RBF - PREP_W1 - PREP_W2;
        const int l = t >> 14;
        const int n = (t >> 7) & 127;
        const int k = t & 127;
        const float val = l1w[l * HID * FIL + k * FIL + n];
        const uint32_t o = (uint32_t)l * 32768u + off2(n, k);
        *(unsigned short*)(g_l1img + o) = __bfloat16_as_ushort(__float2bfloat16(val));
    } else if (id < PREP_RBF + PREP_W1 + PREP_W2 + PREP_L1 + PREP_L2) {
        const int t = id - PREP_RBF - PREP_W1 - PREP_W2 - PREP_L1;
        const int l = t >> 14;
        const int n = (t >> 7) & 127;
        const int k = t & 127;
        const float val = l2w[l * FIL * HID + k * HID + n];
        const uint32_t o = (uint32_t)l * 32768u + off2(n, k);
        *(unsigned short*)(g_l2img + o) = __bfloat16_as_ushort(__float2bfloat16(val));
    } else if (id < PREP_TOTAL) {
        const int t = id - PREP_RBF - PREP_W1 - PREP_W2 - PREP_L1 - PREP_L2;
        const int n = t >> 7;
        const int c = t & 127;
        g_h[t] = emb[z[n] * HID + c];
    }
}

// ---------------- node linear via mma.sync (512 thr, 64-row tile, single-term) ----------
// mode 0: y = x@W + b; g_x1q = y*b2f; zero g_agg rows.  mode 1: y += silu(x@W + b).
#define LIN_A    0
#define LIN_W    16384
#define LIN_B    49152
#define LIN_SMEM_BYTES (49152 + 512)

__global__ void __launch_bounds__(512, 1)
linear_mma_kernel(const float* __restrict__ x,
                  const unsigned char* __restrict__ wimg,
                  const float* __restrict__ b,
                  const float* __restrict__ b2f,
                  float* __restrict__ y,
                  int mode)
{
    extern __shared__ unsigned char base[];
    const uint32_t base32 = smem_u32(base);

    const int tid  = threadIdx.x;
    const int lane = tid & 31;
    const int wid  = tid >> 5;
    const int m0w  = (wid & 3) * 16;
    const int n0w  = (wid >> 2) * 32;
    const int r0   = blockIdx.x * 64;

    {
        const uint4* sw = (const uint4*)wimg;
        uint4* dw = (uint4*)(base + LIN_W);
        for (int i = tid; i < 2048; i += 512) dw[i] = sw[i];
        float* sb = (float*)(base + LIN_B);
        if (tid < 128) sb[tid] = b[tid];
    }

    {
        const int r  = tid >> 3;
        const int k0 = (tid & 7) * 16;
        const float4* xp = (const float4*)(x + (r0 + r) * 128 + k0);
        float4 v0 = xp[0], v1 = xp[1], v2 = xp[2], v3 = xp[3];
        float vv[16];
        *(float4*)&vv[0]  = v0; *(float4*)&vv[4]  = v1;
        *(float4*)&vv[8]  = v2; *(float4*)&vv[12] = v3;
        #pragma unroll
        for (int g = 0; g < 2; g++) {
            uint4 hi;
            uint32_t* hp = (uint32_t*)&hi;
            #pragma unroll
            for (int j = 0; j < 4; j++)
                hp[j] = packbf2(vv[g*8 + 2*j], vv[g*8 + 2*j + 1]);
            *(uint4*)(base + LIN_A + off2(r, k0 + g * 8)) = hi;
        }
    }
    __syncthreads();

    const int lr = lane & 15;
    const int lk = (lane >> 4) * 8;

    float acc[4][4];
    #pragma unroll
    for (int nj = 0; nj < 4; nj++)
        #pragma unroll
        for (int q = 0; q < 4; q++) acc[nj][q] = 0.0f;

    #pragma unroll
    for (int ks = 0; ks < 8; ks++) {
        const int kb = ks * 16 + lk;
        uint32_t Ah[4];
        ldsm4(Ah, base32 + LIN_A + off2(m0w + lr, kb));
        #pragma unroll
        for (int nt = 0; nt < 2; nt++) {
            uint32_t Bh[4];
            ldsm4(Bh, base32 + LIN_W + off2(n0w + nt * 16 + lr, kb));
            #pragma unroll
            for (int h = 0; h < 2; h++)
                mma16816(acc[nt * 2 + h], Ah, Bh[h], Bh[2 + h]);
        }
    }

    {
        float* sb = (float*)(base + LIN_B);
        const int rbase = m0w + (lane >> 2);
        const int cbase = n0w + (lane & 3) * 2;
        #pragma unroll
        for (int nj = 0; nj < 4; nj++) {
            const int col = cbase + nj * 8;
            const float bb0 = sb[col], bb1 = sb[col + 1];
            #pragma unroll
            for (int half = 0; half < 2; half++) {
                const int row = r0 + rbase + half * 8;
                const float v0 = acc[nj][half * 2]     + bb0;
                const float v1 = acc[nj][half * 2 + 1] + bb1;
                float2* yp = (float2*)(y + row * 128 + col);
                if (mode == 0) {
                    float2 v; v.x = v0; v.y = v1;
                    *yp = v;
                    float2 q; q.x = v0 * b2f[col]; q.y = v1 * b2f[col + 1];
                    *(float2*)(g_x1q + row * 128 + col) = q;
                } else {
                    float2 v = *yp;
                    v.x += silu_f(v0);
                    v.y += silu_f(v1);
                    *yp = v;
                }
            }
        }
    }
    if (mode == 0) {
        const int r  = r0 + (tid >> 3);
        const int k0 = (tid & 7) * 16;
        float4 zz; zz.x = zz.y = zz.z = zz.w = 0.0f;
        float4* ap = (float4*)(g_agg + r * 128 + k0);
        ap[0] = zz; ap[1] = zz; ap[2] = zz; ap[3] = zz;
    }
}

// ---------------- fused linear pair (single-term) ----------------
// h += silu(agg@W2+b2); x1 = h@W1+b1; x1q = x1*b2next; zero agg
#define FL_A    0
#define FL_W2   16384
#define FL_W1   49152
#define FL_B2   81920
#define FL_B1   82432
#define FL_SMEM_BYTES 82944

__global__ void __launch_bounds__(512, 1)
fused_linear_kernel(const unsigned char* __restrict__ w2img, const float* __restrict__ b2,
                    const unsigned char* __restrict__ w1img, const float* __restrict__ b1,
                    const float* __restrict__ b2next)
{
    extern __shared__ unsigned char base[];
    const uint32_t base32 = smem_u32(base);

    const int tid  = threadIdx.x;
    const int lane = tid & 31;
    const int wid  = tid >> 5;
    const int m0w  = (wid & 3) * 16;
    const int n0w  = (wid >> 2) * 32;
    const int r0   = blockIdx.x * 64;

    {
        const uint4* s2 = (const uint4*)w2img;
        const uint4* s1 = (const uint4*)w1img;
        uint4* d2 = (uint4*)(base + FL_W2);
        uint4* d1 = (uint4*)(base + FL_W1);
        for (int i = tid; i < 2048; i += 512) { d2[i] = s2[i]; d1[i] = s1[i]; }
        float* sb2 = (float*)(base + FL_B2);
        float* sb1 = (float*)(base + FL_B1);
        if (tid < 128) { sb2[tid] = b2[tid]; sb1[tid] = b1[tid]; }
    }

    {
        const int r  = tid >> 3;
        const int k0 = (tid & 7) * 16;
        const float4* xp = (const float4*)(g_agg + (r0 + r) * 128 + k0);
        float4 v0 = xp[0], v1 = xp[1], v2 = xp[2], v3 = xp[3];
        float vv[16];
        *(float4*)&vv[0]  = v0; *(float4*)&vv[4]  = v1;
        *(float4*)&vv[8]  = v2; *(float4*)&vv[12] = v3;
        #pragma unroll
        for (int g = 0; g < 2; g++) {
            uint4 hi;
            uint32_t* hp = (uint32_t*)&hi;
            #pragma unroll
            for (int j = 0; j < 4; j++)
                hp[j] = packbf2(vv[g*8 + 2*j], vv[g*8 + 2*j + 1]);
            *(uint4*)(base + FL_A + off2(r, k0 + g * 8)) = hi;
        }
    }
    __syncthreads();

    const int lr = lane & 15;
    const int lk = (lane >> 4) * 8;

    float acc[4][4];
    #pragma unroll
    for (int nj = 0; nj < 4; nj++)
        #pragma unroll
        for (int q = 0; q < 4; q++) acc[nj][q] = 0.0f;

    // GEMM A: agg @ W2
    #pragma unroll
    for (int ks = 0; ks < 8; ks++) {
        const int kb = ks * 16 + lk;
        uint32_t Ah[4];
        ldsm4(Ah, base32 + FL_A + off2(m0w + lr, kb));
        #pragma unroll
        for (int nt = 0; nt < 2; nt++) {
            uint32_t Bh[4];
            ldsm4(Bh, base32 + FL_W2 + off2(n0w + nt * 16 + lr, kb));
            #pragma unroll
            for (int h = 0; h < 2; h++)
                mma16816(acc[nt * 2 + h], Ah, Bh[h], Bh[2 + h]);
        }
    }
    __syncthreads();

    // epilogue A: h_new = h_old + silu(acc + b2); restage bf16
    {
        float* sb2 = (float*)(base + FL_B2);
        const int rbase = m0w + (lane >> 2);
        const int cbase = n0w + (lane & 3) * 2;
        #pragma unroll
        for (int nj = 0; nj < 4; nj++) {
            const int col = cbase + nj * 8;
            const float bb0 = sb2[col], bb1 = sb2[col + 1];
            #pragma unroll
            for (int half = 0; half < 2; half++) {
                const int rloc = rbase + half * 8;
                const int row  = r0 + rloc;
                float2* hptr = (float2*)(g_h + row * 128 + col);
                float2 hv = *hptr;
                const float v0 = hv.x + silu_f(acc[nj][half * 2]     + bb0);
                const float v1 = hv.y + silu_f(acc[nj][half * 2 + 1] + bb1);
                float2 nv; nv.x = v0; nv.y = v1;
                *hptr = nv;
                *(uint32_t*)(base + FL_A + off2(rloc, col)) = packbf2(v0, v1);
            }
        }
    }
    __syncthreads();

    #pragma unroll
    for (int nj = 0; nj < 4; nj++)
        #pragma unroll
        for (int q = 0; q < 4; q++) acc[nj][q] = 0.0f;

    // GEMM B: h_new @ W1
    #pragma unroll
    for (int ks = 0; ks < 8; ks++) {
        const int kb = ks * 16 + lk;
        uint32_t Ah[4];
        ldsm4(Ah, base32 + FL_A + off2(m0w + lr, kb));
        #pragma unroll
        for (int nt = 0; nt < 2; nt++) {
            uint32_t Bh[4];
            ldsm4(Bh, base32 + FL_W1 + off2(n0w + nt * 16 + lr, kb));
            #pragma unroll
            for (int h = 0; h < 2; h++)
                mma16816(acc[nt * 2 + h], Ah, Bh[h], Bh[2 + h]);
        }
    }

    // epilogue B: x1 = acc + b1; x1q = x1*b2next; zero agg rows
    {
        float* sb1 = (float*)(base + FL_B1);
        const int rbase = m0w + (lane >> 2);
        const int cbase = n0w + (lane & 3) * 2;
        #pragma unroll
        for (int nj = 0; nj < 4; nj++) {
            const int col = cbase + nj * 8;
            const float bb0 = sb1[col], bb1 = sb1[col + 1];
            const float q0 = b2next[col], q1 = b2next[col + 1];
            #pragma unroll
            for (int half = 0; half < 2; half++) {
                const int row = r0 + rbase + half * 8;
                const float v0 = acc[nj][half * 2]     + bb0;
                const float v1 = acc[nj][half * 2 + 1] + bb1;
                float2 v; v.x = v0; v.y = v1;
                *(float2*)(g_x1 + row * 128 + col) = v;
                float2 q; q.x = v0 * q0; q.y = v1 * q1;
                *(float2*)(g_x1q + row * 128 + col) = q;
            }
        }
    }
    {
        const int r  = r0 + (tid >> 3);
        const int k0 = (tid & 7) * 16;
        float4 zz; zz.x = zz.y = zz.z = zz.w = 0.0f;
        float4* ap = (float4*)(g_agg + r * 128 + k0);
        ap[0] = zz; ap[1] = zz; ap[2] = zz; ap[3] = zz;
    }
}

// ---------------- tensor-core filter kernel, 512 threads ----------------
#define SO_A1   0                 // 2 x 16384 (parity)
#define SO_A2   32768             // 32768
#define SO_B1   65536             // 16384
#define SO_B2   81920             // 32768
#define SO_AUX  114688            // 2 x 5120 (parity)
#define AUXB_X1P 0
#define AUXB_X1Q 2048
#define AUXB_CV  4096
#define AUXB_DST 4608
#define FILT_SMEM_BYTES (SO_AUX + 10240)

__device__ __forceinline__ void filt_prefetch(uint32_t base32, int tile, int par, int tid)
{
    if (tile >= NTILES) return;
    const size_t tb = (size_t)tile * 16384;
    for (int i = tid; i < 1024; i += 512)
        cp_async16(base32 + SO_A1 + par * 16384 + i * 16, g_rbf_hi + tb + i * 16);
    const uint32_t auxb = base32 + SO_AUX + par * 5120;
    if (tid < 128) {
        cp_async16(auxb + AUXB_X1P + tid * 16,
                   (const unsigned char*)g_x1  + (size_t)tile * 2048 + tid * 16);
        cp_async16(auxb + AUXB_X1Q + tid * 16,
                   (const unsigned char*)g_x1q + (size_t)tile * 2048 + tid * 16);
    } else if (tid < 160) {
        const int j = tid - 128;
        cp_async16(auxb + AUXB_CV + j * 16,
                   (const unsigned char*)g_cval + (size_t)tile * 512 + j * 16);
    } else if (tid < 192) {
        const int j = tid - 160;
        cp_async16(auxb + AUXB_DST + j * 16,
                   (const unsigned char*)g_idx + (size_t)tile * 512 + j * 16);
    }
}

__global__ void __launch_bounds__(512, 1)
filter_mma_kernel(const unsigned char* __restrict__ w1hi,
                  const unsigned char* __restrict__ w2hi)
{
    extern __shared__ unsigned char base[];
    const uint32_t base32 = smem_u32(base);

    const int tid  = threadIdx.x;
    const int lane = tid & 31;
    const int wid  = tid >> 5;
    const int wm   = wid & 3;          // warp m-tile: 32 edges
    const int wn   = wid >> 2;         // warp n-tile: 32 channels
    const int m0w  = wm * 32;
    const int n0w  = wn * 32;

    // resident weight copies
    {
        const uint4* s1h = (const uint4*)w1hi;
        const uint4* s2h = (const uint4*)w2hi;
        uint4* d1h = (uint4*)(base + SO_B1);
        uint4* d2h = (uint4*)(base + SO_B2);
        for (int i = tid; i < 1024; i += 512) d1h[i] = s1h[i];
        for (int i = tid; i < 2048; i += 512) d2h[i] = s2h[i];
    }

    // prefetch first tile (A1 + aux) into parity 0
    filt_prefetch(base32, blockIdx.x, 0, tid);
    CP_COMMIT();

    const int lr = lane & 15;
    const int lk = (lane >> 4) * 8;

    __syncthreads();    // weights visible

    // B1 fragments register-resident (tile-invariant)
    uint32_t B1r[4][2][4];
    #pragma unroll
    for (int ks = 0; ks < 4; ks++) {
        const int kb = ks * 16 + lk;
        #pragma unroll
        for (int nt = 0; nt < 2; nt++)
            ldsm4(B1r[ks][nt], base32 + SO_B1 + off1(n0w + nt * 16 + lr, kb));
    }

    int par = 0;
    for (int tile = blockIdx.x; tile < NTILES; tile += gridDim.x, par ^= 1) {
        unsigned char* aux = base + SO_AUX + par * 5120;
        float* sx1p = (float*)(aux + AUXB_X1P);
        float* sx1q = (float*)(aux + AUXB_X1Q);
        float* scv  = (float*)(aux + AUXB_CV);
        int*   sdst = (int*)  (aux + AUXB_DST);

        CP_WAIT0();
        __syncthreads();

        // prefetch next tile into other parity (overlaps both GEMMs)
        filt_prefetch(base32, tile + gridDim.x, par ^ 1, tid);
        CP_COMMIT();

        float acc[2][4][4];
        #pragma unroll
        for (int mi = 0; mi < 2; mi++)
            #pragma unroll
            for (int nj = 0; nj < 4; nj++)
                #pragma unroll
                for (int q = 0; q < 4; q++) acc[mi][nj][q] = 0.0f;

        // ---- GEMM1: K=64 (bias folded), B from registers ----
        const uint32_t a1b = base32 + SO_A1 + par * 16384;
        #pragma unroll
        for (int ks = 0; ks < 4; ks++) {
            const int kb = ks * 16 + lk;
            uint32_t Ah[2][4];
            #pragma unroll
            for (int mi = 0; mi < 2; mi++)
                ldsm4(Ah[mi], a1b + off1(m0w + mi * 16 + lr, kb));
            #pragma unroll
            for (int nt = 0; nt < 2; nt++)
                #pragma unroll
                for (int h = 0; h < 2; h++) {
                    const int nj = nt * 2 + h;
                    #pragma unroll
                    for (int mi = 0; mi < 2; mi++)
                        mma16816(acc[mi][nj], Ah[mi], B1r[ks][nt][h], B1r[ks][nt][2 + h]);
                }
        }

        // ---- epilogue1: silu -> bf16 -> A2 ----
        {
            unsigned char* a2h = base + SO_A2;
            const int rbase = m0w + (lane >> 2);
            const int cbase = n0w + (lane & 3) * 2;
            #pragma unroll
            for (int mi = 0; mi < 2; mi++)
                #pragma unroll
                for (int nj = 0; nj < 4; nj++) {
                    const int col = cbase + nj * 8;
                    #pragma unroll
                    for (int half = 0; half < 2; half++) {
                        const int row = rbase + mi * 16 + half * 8;
                        const float s0 = silu_f(acc[mi][nj][half * 2]);
                        const float s1 = silu_f(acc[mi][nj][half * 2 + 1]);
                        *(uint32_t*)(a2h + off2(row, col)) = packbf2(s0, s1);
                    }
                }
        }
        asm volatile("bar.sync %0, %1;" :: "r"(1 + wm), "r"(128) : "memory");

        #pragma unroll
        for (int mi = 0; mi < 2; mi++)
            #pragma unroll
            for (int nj = 0; nj < 4; nj++)
                #pragma unroll
                for (int q = 0; q < 4; q++) acc[mi][nj][q] = 0.0f;

        // ---- GEMM2: K=128 ----
        #pragma unroll
        for (int ks = 0; ks < 8; ks++) {
            const int kb = ks * 16 + lk;
            uint32_t Ah[2][4];
            #pragma unroll
            for (int mi = 0; mi < 2; mi++)
                ldsm4(Ah[mi], base32 + SO_A2 + off2(m0w + mi * 16 + lr, kb));
            #pragma unroll
            for (int nt = 0; nt < 2; nt++) {
                uint32_t Bh[4];
                ldsm4(Bh, base32 + SO_B2 + off2(n0w + nt * 16 + lr, kb));
                #pragma unroll
                for (int h = 0; h < 2; h++) {
                    const int nj = nt * 2 + h;
                    #pragma unroll
                    for (int mi = 0; mi < 2; mi++)
                        mma16816(acc[mi][nj], Ah[mi], Bh[h], Bh[2 + h]);
                }
            }
        }

        // ---- epilogue2: permuted channels -> red.v4 ----
        {
            const int q4 = (lane & 3) << 2;
            const int rbase = m0w + (lane >> 2);
            const int j4 = m0w >> 5;
            const float* pv = &sx1p[j4 * 128];
            const float* qv = &sx1q[j4 * 128];
            #pragma unroll
            for (int mi = 0; mi < 2; mi++)
                #pragma unroll
                for (int half = 0; half < 2; half++) {
                    const int row = rbase + mi * 16 + half * 8;
                    const float cv = scv[row];
                    const int   dst = sdst[row];
                    float* aggp = &g_agg[dst * 128];
                    #pragma unroll
                    for (int pj = 0; pj < 2; pj++) {
                        const int pb = n0w + (pj << 4) + q4;
                        const float4 pvv = *(const float4*)&pv[pb];
                        const float4 qvv = *(const float4*)&qv[pb];
                        const float m0 = cv * fmaf(acc[mi][2*pj    ][half * 2],     pvv.x, qvv.x);
                        const float m1 = cv * fmaf(acc[mi][2*pj    ][half * 2 + 1], pvv.y, qvv.y);
                        const float m2 = cv * fmaf(acc[mi][2*pj + 1][half * 2],     pvv.z, qvv.z);
                        const float m3 = cv * fmaf(acc[mi][2*pj + 1][half * 2 + 1], pvv.w, qvv.w);
                        red_add_v4(aggp + pb, m0, m1, m2, m3);
                    }
                }
        }
    }
}

// ---------------- output head + per-graph sum ----------------
#define OUT_SMEM_FLOATS (128*128 + 128*65)

__global__ void out_kernel(const float* __restrict__ ow1, const float* __restrict__ ob1,
                           const float* __restrict__ ow2, const float* __restrict__ ob2,
                           float* __restrict__ out)
{
    extern __shared__ float sm[];
    float* sh = sm;
    float* st = sh + 128*128;
    __shared__ float rsum[256];

    const int g    = blockIdx.x;
    const int tid  = threadIdx.x;
    const int base = g * ATOMS;

    for (int idx = tid; idx < 128 * 128; idx += 256)
        sh[idx] = g_h[base * 128 + idx];
    __syncthreads();

    const int d   = tid & 63;
    const int grp = tid >> 6;
    float acc[32];
    #pragma unroll
    for (int e = 0; e < 32; e++) acc[e] = 0.0f;
    const float* hh = sh + grp * 32 * 128;
    #pragma unroll 2
    for (int k = 0; k < 128; k++) {
        const float w = ow1[k * 64 + d];
        #pragma unroll
        for (int e = 0; e < 32; e++) acc[e] += hh[e * 128 + k] * w;
    }
    const float bb = ob1[d];
    #pragma unroll
    for (int e = 0; e < 32; e++) {
        const float v = acc[e] + bb;
        st[(grp * 32 + e) * 65 + d] = silu_f(v);
    }
    __syncthreads();

    float o = 0.0f;
    if (tid < 128) {
        float s = ob2[0];
        #pragma unroll 4
        for (int dd = 0; dd < 64; dd++) s += st[tid * 65 + dd] * ow2[dd];
        o = s;
    }
    rsum[tid] = o;
    __syncthreads();
    for (int s = 128; s >= 1; s >>= 1) {
        if (tid < s) rsum[tid] += rsum[tid + s];
        __syncthreads();
    }
    if (tid == 0) out[g] = rsum[0];
}

// ---------------- launch ----------------
extern "C" void kernel_launch(void* const* d_in, const int* in_sizes, int n_in,
                              void* d_out, int out_size)
{
    const float* pos   = (const float*)d_in[0];
    const int*   z     = (const int*)  d_in[1];
    const int*   batch = (const int*)  d_in[2];
    const float* emb   = (const float*)d_in[3];
    const float* mw1   = (const float*)d_in[4];
    const float* mb1   = (const float*)d_in[5];
    const float* mw2   = (const float*)d_in[6];
    const float* mb2   = (const float*)d_in[7];
    const float* l1w   = (const float*)d_in[8];
    const float* l1b   = (const float*)d_in[9];
    const float* l2w   = (const float*)d_in[10];
    const float* l2b   = (const float*)d_in[11];
    const float* ow1   = (const float*)d_in[12];
    const float* ob1   = (const float*)d_in[13];
    const float* ow2   = (const float*)d_in[14];
    const float* ob2   = (const float*)d_in[15];
    float* out = (float*)d_out;

    float *hp, *x1p, *aggp;
    cudaGetSymbolAddress((void**)&hp,   g_h);
    cudaGetSymbolAddress((void**)&x1p,  g_x1);
    cudaGetSymbolAddress((void**)&aggp, g_agg);
    unsigned char *w1h, *w2h, *l1i, *l2i;
    cudaGetSymbolAddress((void**)&w1h, g_w1_hi);
    cudaGetSymbolAddress((void**)&w2h, g_w2_hi);
    cudaGetSymbolAddress((void**)&l1i, g_l1img);
    cudaGetSymbolAddress((void**)&l2i, g_l2img);

    cudaFuncSetAttribute(filter_mma_kernel, cudaFuncAttributeMaxDynamicSharedMemorySize,
                         FILT_SMEM_BYTES);
    cudaFuncSetAttribute(linear_mma_kernel, cudaFuncAttributeMaxDynamicSharedMemorySize,
                         LIN_SMEM_BYTES);
    cudaFuncSetAttribute(fused_linear_kernel, cudaFuncAttributeMaxDynamicSharedMemorySize,
                         FL_SMEM_BYTES);
    cudaFuncSetAttribute(out_kernel, cudaFuncAttributeMaxDynamicSharedMemorySize,
                         OUT_SMEM_FLOATS * (int)sizeof(float));

    build_graph_kernel<<<NTOT / 4, 128>>>(pos, batch);
    prep_all_kernel<<<(PREP_TOTAL + 255) / 256, 256>>>(mw1, mb1, mw2, l1w, l2w, z, emb);

    linear_mma_kernel<<<NTOT / 64, 512, LIN_SMEM_BYTES>>>(
        hp, l1i, l1b, mb2, x1p, 0);

    for (int l = 0; l < LAYERS; l++) {
        filter_mma_kernel<<<148, 512, FILT_SMEM_BYTES>>>(
            w1h + l * 16384, w2h + l * 32768);
        if (l < LAYERS - 1) {
            fused_linear_kernel<<<NTOT / 64, 512, FL_SMEM_BYTES>>>(
                l2i + l * 32768, l2b + l * HID,
                l1i + (l + 1) * 32768, l1b + (l + 1) * FIL,
                mb2 + (l + 1) * FIL);
        } else {
            linear_mma_kernel<<<NTOT / 64, 512, LIN_SMEM_BYTES>>>(
                aggp, l2i + l * 32768, l2b + l * HID, mb2, hp, 1);
        }
    }

    out_kernel<<<NUM_G, 256, OUT_SMEM_FLOATS * sizeof(float)>>>(ow1, ob1, ow2, ob2, out);
}